// round 1
// baseline (speedup 1.0000x reference)
#include <cuda_runtime.h>
#include <cstdint>
#include <math.h>

// ---------------------------------------------------------------------------
// Problem constants (MambaModel: B=4, L=1024, D=1024, E=2048, N=16, K=4, R=64)
// ---------------------------------------------------------------------------
constexpr int B_  = 4;
constexpr int L_  = 1024;
constexpr int D_  = 1024;
constexpr int E_  = 2048;      // 2*D
constexpr int NS_ = 16;        // state dim N
constexpr int KC_ = 4;         // conv kernel
constexpr int R_  = 64;        // D/16
constexpr int NL_ = 4;         // layers
constexpr int T_  = B_ * L_;   // 4096 tokens
constexpr int XD_ = R_ + 2 * NS_;  // 96

#define CDIV(a, b) (((a) + (b) - 1) / (b))

// ---------------------------------------------------------------------------
// Scratch (static device globals; no runtime allocation allowed)
// ---------------------------------------------------------------------------
__device__ float g_h    [(size_t)T_ * D_];        // residual stream (token, D)   16 MB
__device__ float g_xz   [(size_t)T_ * 2 * E_];    // in_proj output  (token, 2E)  64 MB
__device__ float g_u    [(size_t)T_ * E_];        // conv+silu       (token, E)   32 MB
__device__ float g_xdbl [(size_t)T_ * XD_];       // x_dbl           (token, 96)  1.5 MB
__device__ float g_delta[(size_t)T_ * E_];        // softplus delta  (token, E)   32 MB
__device__ float g_y    [(size_t)T_ * E_];        // scan output     (token, E)   32 MB

// ---------------------------------------------------------------------------
// float4 copy
// ---------------------------------------------------------------------------
__global__ void copy_kernel(const float4* __restrict__ src, float4* __restrict__ dst, int n4) {
    int i = blockIdx.x * blockDim.x + threadIdx.x;
    if (i < n4) dst[i] = src[i];
}

// ---------------------------------------------------------------------------
// Tiled SGEMM:  C[M,N] = A[M,K] * B[N,K]^T   (both row-major, K contiguous)
// EPI: 0 = plain, 1 = softplus(acc + bias[n]), 2 = acc + res[m*ldc+n]
// BM=BN=128, BK=8, 256 threads, 8x8 microtile.
// Requires: M % 128 == 0, K % 8 == 0, lda/ldb rows 16B-aligned (all true here).
// ---------------------------------------------------------------------------
template <int EPI>
__global__ __launch_bounds__(256) void sgemm_kernel(
    int M, int N, int K,
    const float* __restrict__ A, int lda,
    const float* __restrict__ B, int ldb,
    float* __restrict__ C, int ldc,
    const float* __restrict__ bias,
    const float* __restrict__ res)
{
    constexpr int BM = 128, BN = 128, BK = 8, TM = 8, TN = 8;
    __shared__ float As[BK][BM];
    __shared__ float Bs[BK][BN];

    const int tid = threadIdx.x;
    const int m0 = blockIdx.y * BM;
    const int n0 = blockIdx.x * BN;
    const int tx = tid & 15;        // 0..15
    const int ty = tid >> 4;        // 0..15
    const int lrow = tid >> 1;      // 0..127
    const int lk4  = (tid & 1) * 4; // 0 or 4

    float acc[TM][TN];
#pragma unroll
    for (int i = 0; i < TM; i++)
#pragma unroll
        for (int j = 0; j < TN; j++) acc[i][j] = 0.f;

    for (int k0 = 0; k0 < K; k0 += BK) {
        // Load A tile (rows always valid: M multiple of 128)
        {
            const float* p = A + (size_t)(m0 + lrow) * lda + k0 + lk4;
            float4 v = *reinterpret_cast<const float4*>(p);
            As[lk4 + 0][lrow] = v.x;
            As[lk4 + 1][lrow] = v.y;
            As[lk4 + 2][lrow] = v.z;
            As[lk4 + 3][lrow] = v.w;
        }
        // Load B tile (guard rows vs N)
        {
            const int nrow = n0 + lrow;
            float4 v = make_float4(0.f, 0.f, 0.f, 0.f);
            if (nrow < N) {
                const float* p = B + (size_t)nrow * ldb + k0 + lk4;
                v = *reinterpret_cast<const float4*>(p);
            }
            Bs[lk4 + 0][lrow] = v.x;
            Bs[lk4 + 1][lrow] = v.y;
            Bs[lk4 + 2][lrow] = v.z;
            Bs[lk4 + 3][lrow] = v.w;
        }
        __syncthreads();

#pragma unroll
        for (int k = 0; k < BK; k++) {
            float4 a0 = *reinterpret_cast<const float4*>(&As[k][ty * TM]);
            float4 a1 = *reinterpret_cast<const float4*>(&As[k][ty * TM + 4]);
            float4 b0 = *reinterpret_cast<const float4*>(&Bs[k][tx * TN]);
            float4 b1 = *reinterpret_cast<const float4*>(&Bs[k][tx * TN + 4]);
            float a[TM] = {a0.x, a0.y, a0.z, a0.w, a1.x, a1.y, a1.z, a1.w};
            float b[TN] = {b0.x, b0.y, b0.z, b0.w, b1.x, b1.y, b1.z, b1.w};
#pragma unroll
            for (int i = 0; i < TM; i++)
#pragma unroll
                for (int j = 0; j < TN; j++)
                    acc[i][j] = fmaf(a[i], b[j], acc[i][j]);
        }
        __syncthreads();
    }

#pragma unroll
    for (int i = 0; i < TM; i++) {
        const int m = m0 + ty * TM + i;
#pragma unroll
        for (int j = 0; j < TN; j++) {
            const int n = n0 + tx * TN + j;
            if (n < N) {
                float v = acc[i][j];
                if (EPI == 1) {
                    v += bias[n];
                    v = (v > 20.f) ? v : log1pf(__expf(v));  // softplus
                } else if (EPI == 2) {
                    v += res[(size_t)m * ldc + n];
                }
                C[(size_t)m * ldc + n] = v;
            }
        }
    }
}

// ---------------------------------------------------------------------------
// Depthwise causal conv1d (K=4) + bias + SiLU.  Input: first E cols of xz.
// ---------------------------------------------------------------------------
__global__ void conv_silu_kernel(
    const float* __restrict__ xz,   // (T, 2E)
    const float* __restrict__ cw,   // (E, 4)
    const float* __restrict__ cb,   // (E,)
    float* __restrict__ u)          // (T, E)
{
    const int e = blockIdx.x * blockDim.x + threadIdx.x;
    const int t = blockIdx.y;
    const int l = t & (L_ - 1);

    const float4 w = reinterpret_cast<const float4*>(cw)[e];
    float acc = cb[e];
    const float* col = xz + e;
    if (l >= 3) acc = fmaf(col[(size_t)(t - 3) * (2 * E_)], w.x, acc);
    if (l >= 2) acc = fmaf(col[(size_t)(t - 2) * (2 * E_)], w.y, acc);
    if (l >= 1) acc = fmaf(col[(size_t)(t - 1) * (2 * E_)], w.z, acc);
    acc = fmaf(col[(size_t)t * (2 * E_)], w.w, acc);
    // SiLU
    u[(size_t)t * E_ + e] = acc / (1.f + __expf(-acc));
}

// ---------------------------------------------------------------------------
// Selective scan. One thread per (b, e); 16 states in registers; sequential L.
// Fuses: + Dp*u  and  * silu(zgate).
// ---------------------------------------------------------------------------
__global__ __launch_bounds__(128) void scan_kernel(
    const float* __restrict__ delta,  // (T, E)
    const float* __restrict__ u,      // (T, E)
    const float* __restrict__ xz,     // (T, 2E) -> zgate at col E+e
    const float* __restrict__ xdbl,   // (T, 96) -> B at 64..79, C at 80..95
    const float* __restrict__ Alog,   // (E, 16)
    const float* __restrict__ Dp,     // (E,)
    float* __restrict__ y)            // (T, E)
{
    const int e = blockIdx.x * blockDim.x + threadIdx.x;
    const int b = blockIdx.y;

    float An[NS_];
#pragma unroll
    for (int n = 0; n < NS_; n++) An[n] = -__expf(Alog[(size_t)e * NS_ + n]);
    const float dp = Dp[e];

    float h[NS_];
#pragma unroll
    for (int n = 0; n < NS_; n++) h[n] = 0.f;

    for (int l = 0; l < L_; l++) {
        const int t = b * L_ + l;
        const float d  = delta[(size_t)t * E_ + e];
        const float uu = u[(size_t)t * E_ + e];
        const float du = d * uu;

        const float4* bb = reinterpret_cast<const float4*>(xdbl + (size_t)t * XD_ + R_);
        const float4* cc = reinterpret_cast<const float4*>(xdbl + (size_t)t * XD_ + R_ + NS_);
        float Bv[NS_], Cv[NS_];
#pragma unroll
        for (int q = 0; q < 4; q++) {
            float4 v = bb[q];
            Bv[4 * q + 0] = v.x; Bv[4 * q + 1] = v.y; Bv[4 * q + 2] = v.z; Bv[4 * q + 3] = v.w;
            float4 w2 = cc[q];
            Cv[4 * q + 0] = w2.x; Cv[4 * q + 1] = w2.y; Cv[4 * q + 2] = w2.z; Cv[4 * q + 3] = w2.w;
        }

        float yv = 0.f;
#pragma unroll
        for (int n = 0; n < NS_; n++) {
            const float dA = __expf(d * An[n]);
            h[n] = fmaf(dA, h[n], du * Bv[n]);
            yv = fmaf(h[n], Cv[n], yv);
        }

        const float z = xz[(size_t)t * (2 * E_) + E_ + e];
        const float sz = z / (1.f + __expf(-z));
        y[(size_t)t * E_ + e] = (yv + dp * uu) * sz;
    }
}

// ---------------------------------------------------------------------------
// LayerNorm over D, in place. One block per token.
// ---------------------------------------------------------------------------
__global__ void layernorm_kernel(float* __restrict__ h,
                                 const float* __restrict__ g,
                                 const float* __restrict__ bb)
{
    const int t = blockIdx.x;
    float* row = h + (size_t)t * D_;

    float s = 0.f, s2 = 0.f;
    for (int i = threadIdx.x; i < D_; i += blockDim.x) {
        const float v = row[i];
        s += v;
        s2 = fmaf(v, v, s2);
    }
    __shared__ float red[64];
#pragma unroll
    for (int o = 16; o > 0; o >>= 1) {
        s  += __shfl_xor_sync(0xFFFFFFFFu, s, o);
        s2 += __shfl_xor_sync(0xFFFFFFFFu, s2, o);
    }
    const int wid = threadIdx.x >> 5, lid = threadIdx.x & 31;
    if (lid == 0) { red[wid] = s; red[32 + wid] = s2; }
    __syncthreads();
    if (threadIdx.x < 32) {
        const int nw = blockDim.x >> 5;
        float a = (threadIdx.x < nw) ? red[threadIdx.x] : 0.f;
        float c = (threadIdx.x < nw) ? red[32 + threadIdx.x] : 0.f;
#pragma unroll
        for (int o = 16; o > 0; o >>= 1) {
            a += __shfl_xor_sync(0xFFFFFFFFu, a, o);
            c += __shfl_xor_sync(0xFFFFFFFFu, c, o);
        }
        if (threadIdx.x == 0) { red[0] = a; red[1] = c; }
    }
    __syncthreads();
    const float mean = red[0] * (1.f / D_);
    const float var  = red[1] * (1.f / D_) - mean * mean;
    const float inv  = rsqrtf(var + 1e-5f);
    for (int i = threadIdx.x; i < D_; i += blockDim.x) {
        row[i] = (row[i] - mean) * inv * g[i] + bb[i];
    }
}

// ---------------------------------------------------------------------------
// Final mean over L:  out[b, d] = (1/L) sum_l h[b*L+l, d]
// ---------------------------------------------------------------------------
__global__ void mean_kernel(const float* __restrict__ h, float* __restrict__ out) {
    const int d = blockIdx.x * blockDim.x + threadIdx.x;
    const int b = blockIdx.y;
    const float* p = h + (size_t)b * L_ * D_ + d;
    float s = 0.f;
    for (int l = 0; l < L_; l++) s += p[(size_t)l * D_];
    out[b * D_ + d] = s * (1.f / L_);
}

// ---------------------------------------------------------------------------
// Launch
// ---------------------------------------------------------------------------
extern "C" void kernel_launch(void* const* d_in, const int* in_sizes, int n_in,
                              void* d_out, int out_size)
{
    const float* x     = (const float*)d_in[0];
    const float* Win   = (const float*)d_in[1];
    const float* convw = (const float*)d_in[2];
    const float* convb = (const float*)d_in[3];
    const float* Wx    = (const float*)d_in[4];
    const float* Wdt   = (const float*)d_in[5];
    const float* bdt   = (const float*)d_in[6];
    const float* Alog  = (const float*)d_in[7];
    const float* Dp    = (const float*)d_in[8];
    const float* Wout  = (const float*)d_in[9];
    const float* ln_g  = (const float*)d_in[10];
    const float* ln_b  = (const float*)d_in[11];

    float *h, *xz, *u, *xdbl, *delta, *y;
    cudaGetSymbolAddress((void**)&h,     g_h);
    cudaGetSymbolAddress((void**)&xz,    g_xz);
    cudaGetSymbolAddress((void**)&u,     g_u);
    cudaGetSymbolAddress((void**)&xdbl,  g_xdbl);
    cudaGetSymbolAddress((void**)&delta, g_delta);
    cudaGetSymbolAddress((void**)&y,     g_y);

    // residual stream init: h = x  (x is (B, L, D) == (token, D))
    const int n4 = (T_ * D_) / 4;
    copy_kernel<<<CDIV(n4, 256), 256>>>((const float4*)x, (float4*)h, n4);

    for (int i = 0; i < NL_; i++) {
        // 1) xz = h @ Win^T        (4096 x 4096, K=1024)
        sgemm_kernel<0><<<dim3((2 * E_) / 128, T_ / 128), 256>>>(
            T_, 2 * E_, D_,
            h, D_,
            Win + (size_t)i * 2 * E_ * D_, D_,
            xz, 2 * E_, nullptr, nullptr);

        // 2) u = silu(causal_conv(xz[:, :E]) + convb)
        conv_silu_kernel<<<dim3(E_ / 256, T_), 256>>>(
            xz, convw + (size_t)i * E_ * KC_, convb + (size_t)i * E_, u);

        // 3) x_dbl = u @ Wx^T      (4096 x 96, K=2048)
        sgemm_kernel<0><<<dim3(CDIV(XD_, 128), T_ / 128), 256>>>(
            T_, XD_, E_,
            u, E_,
            Wx + (size_t)i * XD_ * E_, E_,
            xdbl, XD_, nullptr, nullptr);

        // 4) delta = softplus(dtr @ Wdt^T + bdt)   (4096 x 2048, K=64)
        sgemm_kernel<1><<<dim3(E_ / 128, T_ / 128), 256>>>(
            T_, E_, R_,
            xdbl, XD_,
            Wdt + (size_t)i * E_ * R_, R_,
            delta, E_, bdt + (size_t)i * E_, nullptr);

        // 5) selective scan -> y (fused +Dp*u, *silu(zgate))
        scan_kernel<<<dim3(E_ / 128, B_), 128>>>(
            delta, u, xz, xdbl,
            Alog + (size_t)i * E_ * NS_, Dp + (size_t)i * E_, y);

        // 6) h = y @ Wout^T + h    (4096 x 1024, K=2048)
        sgemm_kernel<2><<<dim3(D_ / 128, T_ / 128), 256>>>(
            T_, D_, E_,
            y, E_,
            Wout + (size_t)i * D_ * E_, E_,
            h, D_, nullptr, h);

        // 7) layernorm over D, in place
        layernorm_kernel<<<T_, 256>>>(h, ln_g + (size_t)i * D_, ln_b + (size_t)i * D_);
    }

    // out[b, d] = mean over L
    mean_kernel<<<dim3(D_ / 256, B_), 256>>>(h, (float*)d_out);
}

// round 3
// speedup vs baseline: 1.2604x; 1.2604x over previous
#include <cuda_runtime.h>
#include <cstdint>
#include <math.h>

// ---------------------------------------------------------------------------
// Problem constants (MambaModel: B=4, L=1024, D=1024, E=2048, N=16, K=4, R=64)
// ---------------------------------------------------------------------------
constexpr int B_  = 4;
constexpr int L_  = 1024;
constexpr int D_  = 1024;
constexpr int E_  = 2048;      // 2*D
constexpr int NS_ = 16;        // state dim N
constexpr int KC_ = 4;         // conv kernel
constexpr int R_  = 64;        // D/16
constexpr int NL_ = 4;         // layers
constexpr int T_  = B_ * L_;   // 4096 tokens
constexpr int XD_ = R_ + 2 * NS_;  // 96
constexpr int NSPLIT_ = 16;    // split-K factor for x_dbl GEMM

#define CDIV(a, b) (((a) + (b) - 1) / (b))

// ---------------------------------------------------------------------------
// Scratch (static device globals; no runtime allocation allowed)
// ---------------------------------------------------------------------------
__device__ float g_h    [(size_t)T_ * D_];          // residual stream
__device__ float g_xz   [(size_t)T_ * 2 * E_];      // in_proj output
__device__ float g_u    [(size_t)T_ * E_];          // conv+silu
__device__ float g_xdbl [(size_t)T_ * XD_];         // x_dbl
__device__ float g_xp   [(size_t)NSPLIT_ * T_ * XD_]; // split-K partials
__device__ float g_delta[(size_t)T_ * E_];          // softplus delta
__device__ float g_y    [(size_t)T_ * E_];          // scan output

// ---------------------------------------------------------------------------
// float4 copy
// ---------------------------------------------------------------------------
__global__ void copy_kernel(const float4* __restrict__ src, float4* __restrict__ dst, int n4) {
    int i = blockIdx.x * blockDim.x + threadIdx.x;
    if (i < n4) dst[i] = src[i];
}

// ---------------------------------------------------------------------------
// SGEMM v2:  C[M,N] = A[M,K] * B[N,K]^T   (row-major, K contiguous)
// BM=BN=128, BK=16, 256 threads, 8x8 microtile (4+4 split), double-buffered.
// EPI: 0 plain, 1 softplus(acc + bias[n]), 2 acc + res[m*ldc+n]
// Split-K: if kchunk != 0, blockIdx.z selects K window and C slab.
// Requires M % 128 == 0, K % 16 == 0, row strides 16B aligned.
// ---------------------------------------------------------------------------
template <int EPI>
__global__ __launch_bounds__(256) void sgemm_kernel(
    int M, int N, int K,
    const float* __restrict__ A, int lda,
    const float* __restrict__ B, int ldb,
    float* __restrict__ C, int ldc,
    const float* __restrict__ bias,
    const float* __restrict__ res,
    int kchunk, long long cslab)
{
    constexpr int BM = 128, BN = 128, BK = 16;
    __shared__ float As[2][BK][BM];
    __shared__ float Bs[2][BK][BN];

    if (kchunk) {
        A += (size_t)blockIdx.z * kchunk;
        B += (size_t)blockIdx.z * kchunk;
        C += (size_t)blockIdx.z * cslab;
    }

    const int tid  = threadIdx.x;
    const int m0   = blockIdx.y * BM;
    const int n0   = blockIdx.x * BN;
    const int tx   = tid & 15;          // 0..15 -> cols
    const int ty   = tid >> 4;          // 0..15 -> rows
    const int lrow = tid & 127;         // 0..127 (conflict-free smem stores)
    const int lk   = (tid >> 7) * 8;    // 0 or 8

    const float* Ap = A + (size_t)(m0 + lrow) * lda + lk;
    const bool bval = (n0 + lrow) < N;
    const float* Bp = B + (size_t)(bval ? (n0 + lrow) : 0) * ldb + lk;

    float acc[8][8];
#pragma unroll
    for (int i = 0; i < 8; i++)
#pragma unroll
        for (int j = 0; j < 8; j++) acc[i][j] = 0.f;

    // --- prologue: load tile 0 ---
    float4 a0 = *reinterpret_cast<const float4*>(Ap);
    float4 a1 = *reinterpret_cast<const float4*>(Ap + 4);
    float4 b0, b1;
    if (bval) {
        b0 = *reinterpret_cast<const float4*>(Bp);
        b1 = *reinterpret_cast<const float4*>(Bp + 4);
    } else {
        b0 = make_float4(0.f, 0.f, 0.f, 0.f); b1 = b0;
    }

#define STORE_TILE(buf)                                          \
    do {                                                         \
        As[buf][lk + 0][lrow] = a0.x; As[buf][lk + 1][lrow] = a0.y; \
        As[buf][lk + 2][lrow] = a0.z; As[buf][lk + 3][lrow] = a0.w; \
        As[buf][lk + 4][lrow] = a1.x; As[buf][lk + 5][lrow] = a1.y; \
        As[buf][lk + 6][lrow] = a1.z; As[buf][lk + 7][lrow] = a1.w; \
        Bs[buf][lk + 0][lrow] = b0.x; Bs[buf][lk + 1][lrow] = b0.y; \
        Bs[buf][lk + 2][lrow] = b0.z; Bs[buf][lk + 3][lrow] = b0.w; \
        Bs[buf][lk + 4][lrow] = b1.x; Bs[buf][lk + 5][lrow] = b1.y; \
        Bs[buf][lk + 6][lrow] = b1.z; Bs[buf][lk + 7][lrow] = b1.w; \
    } while (0)

#define COMPUTE_TILE(buf)                                                     \
    do {                                                                      \
        _Pragma("unroll")                                                     \
        for (int k = 0; k < BK; k++) {                                        \
            float4 xa0 = *reinterpret_cast<const float4*>(&As[buf][k][ty * 4]);      \
            float4 xa1 = *reinterpret_cast<const float4*>(&As[buf][k][64 + ty * 4]); \
            float4 xb0 = *reinterpret_cast<const float4*>(&Bs[buf][k][tx * 4]);      \
            float4 xb1 = *reinterpret_cast<const float4*>(&Bs[buf][k][64 + tx * 4]); \
            float av[8] = {xa0.x, xa0.y, xa0.z, xa0.w, xa1.x, xa1.y, xa1.z, xa1.w};  \
            float bv[8] = {xb0.x, xb0.y, xb0.z, xb0.w, xb1.x, xb1.y, xb1.z, xb1.w};  \
            _Pragma("unroll")                                                 \
            for (int i = 0; i < 8; i++)                                       \
                _Pragma("unroll")                                             \
                for (int j = 0; j < 8; j++)                                   \
                    acc[i][j] = fmaf(av[i], bv[j], acc[i][j]);                \
        }                                                                     \
    } while (0)

    STORE_TILE(0);
    __syncthreads();

    int buf = 0;
#pragma unroll 1
    for (int k0 = BK; k0 < K; k0 += BK) {
        // prefetch next tile into registers
        a0 = *reinterpret_cast<const float4*>(Ap + k0);
        a1 = *reinterpret_cast<const float4*>(Ap + k0 + 4);
        if (bval) {
            b0 = *reinterpret_cast<const float4*>(Bp + k0);
            b1 = *reinterpret_cast<const float4*>(Bp + k0 + 4);
        } else {
            b0 = make_float4(0.f, 0.f, 0.f, 0.f); b1 = b0;
        }
        COMPUTE_TILE(buf);
        STORE_TILE(buf ^ 1);
        __syncthreads();
        buf ^= 1;
    }
    COMPUTE_TILE(buf);

    // --- epilogue ---
#pragma unroll
    for (int i = 0; i < 8; i++) {
        const int m = m0 + (i < 4 ? ty * 4 + i : 64 + ty * 4 + (i - 4));
#pragma unroll
        for (int j = 0; j < 8; j++) {
            const int n = n0 + (j < 4 ? tx * 4 + j : 64 + tx * 4 + (j - 4));
            if (n < N) {
                float v = acc[i][j];
                if (EPI == 1) {
                    v += bias[n];
                    v = (v > 20.f) ? v : log1pf(__expf(v));  // softplus
                } else if (EPI == 2) {
                    v += res[(size_t)m * ldc + n];
                }
                C[(size_t)m * ldc + n] = v;
            }
        }
    }
#undef STORE_TILE
#undef COMPUTE_TILE
}

// ---------------------------------------------------------------------------
// Split-K reduce: xdbl[i] = sum over NSPLIT_ partials
// ---------------------------------------------------------------------------
__global__ void reduce_splitk_kernel(const float* __restrict__ xp,
                                     float* __restrict__ out, int n) {
    const int i = blockIdx.x * blockDim.x + threadIdx.x;
    if (i >= n) return;
    float s = 0.f;
#pragma unroll
    for (int k = 0; k < NSPLIT_; k++) s += xp[(size_t)k * n + i];
    out[i] = s;
}

// ---------------------------------------------------------------------------
// Depthwise causal conv1d (K=4) + bias + SiLU.  Input: first E cols of xz.
// ---------------------------------------------------------------------------
__global__ void conv_silu_kernel(
    const float* __restrict__ xz,   // (T, 2E)
    const float* __restrict__ cw,   // (E, 4)
    const float* __restrict__ cb,   // (E,)
    float* __restrict__ u)          // (T, E)
{
    const int e = blockIdx.x * blockDim.x + threadIdx.x;
    const int t = blockIdx.y;
    const int l = t & (L_ - 1);

    const float4 w = reinterpret_cast<const float4*>(cw)[e];
    float acc = cb[e];
    const float* col = xz + e;
    if (l >= 3) acc = fmaf(col[(size_t)(t - 3) * (2 * E_)], w.x, acc);
    if (l >= 2) acc = fmaf(col[(size_t)(t - 2) * (2 * E_)], w.y, acc);
    if (l >= 1) acc = fmaf(col[(size_t)(t - 1) * (2 * E_)], w.z, acc);
    acc = fmaf(col[(size_t)t * (2 * E_)], w.w, acc);
    u[(size_t)t * E_ + e] = acc / (1.f + __expf(-acc));
}

// ---------------------------------------------------------------------------
// Selective scan. One thread per (b, e); 16 states in regs; 2-step software
// pipeline so next-step loads overlap the exp chain. 32-thread blocks.
// ---------------------------------------------------------------------------
__device__ __forceinline__ void scan_step(
    float d, float uu, float z,
    float4 B0, float4 B1, float4 B2, float4 B3,
    float4 C0, float4 C1, float4 C2, float4 C3,
    const float* __restrict__ An, float dp,
    float* __restrict__ h, float* __restrict__ yout)
{
    const float du = d * uu;
    float Bv[NS_] = {B0.x, B0.y, B0.z, B0.w, B1.x, B1.y, B1.z, B1.w,
                     B2.x, B2.y, B2.z, B2.w, B3.x, B3.y, B3.z, B3.w};
    float Cv[NS_] = {C0.x, C0.y, C0.z, C0.w, C1.x, C1.y, C1.z, C1.w,
                     C2.x, C2.y, C2.z, C2.w, C3.x, C3.y, C3.z, C3.w};
    float yv = 0.f;
#pragma unroll
    for (int n = 0; n < NS_; n++) {
        const float dA = __expf(d * An[n]);
        h[n] = fmaf(dA, h[n], du * Bv[n]);
        yv = fmaf(h[n], Cv[n], yv);
    }
    const float sz = z / (1.f + __expf(-z));
    *yout = (yv + dp * uu) * sz;
}

__global__ __launch_bounds__(32) void scan_kernel(
    const float* __restrict__ delta,  // (T, E)
    const float* __restrict__ u,      // (T, E)
    const float* __restrict__ xz,     // (T, 2E) -> zgate at col E+e
    const float* __restrict__ xdbl,   // (T, 96) -> B at 64..79, C at 80..95
    const float* __restrict__ Alog,   // (E, 16)
    const float* __restrict__ Dp,     // (E,)
    float* __restrict__ y)            // (T, E)
{
    const int e = blockIdx.x * 32 + threadIdx.x;
    const int b = blockIdx.y;
    const int tbase = b * L_;

    float An[NS_];
#pragma unroll
    for (int n = 0; n < NS_; n++) An[n] = -__expf(Alog[(size_t)e * NS_ + n]);
    const float dp = Dp[e];

    float h[NS_];
#pragma unroll
    for (int n = 0; n < NS_; n++) h[n] = 0.f;

#define SCAN_LOAD(S, t)                                                         \
    do {                                                                        \
        d##S = delta[(size_t)(t) * E_ + e];                                     \
        u##S = u[(size_t)(t) * E_ + e];                                         \
        z##S = xz[(size_t)(t) * (2 * E_) + E_ + e];                             \
        const float4* bp = reinterpret_cast<const float4*>(xdbl + (size_t)(t) * XD_ + R_); \
        B##S##0 = bp[0]; B##S##1 = bp[1]; B##S##2 = bp[2]; B##S##3 = bp[3];     \
        C##S##0 = bp[4]; C##S##1 = bp[5]; C##S##2 = bp[6]; C##S##3 = bp[7];     \
    } while (0)

    float d0, u0, z0, d1, u1, z1;
    float4 B00, B01, B02, B03, C00, C01, C02, C03;
    float4 B10, B11, B12, B13, C10, C11, C12, C13;

    SCAN_LOAD(0, tbase);
#pragma unroll 1
    for (int l = 0; l < L_; l += 2) {
        SCAN_LOAD(1, tbase + l + 1);
        scan_step(d0, u0, z0, B00, B01, B02, B03, C00, C01, C02, C03,
                  An, dp, h, &y[(size_t)(tbase + l) * E_ + e]);
        if (l + 2 < L_) SCAN_LOAD(0, tbase + l + 2);
        scan_step(d1, u1, z1, B10, B11, B12, B13, C10, C11, C12, C13,
                  An, dp, h, &y[(size_t)(tbase + l + 1) * E_ + e]);
    }
#undef SCAN_LOAD
}

// ---------------------------------------------------------------------------
// LayerNorm over D, in place. One block per token.
// ---------------------------------------------------------------------------
__global__ void layernorm_kernel(float* __restrict__ h,
                                 const float* __restrict__ g,
                                 const float* __restrict__ bb)
{
    const int t = blockIdx.x;
    float* row = h + (size_t)t * D_;

    float s = 0.f, s2 = 0.f;
    for (int i = threadIdx.x; i < D_; i += blockDim.x) {
        const float v = row[i];
        s += v;
        s2 = fmaf(v, v, s2);
    }
    __shared__ float red[64];
#pragma unroll
    for (int o = 16; o > 0; o >>= 1) {
        s  += __shfl_xor_sync(0xFFFFFFFFu, s, o);
        s2 += __shfl_xor_sync(0xFFFFFFFFu, s2, o);
    }
    const int wid = threadIdx.x >> 5, lid = threadIdx.x & 31;
    if (lid == 0) { red[wid] = s; red[32 + wid] = s2; }
    __syncthreads();
    if (threadIdx.x < 32) {
        const int nw = blockDim.x >> 5;
        float a = (threadIdx.x < nw) ? red[threadIdx.x] : 0.f;
        float c = (threadIdx.x < nw) ? red[32 + threadIdx.x] : 0.f;
#pragma unroll
        for (int o = 16; o > 0; o >>= 1) {
            a += __shfl_xor_sync(0xFFFFFFFFu, a, o);
            c += __shfl_xor_sync(0xFFFFFFFFu, c, o);
        }
        if (threadIdx.x == 0) { red[0] = a; red[1] = c; }
    }
    __syncthreads();
    const float mean = red[0] * (1.f / D_);
    const float var  = red[1] * (1.f / D_) - mean * mean;
    const float inv  = rsqrtf(var + 1e-5f);
    for (int i = threadIdx.x; i < D_; i += blockDim.x) {
        row[i] = (row[i] - mean) * inv * g[i] + bb[i];
    }
}

// ---------------------------------------------------------------------------
// Final mean over L:  out[b, d] = (1/L) sum_l h[b*L+l, d]
// ---------------------------------------------------------------------------
__global__ void mean_kernel(const float* __restrict__ h, float* __restrict__ out) {
    const int d = blockIdx.x * blockDim.x + threadIdx.x;
    const int b = blockIdx.y;
    const float* p = h + (size_t)b * L_ * D_ + d;
    float s = 0.f;
    for (int l = 0; l < L_; l++) s += p[(size_t)l * D_];
    out[b * D_ + d] = s * (1.f / L_);
}

// ---------------------------------------------------------------------------
// Launch
// ---------------------------------------------------------------------------
extern "C" void kernel_launch(void* const* d_in, const int* in_sizes, int n_in,
                              void* d_out, int out_size)
{
    const float* x     = (const float*)d_in[0];
    const float* Win   = (const float*)d_in[1];
    const float* convw = (const float*)d_in[2];
    const float* convb = (const float*)d_in[3];
    const float* Wx    = (const float*)d_in[4];
    const float* Wdt   = (const float*)d_in[5];
    const float* bdt   = (const float*)d_in[6];
    const float* Alog  = (const float*)d_in[7];
    const float* Dp    = (const float*)d_in[8];
    const float* Wout  = (const float*)d_in[9];
    const float* ln_g  = (const float*)d_in[10];
    const float* ln_b  = (const float*)d_in[11];

    float *h, *xz, *u, *xdbl, *xp, *delta, *y;
    cudaGetSymbolAddress((void**)&h,     g_h);
    cudaGetSymbolAddress((void**)&xz,    g_xz);
    cudaGetSymbolAddress((void**)&u,     g_u);
    cudaGetSymbolAddress((void**)&xdbl,  g_xdbl);
    cudaGetSymbolAddress((void**)&xp,    g_xp);
    cudaGetSymbolAddress((void**)&delta, g_delta);
    cudaGetSymbolAddress((void**)&y,     g_y);

    // residual stream init: h = x
    const int n4 = (T_ * D_) / 4;
    copy_kernel<<<CDIV(n4, 256), 256>>>((const float4*)x, (float4*)h, n4);

    for (int i = 0; i < NL_; i++) {
        // 1) xz = h @ Win^T        (4096 x 4096, K=1024)
        sgemm_kernel<0><<<dim3((2 * E_) / 128, T_ / 128), 256>>>(
            T_, 2 * E_, D_,
            h, D_,
            Win + (size_t)i * 2 * E_ * D_, D_,
            xz, 2 * E_, nullptr, nullptr, 0, 0);

        // 2) u = silu(causal_conv(xz[:, :E]) + convb)
        conv_silu_kernel<<<dim3(E_ / 256, T_), 256>>>(
            xz, convw + (size_t)i * E_ * KC_, convb + (size_t)i * E_, u);

        // 3) x_dbl = u @ Wx^T      (4096 x 96, K=2048), split-K over 16 chunks
        sgemm_kernel<0><<<dim3(1, T_ / 128, NSPLIT_), 256>>>(
            T_, XD_, E_ / NSPLIT_,
            u, E_,
            Wx + (size_t)i * XD_ * E_, E_,
            xp, XD_, nullptr, nullptr,
            E_ / NSPLIT_, (long long)T_ * XD_);
        reduce_splitk_kernel<<<CDIV(T_ * XD_, 256), 256>>>(xp, xdbl, T_ * XD_);

        // 4) delta = softplus(dtr @ Wdt^T + bdt)   (4096 x 2048, K=64)
        sgemm_kernel<1><<<dim3(E_ / 128, T_ / 128), 256>>>(
            T_, E_, R_,
            xdbl, XD_,
            Wdt + (size_t)i * E_ * R_, R_,
            delta, E_, bdt + (size_t)i * E_, nullptr, 0, 0);

        // 5) selective scan -> y (fused +Dp*u, *silu(zgate))
        scan_kernel<<<dim3(E_ / 32, B_), 32>>>(
            delta, u, xz, xdbl,
            Alog + (size_t)i * E_ * NS_, Dp + (size_t)i * E_, y);

        // 6) h = y @ Wout^T + h    (4096 x 1024, K=2048)
        sgemm_kernel<2><<<dim3(D_ / 128, T_ / 128), 256>>>(
            T_, D_, E_,
            y, E_,
            Wout + (size_t)i * D_ * E_, E_,
            h, D_, nullptr, h, 0, 0);

        // 7) layernorm over D, in place
        layernorm_kernel<<<T_, 256>>>(h, ln_g + (size_t)i * D_, ln_b + (size_t)i * D_);
    }

    // out[b, d] = mean over L
    mean_kernel<<<dim3(D_ / 256, B_), 256>>>(h, (float*)d_out);
}

// round 5
// speedup vs baseline: 2.0173x; 1.6005x over previous
#include <cuda_runtime.h>
#include <cuda_bf16.h>
#include <cstdint>
#include <math.h>

// ---------------------------------------------------------------------------
// Problem constants (MambaModel: B=4, L=1024, D=1024, E=2048, N=16, K=4, R=64)
// ---------------------------------------------------------------------------
constexpr int B_  = 4;
constexpr int L_  = 1024;
constexpr int D_  = 1024;
constexpr int E_  = 2048;
constexpr int NS_ = 16;
constexpr int KC_ = 4;
constexpr int R_  = 64;
constexpr int NL_ = 4;
constexpr int T_  = B_ * L_;       // 4096
constexpr int XD_ = R_ + 2 * NS_;  // 96
constexpr int NSPLIT_ = 16;

#define CDIV(a, b) (((a) + (b) - 1) / (b))

// ---------------------------------------------------------------------------
// Scratch
// ---------------------------------------------------------------------------
__device__ float g_h    [(size_t)T_ * D_];
__device__ float g_xz   [(size_t)T_ * 2 * E_];
__device__ float g_u    [(size_t)T_ * E_];
__device__ float g_xdbl [(size_t)T_ * XD_];
__device__ float g_xp   [(size_t)NSPLIT_ * T_ * XD_];
__device__ float g_delta[(size_t)T_ * E_];
__device__ float g_y    [(size_t)T_ * E_];

// ===========================================================================
// Warp-MMA helpers (family-portable: ldmatrix + mma.sync, OK on plain sm_100)
// ===========================================================================
__device__ __forceinline__ uint32_t smem_to_u32(const void* p) {
    uint32_t a;
    asm("{ .reg .u64 t; cvta.to.shared.u64 t, %1; cvt.u32.u64 %0, t; }"
        : "=r"(a) : "l"(p));
    return a;
}

__device__ __forceinline__ void ldmatrix_x4(uint32_t& r0, uint32_t& r1,
                                            uint32_t& r2, uint32_t& r3,
                                            uint32_t addr) {
    asm volatile("ldmatrix.sync.aligned.m8n8.x4.shared.b16 {%0,%1,%2,%3}, [%4];"
                 : "=r"(r0), "=r"(r1), "=r"(r2), "=r"(r3) : "r"(addr));
}

__device__ __forceinline__ void mma_bf16(float& c0, float& c1, float& c2, float& c3,
                                         uint32_t a0, uint32_t a1, uint32_t a2, uint32_t a3,
                                         uint32_t b0, uint32_t b1) {
    asm volatile(
        "mma.sync.aligned.m16n8k16.row.col.f32.bf16.bf16.f32 "
        "{%0,%1,%2,%3}, {%4,%5,%6,%7}, {%8,%9}, {%0,%1,%2,%3};"
        : "+f"(c0), "+f"(c1), "+f"(c2), "+f"(c3)
        : "r"(a0), "r"(a1), "r"(a2), "r"(a3), "r"(b0), "r"(b1));
}

// SW128 swizzle: byte_off within a 128B-row tile
__device__ __forceinline__ uint32_t sw128(uint32_t off) {
    return off ^ ((off >> 3) & 0x70);
}

// ===========================================================================
// HMMA GEMM:  C[M,N] = A[M,K] * B[N,K]^T, fp32 in/out, bf16x3 internally.
// Block tile 128x128, K-chunks of 64, 256 threads (8 warps, 4m x 2n).
// Warp tile 32x64.  EPI: 0 plain, 1 softplus(acc+bias[n]), 2 acc+res.
// Requires M%128==0, N%128==0, K%64==0, A/B rows 16B-aligned.
// smem: 4 tiles (Ah, Al, Bh, Bl), each 128 rows x 64 bf16 (128B, SW128).
// ===========================================================================
constexpr int MM_AH = 0;
constexpr int MM_AL = 16384;
constexpr int MM_BH = 32768;
constexpr int MM_BL = 49152;
constexpr int MM_SMEM = 65536;

// fp32 -> (hi, lo) bf16 split of a 128x64 tile, stored SW128-swizzled.
__device__ __forceinline__ void load_split_tile_256(
    const float* __restrict__ src, int ld, char* dsth, char* dstl, int tid)
{
#pragma unroll
    for (int i = 0; i < 8; i++) {
        const int idx = tid + (i << 8);   // 0..2047
        const int row = idx >> 4;         // 0..127
        const int c4  = idx & 15;         // float4 within the 64-col row
        float4 v = *reinterpret_cast<const float4*>(src + (size_t)row * ld + (c4 << 2));

        __nv_bfloat16 h0 = __float2bfloat16(v.x);
        __nv_bfloat16 h1 = __float2bfloat16(v.y);
        __nv_bfloat16 h2 = __float2bfloat16(v.z);
        __nv_bfloat16 h3 = __float2bfloat16(v.w);
        __nv_bfloat16 l0 = __float2bfloat16(v.x - __bfloat162float(h0));
        __nv_bfloat16 l1 = __float2bfloat16(v.y - __bfloat162float(h1));
        __nv_bfloat16 l2 = __float2bfloat16(v.z - __bfloat162float(h2));
        __nv_bfloat16 l3 = __float2bfloat16(v.w - __bfloat162float(h3));

        __nv_bfloat162 hp0 = __halves2bfloat162(h0, h1);
        __nv_bfloat162 hp1 = __halves2bfloat162(h2, h3);
        __nv_bfloat162 lp0 = __halves2bfloat162(l0, l1);
        __nv_bfloat162 lp1 = __halves2bfloat162(l2, l3);

        uint2 hv, lv;
        hv.x = *reinterpret_cast<uint32_t*>(&hp0);
        hv.y = *reinterpret_cast<uint32_t*>(&hp1);
        lv.x = *reinterpret_cast<uint32_t*>(&lp0);
        lv.y = *reinterpret_cast<uint32_t*>(&lp1);

        const uint32_t sw = sw128((uint32_t)(row << 7) + (uint32_t)(c4 << 3));
        *reinterpret_cast<uint2*>(dsth + sw) = hv;
        *reinterpret_cast<uint2*>(dstl + sw) = lv;
    }
}

template <int EPI>
__global__ __launch_bounds__(256) void mma_gemm_kernel(
    int M, int N, int K,
    const float* __restrict__ A, int lda,
    const float* __restrict__ Bw, int ldb,
    float* __restrict__ C, int ldc,
    const float* __restrict__ bias,
    const float* __restrict__ res)
{
    extern __shared__ __align__(1024) char smem[];
    const uint32_t sb = smem_to_u32(smem);
    const int tid    = threadIdx.x;
    const int wid    = tid >> 5;
    const int lane   = tid & 31;
    const int warp_m = wid >> 1;                 // 0..3
    const int warp_n = wid & 1;                  // 0..1
    const int mb     = warp_m * 32;              // warp row base in tile
    const int nb     = warp_n * 64;              // warp col base in tile
    const int m0 = blockIdx.y * 128;
    const int n0 = blockIdx.x * 128;

    // Precompute ldmatrix intra-tile byte offsets (without the kstep part).
    // A (per m16 tile tm): row = mb + tm*16 + (lane&15), kbyte += (lane>>4)*16
    const int a_row_off = (lane & 15);
    const int a_koff    = (lane >> 4) << 4;
    // B (per n16 group g): row = nb + g*16 + (lane&7) + ((lane>>4)<<3),
    //                      kbyte += ((lane>>3)&1)*16
    const int b_row_off = (lane & 7) + ((lane >> 4) << 3);
    const int b_koff    = ((lane >> 3) & 1) << 4;

    float acc[2][8][4];
#pragma unroll
    for (int i = 0; i < 2; i++)
#pragma unroll
        for (int j = 0; j < 8; j++)
#pragma unroll
            for (int q = 0; q < 4; q++) acc[i][j][q] = 0.f;

    const float* Abase = A  + (size_t)m0 * lda;
    const float* Bbase = Bw + (size_t)n0 * ldb;
    const int nchunks = K >> 6;

    for (int kc = 0; kc < nchunks; kc++) {
        load_split_tile_256(Abase + (kc << 6), lda, smem + MM_AH, smem + MM_AL, tid);
        load_split_tile_256(Bbase + (kc << 6), ldb, smem + MM_BH, smem + MM_BL, tid);
        __syncthreads();

#pragma unroll
        for (int s = 0; s < 4; s++) {          // four k16 steps in the 64-chunk
            const int ks = s << 5;             // byte offset of k16 step (16 bf16 = 32B)
#pragma unroll
            for (int p = 0; p < 3; p++) {      // bf16x3 passes: Ah*Bh, Al*Bh, Ah*Bl
                const uint32_t abase = sb + (p == 1 ? MM_AL : MM_AH);
                const uint32_t bbase = sb + (p == 2 ? MM_BL : MM_BH);

                uint32_t a[2][4];
#pragma unroll
                for (int tm = 0; tm < 2; tm++) {
                    const int row = mb + tm * 16 + a_row_off;
                    const uint32_t off = sw128((uint32_t)(row << 7) + ks + a_koff);
                    ldmatrix_x4(a[tm][0], a[tm][1], a[tm][2], a[tm][3], abase + off);
                }
                uint32_t b[4][4];
#pragma unroll
                for (int g = 0; g < 4; g++) {
                    const int row = nb + g * 16 + b_row_off;
                    const uint32_t off = sw128((uint32_t)(row << 7) + ks + b_koff);
                    ldmatrix_x4(b[g][0], b[g][1], b[g][2], b[g][3], bbase + off);
                }
#pragma unroll
                for (int tm = 0; tm < 2; tm++)
#pragma unroll
                    for (int g = 0; g < 4; g++) {
                        mma_bf16(acc[tm][2*g][0], acc[tm][2*g][1], acc[tm][2*g][2], acc[tm][2*g][3],
                                 a[tm][0], a[tm][1], a[tm][2], a[tm][3], b[g][0], b[g][1]);
                        mma_bf16(acc[tm][2*g+1][0], acc[tm][2*g+1][1], acc[tm][2*g+1][2], acc[tm][2*g+1][3],
                                 a[tm][0], a[tm][1], a[tm][2], a[tm][3], b[g][2], b[g][3]);
                    }
            }
        }
        __syncthreads();
    }

    // Epilogue: c0,c1 at (row = l/4, col = (l%4)*2 + {0,1}); c2,c3 at row+8.
    const int erow = m0 + mb + (lane >> 2);
    const int ecol0 = n0 + nb + (lane & 3) * 2;
#pragma unroll
    for (int tm = 0; tm < 2; tm++) {
#pragma unroll
        for (int j = 0; j < 8; j++) {
            const int col = ecol0 + j * 8;
#pragma unroll
            for (int half = 0; half < 2; half++) {
                const int row = erow + tm * 16 + half * 8;
                float v0 = acc[tm][j][2 * half + 0];
                float v1 = acc[tm][j][2 * half + 1];
                if (EPI == 1) {
                    v0 += bias[col];
                    v1 += bias[col + 1];
                    v0 = (v0 > 20.f) ? v0 : log1pf(__expf(v0));
                    v1 = (v1 > 20.f) ? v1 : log1pf(__expf(v1));
                } else if (EPI == 2) {
                    v0 += res[(size_t)row * ldc + col];
                    v1 += res[(size_t)row * ldc + col + 1];
                }
                C[(size_t)row * ldc + col]     = v0;
                C[(size_t)row * ldc + col + 1] = v1;
            }
        }
    }
}

// ===========================================================================
// FFMA split-K SGEMM (kept for x_dbl: N=96)
// ===========================================================================
__global__ __launch_bounds__(256) void sgemm_splitk_kernel(
    int M, int N, int K,
    const float* __restrict__ A, int lda,
    const float* __restrict__ B, int ldb,
    float* __restrict__ C, int ldc,
    int kchunk, long long cslab)
{
    constexpr int BM = 128, BN = 128, BK = 16;
    __shared__ float As[2][BK][BM];
    __shared__ float Bs[2][BK][BN];

    A += (size_t)blockIdx.z * kchunk;
    B += (size_t)blockIdx.z * kchunk;
    C += (size_t)blockIdx.z * cslab;

    const int tid  = threadIdx.x;
    const int m0   = blockIdx.y * BM;
    const int n0   = blockIdx.x * BN;
    const int tx   = tid & 15;
    const int ty   = tid >> 4;
    const int lrow = tid & 127;
    const int lk   = (tid >> 7) * 8;

    const float* Ap = A + (size_t)(m0 + lrow) * lda + lk;
    const bool bval = (n0 + lrow) < N;
    const float* Bp = B + (size_t)(bval ? (n0 + lrow) : 0) * ldb + lk;

    float acc[8][8];
#pragma unroll
    for (int i = 0; i < 8; i++)
#pragma unroll
        for (int j = 0; j < 8; j++) acc[i][j] = 0.f;

    float4 a0 = *reinterpret_cast<const float4*>(Ap);
    float4 a1 = *reinterpret_cast<const float4*>(Ap + 4);
    float4 b0, b1;
    if (bval) {
        b0 = *reinterpret_cast<const float4*>(Bp);
        b1 = *reinterpret_cast<const float4*>(Bp + 4);
    } else {
        b0 = make_float4(0.f, 0.f, 0.f, 0.f); b1 = b0;
    }

#define STORE_TILE(buf)                                          \
    do {                                                         \
        As[buf][lk + 0][lrow] = a0.x; As[buf][lk + 1][lrow] = a0.y; \
        As[buf][lk + 2][lrow] = a0.z; As[buf][lk + 3][lrow] = a0.w; \
        As[buf][lk + 4][lrow] = a1.x; As[buf][lk + 5][lrow] = a1.y; \
        As[buf][lk + 6][lrow] = a1.z; As[buf][lk + 7][lrow] = a1.w; \
        Bs[buf][lk + 0][lrow] = b0.x; Bs[buf][lk + 1][lrow] = b0.y; \
        Bs[buf][lk + 2][lrow] = b0.z; Bs[buf][lk + 3][lrow] = b0.w; \
        Bs[buf][lk + 4][lrow] = b1.x; Bs[buf][lk + 5][lrow] = b1.y; \
        Bs[buf][lk + 6][lrow] = b1.z; Bs[buf][lk + 7][lrow] = b1.w; \
    } while (0)

#define COMPUTE_TILE(buf)                                                     \
    do {                                                                      \
        _Pragma("unroll")                                                     \
        for (int k = 0; k < BK; k++) {                                        \
            float4 xa0 = *reinterpret_cast<const float4*>(&As[buf][k][ty * 4]);      \
            float4 xa1 = *reinterpret_cast<const float4*>(&As[buf][k][64 + ty * 4]); \
            float4 xb0 = *reinterpret_cast<const float4*>(&Bs[buf][k][tx * 4]);      \
            float4 xb1 = *reinterpret_cast<const float4*>(&Bs[buf][k][64 + tx * 4]); \
            float av[8] = {xa0.x, xa0.y, xa0.z, xa0.w, xa1.x, xa1.y, xa1.z, xa1.w};  \
            float bv[8] = {xb0.x, xb0.y, xb0.z, xb0.w, xb1.x, xb1.y, xb1.z, xb1.w};  \
            _Pragma("unroll")                                                 \
            for (int i = 0; i < 8; i++)                                       \
                _Pragma("unroll")                                             \
                for (int j = 0; j < 8; j++)                                   \
                    acc[i][j] = fmaf(av[i], bv[j], acc[i][j]);                \
        }                                                                     \
    } while (0)

    STORE_TILE(0);
    __syncthreads();

    int buf = 0;
#pragma unroll 1
    for (int k0 = BK; k0 < K; k0 += BK) {
        a0 = *reinterpret_cast<const float4*>(Ap + k0);
        a1 = *reinterpret_cast<const float4*>(Ap + k0 + 4);
        if (bval) {
            b0 = *reinterpret_cast<const float4*>(Bp + k0);
            b1 = *reinterpret_cast<const float4*>(Bp + k0 + 4);
        } else {
            b0 = make_float4(0.f, 0.f, 0.f, 0.f); b1 = b0;
        }
        COMPUTE_TILE(buf);
        STORE_TILE(buf ^ 1);
        __syncthreads();
        buf ^= 1;
    }
    COMPUTE_TILE(buf);

#pragma unroll
    for (int i = 0; i < 8; i++) {
        const int m = m0 + (i < 4 ? ty * 4 + i : 64 + ty * 4 + (i - 4));
#pragma unroll
        for (int j = 0; j < 8; j++) {
            const int n = n0 + (j < 4 ? tx * 4 + j : 64 + tx * 4 + (j - 4));
            if (n < N) C[(size_t)m * ldc + n] = acc[i][j];
        }
    }
#undef STORE_TILE
#undef COMPUTE_TILE
}

__global__ void reduce_splitk_kernel(const float* __restrict__ xp,
                                     float* __restrict__ out, int n) {
    const int i = blockIdx.x * blockDim.x + threadIdx.x;
    if (i >= n) return;
    float s = 0.f;
#pragma unroll
    for (int k = 0; k < NSPLIT_; k++) s += xp[(size_t)k * n + i];
    out[i] = s;
}

// ---------------------------------------------------------------------------
// Misc kernels
// ---------------------------------------------------------------------------
__global__ void copy_kernel(const float4* __restrict__ src, float4* __restrict__ dst, int n4) {
    int i = blockIdx.x * blockDim.x + threadIdx.x;
    if (i < n4) dst[i] = src[i];
}

__global__ void conv_silu_kernel(
    const float* __restrict__ xz, const float* __restrict__ cw,
    const float* __restrict__ cb, float* __restrict__ u)
{
    const int e = blockIdx.x * blockDim.x + threadIdx.x;
    const int t = blockIdx.y;
    const int l = t & (L_ - 1);
    const float4 w = reinterpret_cast<const float4*>(cw)[e];
    float acc = cb[e];
    const float* col = xz + e;
    if (l >= 3) acc = fmaf(col[(size_t)(t - 3) * (2 * E_)], w.x, acc);
    if (l >= 2) acc = fmaf(col[(size_t)(t - 2) * (2 * E_)], w.y, acc);
    if (l >= 1) acc = fmaf(col[(size_t)(t - 1) * (2 * E_)], w.z, acc);
    acc = fmaf(col[(size_t)t * (2 * E_)], w.w, acc);
    u[(size_t)t * E_ + e] = acc / (1.f + __expf(-acc));
}

__device__ __forceinline__ void scan_step(
    float d, float uu, float z,
    float4 B0, float4 B1, float4 B2, float4 B3,
    float4 C0, float4 C1, float4 C2, float4 C3,
    const float* __restrict__ An, float dp,
    float* __restrict__ h, float* __restrict__ yout)
{
    const float du = d * uu;
    float Bv[NS_] = {B0.x, B0.y, B0.z, B0.w, B1.x, B1.y, B1.z, B1.w,
                     B2.x, B2.y, B2.z, B2.w, B3.x, B3.y, B3.z, B3.w};
    float Cv[NS_] = {C0.x, C0.y, C0.z, C0.w, C1.x, C1.y, C1.z, C1.w,
                     C2.x, C2.y, C2.z, C2.w, C3.x, C3.y, C3.z, C3.w};
    float yv = 0.f;
#pragma unroll
    for (int n = 0; n < NS_; n++) {
        const float dA = __expf(d * An[n]);
        h[n] = fmaf(dA, h[n], du * Bv[n]);
        yv = fmaf(h[n], Cv[n], yv);
    }
    const float sz = z / (1.f + __expf(-z));
    *yout = (yv + dp * uu) * sz;
}

__global__ __launch_bounds__(32) void scan_kernel(
    const float* __restrict__ delta, const float* __restrict__ u,
    const float* __restrict__ xz, const float* __restrict__ xdbl,
    const float* __restrict__ Alog, const float* __restrict__ Dp,
    float* __restrict__ y)
{
    const int e = blockIdx.x * 32 + threadIdx.x;
    const int b = blockIdx.y;
    const int tbase = b * L_;

    float An[NS_];
#pragma unroll
    for (int n = 0; n < NS_; n++) An[n] = -__expf(Alog[(size_t)e * NS_ + n]);
    const float dp = Dp[e];

    float h[NS_];
#pragma unroll
    for (int n = 0; n < NS_; n++) h[n] = 0.f;

#define SCAN_LOAD(S, t)                                                         \
    do {                                                                        \
        d##S = delta[(size_t)(t) * E_ + e];                                     \
        u##S = u[(size_t)(t) * E_ + e];                                         \
        z##S = xz[(size_t)(t) * (2 * E_) + E_ + e];                             \
        const float4* bp = reinterpret_cast<const float4*>(xdbl + (size_t)(t) * XD_ + R_); \
        B##S##0 = bp[0]; B##S##1 = bp[1]; B##S##2 = bp[2]; B##S##3 = bp[3];     \
        C##S##0 = bp[4]; C##S##1 = bp[5]; C##S##2 = bp[6]; C##S##3 = bp[7];     \
    } while (0)

    float d0, u0, z0, d1, u1, z1;
    float4 B00, B01, B02, B03, C00, C01, C02, C03;
    float4 B10, B11, B12, B13, C10, C11, C12, C13;

    SCAN_LOAD(0, tbase);
#pragma unroll 1
    for (int l = 0; l < L_; l += 2) {
        SCAN_LOAD(1, tbase + l + 1);
        scan_step(d0, u0, z0, B00, B01, B02, B03, C00, C01, C02, C03,
                  An, dp, h, &y[(size_t)(tbase + l) * E_ + e]);
        if (l + 2 < L_) SCAN_LOAD(0, tbase + l + 2);
        scan_step(d1, u1, z1, B10, B11, B12, B13, C10, C11, C12, C13,
                  An, dp, h, &y[(size_t)(tbase + l + 1) * E_ + e]);
    }
#undef SCAN_LOAD
}

__global__ void layernorm_kernel(float* __restrict__ h,
                                 const float* __restrict__ g,
                                 const float* __restrict__ bb)
{
    const int t = blockIdx.x;
    float* row = h + (size_t)t * D_;
    float s = 0.f, s2 = 0.f;
    for (int i = threadIdx.x; i < D_; i += blockDim.x) {
        const float v = row[i];
        s += v;
        s2 = fmaf(v, v, s2);
    }
    __shared__ float red[64];
#pragma unroll
    for (int o = 16; o > 0; o >>= 1) {
        s  += __shfl_xor_sync(0xFFFFFFFFu, s, o);
        s2 += __shfl_xor_sync(0xFFFFFFFFu, s2, o);
    }
    const int wid = threadIdx.x >> 5, lid = threadIdx.x & 31;
    if (lid == 0) { red[wid] = s; red[32 + wid] = s2; }
    __syncthreads();
    if (threadIdx.x < 32) {
        const int nw = blockDim.x >> 5;
        float a = (threadIdx.x < nw) ? red[threadIdx.x] : 0.f;
        float c = (threadIdx.x < nw) ? red[32 + threadIdx.x] : 0.f;
#pragma unroll
        for (int o = 16; o > 0; o >>= 1) {
            a += __shfl_xor_sync(0xFFFFFFFFu, a, o);
            c += __shfl_xor_sync(0xFFFFFFFFu, c, o);
        }
        if (threadIdx.x == 0) { red[0] = a; red[1] = c; }
    }
    __syncthreads();
    const float mean = red[0] * (1.f / D_);
    const float var  = red[1] * (1.f / D_) - mean * mean;
    const float inv  = rsqrtf(var + 1e-5f);
    for (int i = threadIdx.x; i < D_; i += blockDim.x)
        row[i] = (row[i] - mean) * inv * g[i] + bb[i];
}

__global__ void mean_kernel(const float* __restrict__ h, float* __restrict__ out) {
    const int d = blockIdx.x * blockDim.x + threadIdx.x;
    const int b = blockIdx.y;
    const float* p = h + (size_t)b * L_ * D_ + d;
    float s = 0.f;
    for (int l = 0; l < L_; l++) s += p[(size_t)l * D_];
    out[b * D_ + d] = s * (1.f / L_);
}

// ---------------------------------------------------------------------------
// Launch
// ---------------------------------------------------------------------------
extern "C" void kernel_launch(void* const* d_in, const int* in_sizes, int n_in,
                              void* d_out, int out_size)
{
    const float* x     = (const float*)d_in[0];
    const float* Win   = (const float*)d_in[1];
    const float* convw = (const float*)d_in[2];
    const float* convb = (const float*)d_in[3];
    const float* Wx    = (const float*)d_in[4];
    const float* Wdt   = (const float*)d_in[5];
    const float* bdt   = (const float*)d_in[6];
    const float* Alog  = (const float*)d_in[7];
    const float* Dp    = (const float*)d_in[8];
    const float* Wout  = (const float*)d_in[9];
    const float* ln_g  = (const float*)d_in[10];
    const float* ln_b  = (const float*)d_in[11];

    float *h, *xz, *u, *xdbl, *xp, *delta, *y;
    cudaGetSymbolAddress((void**)&h,     g_h);
    cudaGetSymbolAddress((void**)&xz,    g_xz);
    cudaGetSymbolAddress((void**)&u,     g_u);
    cudaGetSymbolAddress((void**)&xdbl,  g_xdbl);
    cudaGetSymbolAddress((void**)&xp,    g_xp);
    cudaGetSymbolAddress((void**)&delta, g_delta);
    cudaGetSymbolAddress((void**)&y,     g_y);

    cudaFuncSetAttribute(mma_gemm_kernel<0>, cudaFuncAttributeMaxDynamicSharedMemorySize, MM_SMEM);
    cudaFuncSetAttribute(mma_gemm_kernel<1>, cudaFuncAttributeMaxDynamicSharedMemorySize, MM_SMEM);
    cudaFuncSetAttribute(mma_gemm_kernel<2>, cudaFuncAttributeMaxDynamicSharedMemorySize, MM_SMEM);

    const int n4 = (T_ * D_) / 4;
    copy_kernel<<<CDIV(n4, 256), 256>>>((const float4*)x, (float4*)h, n4);

    for (int i = 0; i < NL_; i++) {
        // 1) xz = h @ Win^T   (4096 x 4096, K=1024) — HMMA bf16x3
        mma_gemm_kernel<0><<<dim3((2 * E_) / 128, T_ / 128), 256, MM_SMEM>>>(
            T_, 2 * E_, D_,
            h, D_,
            Win + (size_t)i * 2 * E_ * D_, D_,
            xz, 2 * E_, nullptr, nullptr);

        // 2) u = silu(causal_conv(xz[:, :E]) + convb)
        conv_silu_kernel<<<dim3(E_ / 256, T_), 256>>>(
            xz, convw + (size_t)i * E_ * KC_, convb + (size_t)i * E_, u);

        // 3) x_dbl = u @ Wx^T  (4096 x 96, K=2048) — split-K FFMA
        sgemm_splitk_kernel<<<dim3(1, T_ / 128, NSPLIT_), 256>>>(
            T_, XD_, E_ / NSPLIT_,
            u, E_,
            Wx + (size_t)i * XD_ * E_, E_,
            xp, XD_,
            E_ / NSPLIT_, (long long)T_ * XD_);
        reduce_splitk_kernel<<<CDIV(T_ * XD_, 256), 256>>>(xp, xdbl, T_ * XD_);

        // 4) delta = softplus(dtr @ Wdt^T + bdt)  (4096 x 2048, K=64) — HMMA
        mma_gemm_kernel<1><<<dim3(E_ / 128, T_ / 128), 256, MM_SMEM>>>(
            T_, E_, R_,
            xdbl, XD_,
            Wdt + (size_t)i * E_ * R_, R_,
            delta, E_, bdt + (size_t)i * E_, nullptr);

        // 5) selective scan -> y
        scan_kernel<<<dim3(E_ / 32, B_), 32>>>(
            delta, u, xz, xdbl,
            Alog + (size_t)i * E_ * NS_, Dp + (size_t)i * E_, y);

        // 6) h = y @ Wout^T + h  (4096 x 1024, K=2048) — HMMA + residual
        mma_gemm_kernel<2><<<dim3(D_ / 128, T_ / 128), 256, MM_SMEM>>>(
            T_, D_, E_,
            y, E_,
            Wout + (size_t)i * D_ * E_, E_,
            h, D_, nullptr, h);

        // 7) layernorm
        layernorm_kernel<<<T_, 256>>>(h, ln_g + (size_t)i * D_, ln_b + (size_t)i * D_);
    }

    mean_kernel<<<dim3(D_ / 256, B_), 256>>>(h, (float*)d_out);
}

// round 6
// speedup vs baseline: 2.5266x; 1.2525x over previous
#include <cuda_runtime.h>
#include <cuda_bf16.h>
#include <cstdint>
#include <math.h>

// ---------------------------------------------------------------------------
// Problem constants (MambaModel: B=4, L=1024, D=1024, E=2048, N=16, K=4, R=64)
// ---------------------------------------------------------------------------
constexpr int B_  = 4;
constexpr int L_  = 1024;
constexpr int D_  = 1024;
constexpr int E_  = 2048;
constexpr int NS_ = 16;
constexpr int KC_ = 4;
constexpr int R_  = 64;
constexpr int NL_ = 4;
constexpr int T_  = B_ * L_;       // 4096
constexpr int XD_ = R_ + 2 * NS_;  // 96
constexpr int XSPLIT_ = 8;         // split-K for x_dbl HMMA

#define CDIV(a, b) (((a) + (b) - 1) / (b))

// ---------------------------------------------------------------------------
// Scratch (fp32)
// ---------------------------------------------------------------------------
__device__ float g_h    [(size_t)T_ * D_];
__device__ float g_xz   [(size_t)T_ * 2 * E_];
__device__ float g_u    [(size_t)T_ * E_];
__device__ float g_xdbl [(size_t)T_ * XD_];
__device__ float g_xp   [(size_t)XSPLIT_ * T_ * 128];
__device__ float g_delta[(size_t)T_ * E_];

// bf16 hi/lo operand buffers
__device__ __nv_bfloat16 g_winh[(size_t)NL_ * 2 * E_ * D_];
__device__ __nv_bfloat16 g_winl[(size_t)NL_ * 2 * E_ * D_];
__device__ __nv_bfloat16 g_wouth[(size_t)NL_ * D_ * E_];
__device__ __nv_bfloat16 g_woutl[(size_t)NL_ * D_ * E_];
__device__ __nv_bfloat16 g_wdth[(size_t)NL_ * E_ * R_];
__device__ __nv_bfloat16 g_wdtl[(size_t)NL_ * E_ * R_];
__device__ __nv_bfloat16 g_wxph[(size_t)NL_ * 128 * E_];
__device__ __nv_bfloat16 g_wxpl[(size_t)NL_ * 128 * E_];
__device__ __nv_bfloat16 g_hh[(size_t)T_ * D_];
__device__ __nv_bfloat16 g_hl[(size_t)T_ * D_];
__device__ __nv_bfloat16 g_uh[(size_t)T_ * E_];
__device__ __nv_bfloat16 g_ul[(size_t)T_ * E_];
__device__ __nv_bfloat16 g_yh[(size_t)T_ * E_];
__device__ __nv_bfloat16 g_yl[(size_t)T_ * E_];
__device__ __nv_bfloat16 g_dtrh[(size_t)T_ * R_];
__device__ __nv_bfloat16 g_dtrl[(size_t)T_ * R_];

// ---------------------------------------------------------------------------
// Helpers
// ---------------------------------------------------------------------------
__device__ __forceinline__ uint32_t smem_to_u32(const void* p) {
    uint32_t a;
    asm("{ .reg .u64 t; cvta.to.shared.u64 t, %1; cvt.u32.u64 %0, t; }"
        : "=r"(a) : "l"(p));
    return a;
}

__device__ __forceinline__ void cp_async16(uint32_t dst, const void* src) {
    asm volatile("cp.async.cg.shared.global [%0], [%1], 16;" :: "r"(dst), "l"(src));
}
#define CP_COMMIT() asm volatile("cp.async.commit_group;" ::: "memory")
#define CP_WAIT1()  asm volatile("cp.async.wait_group 1;" ::: "memory")

__device__ __forceinline__ void ldmatrix_x4(uint32_t& r0, uint32_t& r1,
                                            uint32_t& r2, uint32_t& r3,
                                            uint32_t addr) {
    asm volatile("ldmatrix.sync.aligned.m8n8.x4.shared.b16 {%0,%1,%2,%3}, [%4];"
                 : "=r"(r0), "=r"(r1), "=r"(r2), "=r"(r3) : "r"(addr));
}

__device__ __forceinline__ void mma_bf16(float& c0, float& c1, float& c2, float& c3,
                                         uint32_t a0, uint32_t a1, uint32_t a2, uint32_t a3,
                                         uint32_t b0, uint32_t b1) {
    asm volatile(
        "mma.sync.aligned.m16n8k16.row.col.f32.bf16.bf16.f32 "
        "{%0,%1,%2,%3}, {%4,%5,%6,%7}, {%8,%9}, {%0,%1,%2,%3};"
        : "+f"(c0), "+f"(c1), "+f"(c2), "+f"(c3)
        : "r"(a0), "r"(a1), "r"(a2), "r"(a3), "r"(b0), "r"(b1));
}

// SW64 swizzle for 64B-row tiles (128 rows x 32 bf16)
__device__ __forceinline__ uint32_t sw64(uint32_t off) {
    return off ^ ((off >> 3) & 0x30);
}

__device__ __forceinline__ void split_bf16(float v, __nv_bfloat16& h, __nv_bfloat16& l) {
    h = __float2bfloat16(v);
    l = __float2bfloat16(v - __bfloat162float(h));
}

// ===========================================================================
// HMMA GEMM (all-bf16 operands): C[M,N] = A[M,K]*B[N,K]^T + epi.
// A/B given as hi/lo bf16 pairs. Block 128x128, K-chunk 32, double-buffered
// cp.async. 256 threads = 8 warps (4m x 2n), warp tile 32x64, bf16x3 passes.
// EPI: 0 plain, 1 softplus(acc+bias[n]), 2 acc+res.
// kchunk!=0: split-K (blockIdx.z selects K window + C slab).
// M%128==0, N%128==0, K%32==0 required.
// ===========================================================================
__device__ __forceinline__ void load_tile_async(
    const __nv_bfloat16* src, int ld, uint32_t dst_sb, int tid)
{
#pragma unroll
    for (int i = 0; i < 2; i++) {
        const int idx = tid + (i << 8);         // 0..511
        const int row = idx >> 2;               // 0..127
        const int c   = idx & 3;                // 16B chunk in 64B row
        const uint32_t off = (uint32_t)(row << 6) + (uint32_t)(c << 4);
        cp_async16(dst_sb + sw64(off), src + (size_t)row * ld + (c << 3));
    }
}

constexpr int GS_STAGE = 32768;   // bytes per stage
constexpr int GS_AL = 8192, GS_BH = 16384, GS_BL = 24576;
constexpr int GS_SMEM = 2 * GS_STAGE;  // 64 KB

template <int EPI>
__global__ __launch_bounds__(256) void hmma_gemm(
    int M, int N, int K,
    const __nv_bfloat16* __restrict__ Ah, const __nv_bfloat16* __restrict__ Al, int lda,
    const __nv_bfloat16* __restrict__ Bh, const __nv_bfloat16* __restrict__ Bl, int ldb,
    float* __restrict__ C, int ldc,
    const float* __restrict__ bias,
    const float* __restrict__ res,
    int kchunk, long long cslab)
{
    extern __shared__ __align__(1024) char smem[];
    const uint32_t sb = smem_to_u32(smem);
    const int tid    = threadIdx.x;
    const int wid    = tid >> 5;
    const int lane   = tid & 31;
    const int mb     = (wid >> 1) * 32;
    const int nb     = (wid & 1) * 64;
    const int m0 = blockIdx.y * 128;
    const int n0 = blockIdx.x * 128;

    int Kloc = K, koff = 0;
    if (kchunk) {
        Kloc = kchunk;
        koff = blockIdx.z * kchunk;
        C += (size_t)blockIdx.z * cslab;
    }

    const __nv_bfloat16* A0h = Ah + (size_t)m0 * lda + koff;
    const __nv_bfloat16* A0l = Al + (size_t)m0 * lda + koff;
    const __nv_bfloat16* B0h = Bh + (size_t)n0 * ldb + koff;
    const __nv_bfloat16* B0l = Bl + (size_t)n0 * ldb + koff;

    const int a_row_off = (lane & 15);
    const int a_koff    = (lane >> 4) << 4;
    const int b_row_off = (lane & 7) + ((lane >> 4) << 3);
    const int b_koff    = ((lane >> 3) & 1) << 4;

    float acc[2][8][4];
#pragma unroll
    for (int i = 0; i < 2; i++)
#pragma unroll
        for (int j = 0; j < 8; j++)
#pragma unroll
            for (int q = 0; q < 4; q++) acc[i][j][q] = 0.f;

    const int nch = Kloc >> 5;

#define LOAD_CHUNK(kc, stage)                                                  \
    do {                                                                       \
        const int kk = (kc) << 5;                                              \
        const uint32_t s0 = sb + (stage) * GS_STAGE;                           \
        load_tile_async(A0h + kk, lda, s0,          tid);                      \
        load_tile_async(A0l + kk, lda, s0 + GS_AL,  tid);                      \
        load_tile_async(B0h + kk, ldb, s0 + GS_BH,  tid);                      \
        load_tile_async(B0l + kk, ldb, s0 + GS_BL,  tid);                      \
    } while (0)

    LOAD_CHUNK(0, 0);
    CP_COMMIT();

    int buf = 0;
#pragma unroll 1
    for (int kc = 0; kc < nch; kc++) {
        if (kc + 1 < nch) LOAD_CHUNK(kc + 1, buf ^ 1);
        CP_COMMIT();
        CP_WAIT1();
        __syncthreads();

        const uint32_t stage = sb + buf * GS_STAGE;
#pragma unroll
        for (int s = 0; s < 2; s++) {
            const int ks = s << 5;
#pragma unroll
            for (int p = 0; p < 3; p++) {
                const uint32_t abase = stage + (p == 1 ? GS_AL : 0);
                const uint32_t bbase = stage + GS_BH + (p == 2 ? GS_AL : 0);

                uint32_t a[2][4];
#pragma unroll
                for (int tm = 0; tm < 2; tm++) {
                    const int row = mb + tm * 16 + a_row_off;
                    ldmatrix_x4(a[tm][0], a[tm][1], a[tm][2], a[tm][3],
                                abase + sw64((uint32_t)(row << 6) + ks + a_koff));
                }
                uint32_t b[4][4];
#pragma unroll
                for (int g = 0; g < 4; g++) {
                    const int row = nb + g * 16 + b_row_off;
                    ldmatrix_x4(b[g][0], b[g][1], b[g][2], b[g][3],
                                bbase + sw64((uint32_t)(row << 6) + ks + b_koff));
                }
#pragma unroll
                for (int tm = 0; tm < 2; tm++)
#pragma unroll
                    for (int g = 0; g < 4; g++) {
                        mma_bf16(acc[tm][2*g][0], acc[tm][2*g][1], acc[tm][2*g][2], acc[tm][2*g][3],
                                 a[tm][0], a[tm][1], a[tm][2], a[tm][3], b[g][0], b[g][1]);
                        mma_bf16(acc[tm][2*g+1][0], acc[tm][2*g+1][1], acc[tm][2*g+1][2], acc[tm][2*g+1][3],
                                 a[tm][0], a[tm][1], a[tm][2], a[tm][3], b[g][2], b[g][3]);
                    }
            }
        }
        __syncthreads();
        buf ^= 1;
    }
#undef LOAD_CHUNK

    const int erow = m0 + mb + (lane >> 2);
    const int ecol0 = n0 + nb + (lane & 3) * 2;
#pragma unroll
    for (int tm = 0; tm < 2; tm++) {
#pragma unroll
        for (int j = 0; j < 8; j++) {
            const int col = ecol0 + j * 8;
#pragma unroll
            for (int half = 0; half < 2; half++) {
                const int row = erow + tm * 16 + half * 8;
                float v0 = acc[tm][j][2 * half + 0];
                float v1 = acc[tm][j][2 * half + 1];
                if (EPI == 1) {
                    v0 += bias[col];
                    v1 += bias[col + 1];
                    v0 = (v0 > 20.f) ? v0 : log1pf(__expf(v0));
                    v1 = (v1 > 20.f) ? v1 : log1pf(__expf(v1));
                } else if (EPI == 2) {
                    v0 += res[(size_t)row * ldc + col];
                    v1 += res[(size_t)row * ldc + col + 1];
                }
                C[(size_t)row * ldc + col]     = v0;
                C[(size_t)row * ldc + col + 1] = v1;
            }
        }
    }
}

// ---------------------------------------------------------------------------
// Weight / activation split kernels
// ---------------------------------------------------------------------------
__global__ void split_kernel(const float4* __restrict__ src,
                             __nv_bfloat16* __restrict__ dh,
                             __nv_bfloat16* __restrict__ dl, int n4)
{
    const int i = blockIdx.x * blockDim.x + threadIdx.x;
    if (i >= n4) return;
    float4 v = src[i];
    __nv_bfloat16 h0, h1, h2, h3, l0, l1, l2, l3;
    split_bf16(v.x, h0, l0); split_bf16(v.y, h1, l1);
    split_bf16(v.z, h2, l2); split_bf16(v.w, h3, l3);
    __nv_bfloat162 hp0 = __halves2bfloat162(h0, h1), hp1 = __halves2bfloat162(h2, h3);
    __nv_bfloat162 lp0 = __halves2bfloat162(l0, l1), lp1 = __halves2bfloat162(l2, l3);
    uint2 hv = {*reinterpret_cast<uint32_t*>(&hp0), *reinterpret_cast<uint32_t*>(&hp1)};
    uint2 lv = {*reinterpret_cast<uint32_t*>(&lp0), *reinterpret_cast<uint32_t*>(&lp1)};
    *reinterpret_cast<uint2*>(dh + 4 * (size_t)i) = hv;
    *reinterpret_cast<uint2*>(dl + 4 * (size_t)i) = lv;
}

// Wx (NL, 96, E) -> padded (NL, 128, E) hi/lo, rows 96..127 zero.
__global__ void wxpad_kernel(const float* __restrict__ wx,
                             __nv_bfloat16* __restrict__ dh,
                             __nv_bfloat16* __restrict__ dl)
{
    const int i = blockIdx.x * blockDim.x + threadIdx.x;
    const int nt = NL_ * 128 * E_;
    if (i >= nt) return;
    const int lyr = i / (128 * E_);
    const int rem = i - lyr * 128 * E_;
    const int r = rem / E_;
    const int c = rem - r * E_;
    float v = (r < XD_) ? wx[((size_t)lyr * XD_ + r) * E_ + c] : 0.f;
    __nv_bfloat16 h, l;
    split_bf16(v, h, l);
    dh[i] = h; dl[i] = l;
}

__global__ void init_h_kernel(const float4* __restrict__ x, float4* __restrict__ h,
                              __nv_bfloat16* __restrict__ hh,
                              __nv_bfloat16* __restrict__ hl, int n4)
{
    const int i = blockIdx.x * blockDim.x + threadIdx.x;
    if (i >= n4) return;
    float4 v = x[i];
    h[i] = v;
    __nv_bfloat16 h0, h1, h2, h3, l0, l1, l2, l3;
    split_bf16(v.x, h0, l0); split_bf16(v.y, h1, l1);
    split_bf16(v.z, h2, l2); split_bf16(v.w, h3, l3);
    __nv_bfloat162 hp0 = __halves2bfloat162(h0, h1), hp1 = __halves2bfloat162(h2, h3);
    __nv_bfloat162 lp0 = __halves2bfloat162(l0, l1), lp1 = __halves2bfloat162(l2, l3);
    uint2 hv = {*reinterpret_cast<uint32_t*>(&hp0), *reinterpret_cast<uint32_t*>(&hp1)};
    uint2 lv = {*reinterpret_cast<uint32_t*>(&lp0), *reinterpret_cast<uint32_t*>(&lp1)};
    *reinterpret_cast<uint2*>(hh + 4 * (size_t)i) = hv;
    *reinterpret_cast<uint2*>(hl + 4 * (size_t)i) = lv;
}

// ---------------------------------------------------------------------------
// Depthwise causal conv1d + SiLU; writes u fp32 and bf16 hi/lo.
// ---------------------------------------------------------------------------
__global__ void conv_silu_kernel(
    const float* __restrict__ xz, const float* __restrict__ cw,
    const float* __restrict__ cb, float* __restrict__ u,
    __nv_bfloat16* __restrict__ uh, __nv_bfloat16* __restrict__ ul)
{
    const int e = blockIdx.x * blockDim.x + threadIdx.x;
    const int t = blockIdx.y;
    const int l = t & (L_ - 1);
    const float4 w = reinterpret_cast<const float4*>(cw)[e];
    float acc = cb[e];
    const float* col = xz + e;
    if (l >= 3) acc = fmaf(col[(size_t)(t - 3) * (2 * E_)], w.x, acc);
    if (l >= 2) acc = fmaf(col[(size_t)(t - 2) * (2 * E_)], w.y, acc);
    if (l >= 1) acc = fmaf(col[(size_t)(t - 1) * (2 * E_)], w.z, acc);
    acc = fmaf(col[(size_t)t * (2 * E_)], w.w, acc);
    const float v = acc / (1.f + __expf(-acc));
    const size_t o = (size_t)t * E_ + e;
    u[o] = v;
    __nv_bfloat16 hh, ll;
    split_bf16(v, hh, ll);
    uh[o] = hh; ul[o] = ll;
}

// ---------------------------------------------------------------------------
// Split-K reduce for x_dbl (128-wide partials -> 96-wide) + dtr hi/lo
// ---------------------------------------------------------------------------
__global__ void reduce_xdbl_kernel(const float* __restrict__ xp,
                                   float* __restrict__ xdbl,
                                   __nv_bfloat16* __restrict__ dtrh,
                                   __nv_bfloat16* __restrict__ dtrl)
{
    const int i = blockIdx.x * blockDim.x + threadIdx.x;
    if (i >= T_ * XD_) return;
    const int t = i / XD_;
    const int c = i - t * XD_;
    float s = 0.f;
#pragma unroll
    for (int k = 0; k < XSPLIT_; k++) s += xp[(size_t)k * T_ * 128 + (size_t)t * 128 + c];
    xdbl[i] = s;
    if (c < R_) {
        __nv_bfloat16 hh, ll;
        split_bf16(s, hh, ll);
        dtrh[(size_t)t * R_ + c] = hh;
        dtrl[(size_t)t * R_ + c] = ll;
    }
}

// ---------------------------------------------------------------------------
// Selective scan; writes y as bf16 hi/lo (only GEMM6 consumes y).
// ---------------------------------------------------------------------------
__device__ __forceinline__ void scan_step(
    float d, float uu, float z,
    float4 B0, float4 B1, float4 B2, float4 B3,
    float4 C0, float4 C1, float4 C2, float4 C3,
    const float* __restrict__ An, float dp,
    float* __restrict__ h, __nv_bfloat16* yh, __nv_bfloat16* yl)
{
    const float du = d * uu;
    float Bv[NS_] = {B0.x, B0.y, B0.z, B0.w, B1.x, B1.y, B1.z, B1.w,
                     B2.x, B2.y, B2.z, B2.w, B3.x, B3.y, B3.z, B3.w};
    float Cv[NS_] = {C0.x, C0.y, C0.z, C0.w, C1.x, C1.y, C1.z, C1.w,
                     C2.x, C2.y, C2.z, C2.w, C3.x, C3.y, C3.z, C3.w};
    float yv = 0.f;
#pragma unroll
    for (int n = 0; n < NS_; n++) {
        const float dA = __expf(d * An[n]);
        h[n] = fmaf(dA, h[n], du * Bv[n]);
        yv = fmaf(h[n], Cv[n], yv);
    }
    const float sz = z / (1.f + __expf(-z));
    const float v = (yv + dp * uu) * sz;
    __nv_bfloat16 hh, ll;
    split_bf16(v, hh, ll);
    *yh = hh; *yl = ll;
}

__global__ __launch_bounds__(32) void scan_kernel(
    const float* __restrict__ delta, const float* __restrict__ u,
    const float* __restrict__ xz, const float* __restrict__ xdbl,
    const float* __restrict__ Alog, const float* __restrict__ Dp,
    __nv_bfloat16* __restrict__ yh, __nv_bfloat16* __restrict__ yl)
{
    const int e = blockIdx.x * 32 + threadIdx.x;
    const int b = blockIdx.y;
    const int tbase = b * L_;

    float An[NS_];
#pragma unroll
    for (int n = 0; n < NS_; n++) An[n] = -__expf(Alog[(size_t)e * NS_ + n]);
    const float dp = Dp[e];

    float h[NS_];
#pragma unroll
    for (int n = 0; n < NS_; n++) h[n] = 0.f;

#define SCAN_LOAD(S, t)                                                         \
    do {                                                                        \
        d##S = delta[(size_t)(t) * E_ + e];                                     \
        u##S = u[(size_t)(t) * E_ + e];                                         \
        z##S = xz[(size_t)(t) * (2 * E_) + E_ + e];                             \
        const float4* bp = reinterpret_cast<const float4*>(xdbl + (size_t)(t) * XD_ + R_); \
        B##S##0 = bp[0]; B##S##1 = bp[1]; B##S##2 = bp[2]; B##S##3 = bp[3];     \
        C##S##0 = bp[4]; C##S##1 = bp[5]; C##S##2 = bp[6]; C##S##3 = bp[7];     \
    } while (0)

    float d0, u0, z0, d1, u1, z1;
    float4 B00, B01, B02, B03, C00, C01, C02, C03;
    float4 B10, B11, B12, B13, C10, C11, C12, C13;

    SCAN_LOAD(0, tbase);
#pragma unroll 1
    for (int l = 0; l < L_; l += 2) {
        SCAN_LOAD(1, tbase + l + 1);
        scan_step(d0, u0, z0, B00, B01, B02, B03, C00, C01, C02, C03,
                  An, dp, h,
                  &yh[(size_t)(tbase + l) * E_ + e], &yl[(size_t)(tbase + l) * E_ + e]);
        if (l + 2 < L_) SCAN_LOAD(0, tbase + l + 2);
        scan_step(d1, u1, z1, B10, B11, B12, B13, C10, C11, C12, C13,
                  An, dp, h,
                  &yh[(size_t)(tbase + l + 1) * E_ + e], &yl[(size_t)(tbase + l + 1) * E_ + e]);
    }
#undef SCAN_LOAD
}

// ---------------------------------------------------------------------------
// LayerNorm over D, in place; also writes h hi/lo bf16.
// ---------------------------------------------------------------------------
__global__ void layernorm_kernel(float* __restrict__ h,
                                 const float* __restrict__ g,
                                 const float* __restrict__ bb,
                                 __nv_bfloat16* __restrict__ hh,
                                 __nv_bfloat16* __restrict__ hl)
{
    const int t = blockIdx.x;
    float* row = h + (size_t)t * D_;
    float s = 0.f, s2 = 0.f;
    for (int i = threadIdx.x; i < D_; i += blockDim.x) {
        const float v = row[i];
        s += v;
        s2 = fmaf(v, v, s2);
    }
    __shared__ float red[64];
#pragma unroll
    for (int o = 16; o > 0; o >>= 1) {
        s  += __shfl_xor_sync(0xFFFFFFFFu, s, o);
        s2 += __shfl_xor_sync(0xFFFFFFFFu, s2, o);
    }
    const int wid = threadIdx.x >> 5, lid = threadIdx.x & 31;
    if (lid == 0) { red[wid] = s; red[32 + wid] = s2; }
    __syncthreads();
    if (threadIdx.x < 32) {
        const int nw = blockDim.x >> 5;
        float a = (threadIdx.x < nw) ? red[threadIdx.x] : 0.f;
        float c = (threadIdx.x < nw) ? red[32 + threadIdx.x] : 0.f;
#pragma unroll
        for (int o = 16; o > 0; o >>= 1) {
            a += __shfl_xor_sync(0xFFFFFFFFu, a, o);
            c += __shfl_xor_sync(0xFFFFFFFFu, c, o);
        }
        if (threadIdx.x == 0) { red[0] = a; red[1] = c; }
    }
    __syncthreads();
    const float mean = red[0] * (1.f / D_);
    const float var  = red[1] * (1.f / D_) - mean * mean;
    const float inv  = rsqrtf(var + 1e-5f);
    for (int i = threadIdx.x; i < D_; i += blockDim.x) {
        const float v = (row[i] - mean) * inv * g[i] + bb[i];
        row[i] = v;
        __nv_bfloat16 hv, lv;
        split_bf16(v, hv, lv);
        hh[(size_t)t * D_ + i] = hv;
        hl[(size_t)t * D_ + i] = lv;
    }
}

__global__ void mean_kernel(const float* __restrict__ h, float* __restrict__ out) {
    const int d = blockIdx.x * blockDim.x + threadIdx.x;
    const int b = blockIdx.y;
    const float* p = h + (size_t)b * L_ * D_ + d;
    float s = 0.f;
    for (int l = 0; l < L_; l++) s += p[(size_t)l * D_];
    out[b * D_ + d] = s * (1.f / L_);
}

// ---------------------------------------------------------------------------
// Launch
// ---------------------------------------------------------------------------
extern "C" void kernel_launch(void* const* d_in, const int* in_sizes, int n_in,
                              void* d_out, int out_size)
{
    const float* x     = (const float*)d_in[0];
    const float* Win   = (const float*)d_in[1];
    const float* convw = (const float*)d_in[2];
    const float* convb = (const float*)d_in[3];
    const float* Wx    = (const float*)d_in[4];
    const float* Wdt   = (const float*)d_in[5];
    const float* bdt   = (const float*)d_in[6];
    const float* Alog  = (const float*)d_in[7];
    const float* Dp    = (const float*)d_in[8];
    const float* Wout  = (const float*)d_in[9];
    const float* ln_g  = (const float*)d_in[10];
    const float* ln_b  = (const float*)d_in[11];

    float *h, *xz, *u, *xdbl, *xp, *delta;
    cudaGetSymbolAddress((void**)&h,     g_h);
    cudaGetSymbolAddress((void**)&xz,    g_xz);
    cudaGetSymbolAddress((void**)&u,     g_u);
    cudaGetSymbolAddress((void**)&xdbl,  g_xdbl);
    cudaGetSymbolAddress((void**)&xp,    g_xp);
    cudaGetSymbolAddress((void**)&delta, g_delta);

    __nv_bfloat16 *winh, *winl, *wouth, *woutl, *wdth, *wdtl, *wxph, *wxpl;
    __nv_bfloat16 *hh, *hl, *uh, *ul, *yh, *yl, *dtrh, *dtrl;
    cudaGetSymbolAddress((void**)&winh,  g_winh);
    cudaGetSymbolAddress((void**)&winl,  g_winl);
    cudaGetSymbolAddress((void**)&wouth, g_wouth);
    cudaGetSymbolAddress((void**)&woutl, g_woutl);
    cudaGetSymbolAddress((void**)&wdth,  g_wdth);
    cudaGetSymbolAddress((void**)&wdtl,  g_wdtl);
    cudaGetSymbolAddress((void**)&wxph,  g_wxph);
    cudaGetSymbolAddress((void**)&wxpl,  g_wxpl);
    cudaGetSymbolAddress((void**)&hh,    g_hh);
    cudaGetSymbolAddress((void**)&hl,    g_hl);
    cudaGetSymbolAddress((void**)&uh,    g_uh);
    cudaGetSymbolAddress((void**)&ul,    g_ul);
    cudaGetSymbolAddress((void**)&yh,    g_yh);
    cudaGetSymbolAddress((void**)&yl,    g_yl);
    cudaGetSymbolAddress((void**)&dtrh,  g_dtrh);
    cudaGetSymbolAddress((void**)&dtrl,  g_dtrl);

    cudaFuncSetAttribute(hmma_gemm<0>, cudaFuncAttributeMaxDynamicSharedMemorySize, GS_SMEM);
    cudaFuncSetAttribute(hmma_gemm<1>, cudaFuncAttributeMaxDynamicSharedMemorySize, GS_SMEM);
    cudaFuncSetAttribute(hmma_gemm<2>, cudaFuncAttributeMaxDynamicSharedMemorySize, GS_SMEM);

    // ---- one-time (per call) weight splits ----
    {
        int n4 = NL_ * 2 * E_ * D_ / 4;
        split_kernel<<<CDIV(n4, 256), 256>>>((const float4*)Win, winh, winl, n4);
        n4 = NL_ * D_ * E_ / 4;
        split_kernel<<<CDIV(n4, 256), 256>>>((const float4*)Wout, wouth, woutl, n4);
        n4 = NL_ * E_ * R_ / 4;
        split_kernel<<<CDIV(n4, 256), 256>>>((const float4*)Wdt, wdth, wdtl, n4);
        const int nt = NL_ * 128 * E_;
        wxpad_kernel<<<CDIV(nt, 256), 256>>>(Wx, wxph, wxpl);
    }

    const int n4 = (T_ * D_) / 4;
    init_h_kernel<<<CDIV(n4, 256), 256>>>((const float4*)x, (float4*)h, hh, hl, n4);

    for (int i = 0; i < NL_; i++) {
        // 1) xz = h @ Win^T   (4096 x 4096, K=1024)
        hmma_gemm<0><<<dim3((2 * E_) / 128, T_ / 128), 256, GS_SMEM>>>(
            T_, 2 * E_, D_,
            hh, hl, D_,
            winh + (size_t)i * 2 * E_ * D_, winl + (size_t)i * 2 * E_ * D_, D_,
            xz, 2 * E_, nullptr, nullptr, 0, 0);

        // 2) u = silu(causal_conv(xz[:, :E]) + convb)   (+ bf16 split)
        conv_silu_kernel<<<dim3(E_ / 256, T_), 256>>>(
            xz, convw + (size_t)i * E_ * KC_, convb + (size_t)i * E_, u, uh, ul);

        // 3) x_dbl = u @ Wx^T  (4096 x 128pad, K=2048), split-K x8 HMMA
        hmma_gemm<0><<<dim3(1, T_ / 128, XSPLIT_), 256, GS_SMEM>>>(
            T_, 128, E_,
            uh, ul, E_,
            wxph + (size_t)i * 128 * E_, wxpl + (size_t)i * 128 * E_, E_,
            xp, 128, nullptr, nullptr,
            E_ / XSPLIT_, (long long)T_ * 128);
        reduce_xdbl_kernel<<<CDIV(T_ * XD_, 256), 256>>>(xp, xdbl, dtrh, dtrl);

        // 4) delta = softplus(dtr @ Wdt^T + bdt)  (4096 x 2048, K=64)
        hmma_gemm<1><<<dim3(E_ / 128, T_ / 128), 256, GS_SMEM>>>(
            T_, E_, R_,
            dtrh, dtrl, R_,
            wdth + (size_t)i * E_ * R_, wdtl + (size_t)i * E_ * R_, R_,
            delta, E_, bdt + (size_t)i * E_, nullptr, 0, 0);

        // 5) selective scan -> y (bf16 hi/lo)
        scan_kernel<<<dim3(E_ / 32, B_), 32>>>(
            delta, u, xz, xdbl,
            Alog + (size_t)i * E_ * NS_, Dp + (size_t)i * E_, yh, yl);

        // 6) h = y @ Wout^T + h  (4096 x 1024, K=2048)
        hmma_gemm<2><<<dim3(D_ / 128, T_ / 128), 256, GS_SMEM>>>(
            T_, D_, E_,
            yh, yl, E_,
            wouth + (size_t)i * D_ * E_, woutl + (size_t)i * D_ * E_, E_,
            h, D_, nullptr, h, 0, 0);

        // 7) layernorm (+ h bf16 split)
        layernorm_kernel<<<T_, 256>>>(h, ln_g + (size_t)i * D_, ln_b + (size_t)i * D_, hh, hl);
    }

    mean_kernel<<<dim3(D_ / 256, B_), 256>>>(h, (float*)d_out);
}

// round 7
// speedup vs baseline: 2.5733x; 1.0185x over previous
#include <cuda_runtime.h>
#include <cuda_bf16.h>
#include <cstdint>
#include <math.h>

// ---------------------------------------------------------------------------
// Problem constants (MambaModel: B=4, L=1024, D=1024, E=2048, N=16, K=4, R=64)
// ---------------------------------------------------------------------------
constexpr int B_  = 4;
constexpr int L_  = 1024;
constexpr int D_  = 1024;
constexpr int E_  = 2048;
constexpr int NS_ = 16;
constexpr int KC_ = 4;
constexpr int R_  = 64;
constexpr int NL_ = 4;
constexpr int T_  = B_ * L_;       // 4096
constexpr int XD_ = R_ + 2 * NS_;  // 96
constexpr int XSPLIT_ = 8;         // split-K for x_dbl HMMA

#define CDIV(a, b) (((a) + (b) - 1) / (b))

// ---------------------------------------------------------------------------
// Scratch (fp32)
// ---------------------------------------------------------------------------
__device__ float g_h    [(size_t)T_ * D_];
__device__ float g_xz   [(size_t)T_ * 2 * E_];
__device__ float g_u    [(size_t)T_ * E_];
__device__ float g_xdbl [(size_t)T_ * XD_];
__device__ float g_xp   [(size_t)XSPLIT_ * T_ * 128];
__device__ float g_delta[(size_t)T_ * E_];

// bf16 hi/lo operand buffers
__device__ __nv_bfloat16 g_winh[(size_t)NL_ * 2 * E_ * D_];
__device__ __nv_bfloat16 g_winl[(size_t)NL_ * 2 * E_ * D_];
__device__ __nv_bfloat16 g_wouth[(size_t)NL_ * D_ * E_];
__device__ __nv_bfloat16 g_woutl[(size_t)NL_ * D_ * E_];
__device__ __nv_bfloat16 g_wdth[(size_t)NL_ * E_ * R_];
__device__ __nv_bfloat16 g_wdtl[(size_t)NL_ * E_ * R_];
__device__ __nv_bfloat16 g_wxph[(size_t)NL_ * 128 * E_];
__device__ __nv_bfloat16 g_wxpl[(size_t)NL_ * 128 * E_];
__device__ __nv_bfloat16 g_hh[(size_t)T_ * D_];
__device__ __nv_bfloat16 g_hl[(size_t)T_ * D_];
__device__ __nv_bfloat16 g_uh[(size_t)T_ * E_];
__device__ __nv_bfloat16 g_ul[(size_t)T_ * E_];
__device__ __nv_bfloat16 g_yh[(size_t)T_ * E_];
__device__ __nv_bfloat16 g_yl[(size_t)T_ * E_];
__device__ __nv_bfloat16 g_dtrh[(size_t)T_ * R_];
__device__ __nv_bfloat16 g_dtrl[(size_t)T_ * R_];

// ---------------------------------------------------------------------------
// Helpers
// ---------------------------------------------------------------------------
__device__ __forceinline__ uint32_t smem_to_u32(const void* p) {
    uint32_t a;
    asm("{ .reg .u64 t; cvta.to.shared.u64 t, %1; cvt.u32.u64 %0, t; }"
        : "=r"(a) : "l"(p));
    return a;
}

__device__ __forceinline__ void cp_async16(uint32_t dst, const void* src) {
    asm volatile("cp.async.cg.shared.global [%0], [%1], 16;" :: "r"(dst), "l"(src));
}
#define CP_COMMIT() asm volatile("cp.async.commit_group;" ::: "memory")
#define CP_WAIT1()  asm volatile("cp.async.wait_group 1;" ::: "memory")

__device__ __forceinline__ void ldmatrix_x4(uint32_t& r0, uint32_t& r1,
                                            uint32_t& r2, uint32_t& r3,
                                            uint32_t addr) {
    asm volatile("ldmatrix.sync.aligned.m8n8.x4.shared.b16 {%0,%1,%2,%3}, [%4];"
                 : "=r"(r0), "=r"(r1), "=r"(r2), "=r"(r3) : "r"(addr));
}

__device__ __forceinline__ void mma_bf16(float& c0, float& c1, float& c2, float& c3,
                                         uint32_t a0, uint32_t a1, uint32_t a2, uint32_t a3,
                                         uint32_t b0, uint32_t b1) {
    asm volatile(
        "mma.sync.aligned.m16n8k16.row.col.f32.bf16.bf16.f32 "
        "{%0,%1,%2,%3}, {%4,%5,%6,%7}, {%8,%9}, {%0,%1,%2,%3};"
        : "+f"(c0), "+f"(c1), "+f"(c2), "+f"(c3)
        : "r"(a0), "r"(a1), "r"(a2), "r"(a3), "r"(b0), "r"(b1));
}

// SW64 swizzle for 64B-row tiles (128 rows x 32 bf16)
__device__ __forceinline__ uint32_t sw64(uint32_t off) {
    return off ^ ((off >> 3) & 0x30);
}

__device__ __forceinline__ void split_bf16(float v, __nv_bfloat16& h, __nv_bfloat16& l) {
    h = __float2bfloat16(v);
    l = __float2bfloat16(v - __bfloat162float(h));
}

// ===========================================================================
// HMMA GEMM (all-bf16 operands): C[M,N] = A[M,K]*B[N,K]^T + epi.
// Block 128x128, K-chunk 32, double-buffered cp.async, bf16x3 passes.
// EPI: 0 plain, 1 softplus(acc+bias[n]), 2 acc+res.
// ===========================================================================
__device__ __forceinline__ void load_tile_async(
    const __nv_bfloat16* src, int ld, uint32_t dst_sb, int tid)
{
#pragma unroll
    for (int i = 0; i < 2; i++) {
        const int idx = tid + (i << 8);         // 0..511
        const int row = idx >> 2;               // 0..127
        const int c   = idx & 3;                // 16B chunk in 64B row
        const uint32_t off = (uint32_t)(row << 6) + (uint32_t)(c << 4);
        cp_async16(dst_sb + sw64(off), src + (size_t)row * ld + (c << 3));
    }
}

constexpr int GS_STAGE = 32768;   // bytes per stage
constexpr int GS_AL = 8192, GS_BH = 16384, GS_BL = 24576;
constexpr int GS_SMEM = 2 * GS_STAGE;  // 64 KB

template <int EPI>
__global__ __launch_bounds__(256) void hmma_gemm(
    int M, int N, int K,
    const __nv_bfloat16* __restrict__ Ah, const __nv_bfloat16* __restrict__ Al, int lda,
    const __nv_bfloat16* __restrict__ Bh, const __nv_bfloat16* __restrict__ Bl, int ldb,
    float* __restrict__ C, int ldc,
    const float* __restrict__ bias,
    const float* __restrict__ res,
    int kchunk, long long cslab)
{
    extern __shared__ __align__(1024) char smem[];
    const uint32_t sb = smem_to_u32(smem);
    const int tid    = threadIdx.x;
    const int wid    = tid >> 5;
    const int lane   = tid & 31;
    const int mb     = (wid >> 1) * 32;
    const int nb     = (wid & 1) * 64;
    const int m0 = blockIdx.y * 128;
    const int n0 = blockIdx.x * 128;

    int Kloc = K, koff = 0;
    if (kchunk) {
        Kloc = kchunk;
        koff = blockIdx.z * kchunk;
        C += (size_t)blockIdx.z * cslab;
    }

    const __nv_bfloat16* A0h = Ah + (size_t)m0 * lda + koff;
    const __nv_bfloat16* A0l = Al + (size_t)m0 * lda + koff;
    const __nv_bfloat16* B0h = Bh + (size_t)n0 * ldb + koff;
    const __nv_bfloat16* B0l = Bl + (size_t)n0 * ldb + koff;

    const int a_row_off = (lane & 15);
    const int a_koff    = (lane >> 4) << 4;
    const int b_row_off = (lane & 7) + ((lane >> 4) << 3);
    const int b_koff    = ((lane >> 3) & 1) << 4;

    float acc[2][8][4];
#pragma unroll
    for (int i = 0; i < 2; i++)
#pragma unroll
        for (int j = 0; j < 8; j++)
#pragma unroll
            for (int q = 0; q < 4; q++) acc[i][j][q] = 0.f;

    const int nch = Kloc >> 5;

#define LOAD_CHUNK(kc, stage)                                                  \
    do {                                                                       \
        const int kk = (kc) << 5;                                              \
        const uint32_t s0 = sb + (stage) * GS_STAGE;                           \
        load_tile_async(A0h + kk, lda, s0,          tid);                      \
        load_tile_async(A0l + kk, lda, s0 + GS_AL,  tid);                      \
        load_tile_async(B0h + kk, ldb, s0 + GS_BH,  tid);                      \
        load_tile_async(B0l + kk, ldb, s0 + GS_BL,  tid);                      \
    } while (0)

    LOAD_CHUNK(0, 0);
    CP_COMMIT();

    int buf = 0;
#pragma unroll 1
    for (int kc = 0; kc < nch; kc++) {
        if (kc + 1 < nch) LOAD_CHUNK(kc + 1, buf ^ 1);
        CP_COMMIT();
        CP_WAIT1();
        __syncthreads();

        const uint32_t stage = sb + buf * GS_STAGE;
#pragma unroll
        for (int s = 0; s < 2; s++) {
            const int ks = s << 5;
#pragma unroll
            for (int p = 0; p < 3; p++) {
                const uint32_t abase = stage + (p == 1 ? GS_AL : 0);
                const uint32_t bbase = stage + GS_BH + (p == 2 ? GS_AL : 0);

                uint32_t a[2][4];
#pragma unroll
                for (int tm = 0; tm < 2; tm++) {
                    const int row = mb + tm * 16 + a_row_off;
                    ldmatrix_x4(a[tm][0], a[tm][1], a[tm][2], a[tm][3],
                                abase + sw64((uint32_t)(row << 6) + ks + a_koff));
                }
                uint32_t b[4][4];
#pragma unroll
                for (int g = 0; g < 4; g++) {
                    const int row = nb + g * 16 + b_row_off;
                    ldmatrix_x4(b[g][0], b[g][1], b[g][2], b[g][3],
                                bbase + sw64((uint32_t)(row << 6) + ks + b_koff));
                }
#pragma unroll
                for (int tm = 0; tm < 2; tm++)
#pragma unroll
                    for (int g = 0; g < 4; g++) {
                        mma_bf16(acc[tm][2*g][0], acc[tm][2*g][1], acc[tm][2*g][2], acc[tm][2*g][3],
                                 a[tm][0], a[tm][1], a[tm][2], a[tm][3], b[g][0], b[g][1]);
                        mma_bf16(acc[tm][2*g+1][0], acc[tm][2*g+1][1], acc[tm][2*g+1][2], acc[tm][2*g+1][3],
                                 a[tm][0], a[tm][1], a[tm][2], a[tm][3], b[g][2], b[g][3]);
                    }
            }
        }
        __syncthreads();
        buf ^= 1;
    }
#undef LOAD_CHUNK

    const int erow = m0 + mb + (lane >> 2);
    const int ecol0 = n0 + nb + (lane & 3) * 2;
#pragma unroll
    for (int tm = 0; tm < 2; tm++) {
#pragma unroll
        for (int j = 0; j < 8; j++) {
            const int col = ecol0 + j * 8;
#pragma unroll
            for (int half = 0; half < 2; half++) {
                const int row = erow + tm * 16 + half * 8;
                float v0 = acc[tm][j][2 * half + 0];
                float v1 = acc[tm][j][2 * half + 1];
                if (EPI == 1) {
                    v0 += bias[col];
                    v1 += bias[col + 1];
                    v0 = (v0 > 20.f) ? v0 : log1pf(__expf(v0));
                    v1 = (v1 > 20.f) ? v1 : log1pf(__expf(v1));
                } else if (EPI == 2) {
                    v0 += res[(size_t)row * ldc + col];
                    v1 += res[(size_t)row * ldc + col + 1];
                }
                C[(size_t)row * ldc + col]     = v0;
                C[(size_t)row * ldc + col + 1] = v1;
            }
        }
    }
}

// ---------------------------------------------------------------------------
// Weight / activation split kernels
// ---------------------------------------------------------------------------
__global__ void split_kernel(const float4* __restrict__ src,
                             __nv_bfloat16* __restrict__ dh,
                             __nv_bfloat16* __restrict__ dl, int n4)
{
    const int i = blockIdx.x * blockDim.x + threadIdx.x;
    if (i >= n4) return;
    float4 v = src[i];
    __nv_bfloat16 h0, h1, h2, h3, l0, l1, l2, l3;
    split_bf16(v.x, h0, l0); split_bf16(v.y, h1, l1);
    split_bf16(v.z, h2, l2); split_bf16(v.w, h3, l3);
    __nv_bfloat162 hp0 = __halves2bfloat162(h0, h1), hp1 = __halves2bfloat162(h2, h3);
    __nv_bfloat162 lp0 = __halves2bfloat162(l0, l1), lp1 = __halves2bfloat162(l2, l3);
    uint2 hv = {*reinterpret_cast<uint32_t*>(&hp0), *reinterpret_cast<uint32_t*>(&hp1)};
    uint2 lv = {*reinterpret_cast<uint32_t*>(&lp0), *reinterpret_cast<uint32_t*>(&lp1)};
    *reinterpret_cast<uint2*>(dh + 4 * (size_t)i) = hv;
    *reinterpret_cast<uint2*>(dl + 4 * (size_t)i) = lv;
}

// Wx (NL, 96, E) -> padded (NL, 128, E) hi/lo, rows 96..127 zero.
__global__ void wxpad_kernel(const float* __restrict__ wx,
                             __nv_bfloat16* __restrict__ dh,
                             __nv_bfloat16* __restrict__ dl)
{
    const int i = blockIdx.x * blockDim.x + threadIdx.x;
    const int nt = NL_ * 128 * E_;
    if (i >= nt) return;
    const int lyr = i / (128 * E_);
    const int rem = i - lyr * 128 * E_;
    const int r = rem / E_;
    const int c = rem - r * E_;
    float v = (r < XD_) ? wx[((size_t)lyr * XD_ + r) * E_ + c] : 0.f;
    __nv_bfloat16 h, l;
    split_bf16(v, h, l);
    dh[i] = h; dl[i] = l;
}

__global__ void init_h_kernel(const float4* __restrict__ x, float4* __restrict__ h,
                              __nv_bfloat16* __restrict__ hh,
                              __nv_bfloat16* __restrict__ hl, int n4)
{
    const int i = blockIdx.x * blockDim.x + threadIdx.x;
    if (i >= n4) return;
    float4 v = x[i];
    h[i] = v;
    __nv_bfloat16 h0, h1, h2, h3, l0, l1, l2, l3;
    split_bf16(v.x, h0, l0); split_bf16(v.y, h1, l1);
    split_bf16(v.z, h2, l2); split_bf16(v.w, h3, l3);
    __nv_bfloat162 hp0 = __halves2bfloat162(h0, h1), hp1 = __halves2bfloat162(h2, h3);
    __nv_bfloat162 lp0 = __halves2bfloat162(l0, l1), lp1 = __halves2bfloat162(l2, l3);
    uint2 hv = {*reinterpret_cast<uint32_t*>(&hp0), *reinterpret_cast<uint32_t*>(&hp1)};
    uint2 lv = {*reinterpret_cast<uint32_t*>(&lp0), *reinterpret_cast<uint32_t*>(&lp1)};
    *reinterpret_cast<uint2*>(hh + 4 * (size_t)i) = hv;
    *reinterpret_cast<uint2*>(hl + 4 * (size_t)i) = lv;
}

// ---------------------------------------------------------------------------
// Depthwise causal conv1d + SiLU; writes u fp32 and bf16 hi/lo.
// ---------------------------------------------------------------------------
__global__ void conv_silu_kernel(
    const float* __restrict__ xz, const float* __restrict__ cw,
    const float* __restrict__ cb, float* __restrict__ u,
    __nv_bfloat16* __restrict__ uh, __nv_bfloat16* __restrict__ ul)
{
    const int e = blockIdx.x * blockDim.x + threadIdx.x;
    const int t = blockIdx.y;
    const int l = t & (L_ - 1);
    const float4 w = reinterpret_cast<const float4*>(cw)[e];
    float acc = cb[e];
    const float* col = xz + e;
    if (l >= 3) acc = fmaf(col[(size_t)(t - 3) * (2 * E_)], w.x, acc);
    if (l >= 2) acc = fmaf(col[(size_t)(t - 2) * (2 * E_)], w.y, acc);
    if (l >= 1) acc = fmaf(col[(size_t)(t - 1) * (2 * E_)], w.z, acc);
    acc = fmaf(col[(size_t)t * (2 * E_)], w.w, acc);
    const float v = acc / (1.f + __expf(-acc));
    const size_t o = (size_t)t * E_ + e;
    u[o] = v;
    __nv_bfloat16 hh, ll;
    split_bf16(v, hh, ll);
    uh[o] = hh; ul[o] = ll;
}

// ---------------------------------------------------------------------------
// Split-K reduce for x_dbl (128-wide partials -> 96-wide) + dtr hi/lo
// ---------------------------------------------------------------------------
__global__ void reduce_xdbl_kernel(const float* __restrict__ xp,
                                   float* __restrict__ xdbl,
                                   __nv_bfloat16* __restrict__ dtrh,
                                   __nv_bfloat16* __restrict__ dtrl)
{
    const int i = blockIdx.x * blockDim.x + threadIdx.x;
    if (i >= T_ * XD_) return;
    const int t = i / XD_;
    const int c = i - t * XD_;
    float s = 0.f;
#pragma unroll
    for (int k = 0; k < XSPLIT_; k++) s += xp[(size_t)k * T_ * 128 + (size_t)t * 128 + c];
    xdbl[i] = s;
    if (c < R_) {
        __nv_bfloat16 hh, ll;
        split_bf16(s, hh, ll);
        dtrh[(size_t)t * R_ + c] = hh;
        dtrl[(size_t)t * R_ + c] = ll;
    }
}

// ---------------------------------------------------------------------------
// Selective scan, state-parallel: 4 lanes per channel, 4 states each.
// Block 128 threads covers 32 channels; grid (E/32, B) = 256 blocks.
// y reduced across the quad via shfl; lane0 applies +Dp*u and *silu(z),
// writes bf16 hi/lo. 2-step software pipeline on all loads.
// ---------------------------------------------------------------------------
__global__ __launch_bounds__(128) void scan_kernel(
    const float* __restrict__ delta, const float* __restrict__ u,
    const float* __restrict__ xz, const float* __restrict__ xdbl,
    const float* __restrict__ Alog, const float* __restrict__ Dp,
    __nv_bfloat16* __restrict__ yh, __nv_bfloat16* __restrict__ yl)
{
    const int tid = threadIdx.x;
    const int sg  = tid & 3;                   // state group 0..3 (4 states)
    const int e   = blockIdx.x * 32 + (tid >> 2);
    const int b   = blockIdx.y;
    const int tbase = b * L_;

    float An[4];
#pragma unroll
    for (int j = 0; j < 4; j++)
        An[j] = -__expf(Alog[(size_t)e * NS_ + sg * 4 + j]);
    const float dp = Dp[e];

    float h0 = 0.f, h1 = 0.f, h2 = 0.f, h3 = 0.f;

#define SLOAD(S, t)                                                             \
    do {                                                                        \
        d##S = delta[(size_t)(t) * E_ + e];                                     \
        u##S = u[(size_t)(t) * E_ + e];                                         \
        z##S = xz[(size_t)(t) * (2 * E_) + E_ + e];                             \
        Bv##S = *reinterpret_cast<const float4*>(xdbl + (size_t)(t) * XD_ + R_ + sg * 4);        \
        Cv##S = *reinterpret_cast<const float4*>(xdbl + (size_t)(t) * XD_ + R_ + NS_ + sg * 4);  \
    } while (0)

#define SSTEP(S, t)                                                             \
    do {                                                                        \
        const float du = d##S * u##S;                                           \
        h0 = fmaf(__expf(d##S * An[0]), h0, du * Bv##S.x);                      \
        h1 = fmaf(__expf(d##S * An[1]), h1, du * Bv##S.y);                      \
        h2 = fmaf(__expf(d##S * An[2]), h2, du * Bv##S.z);                      \
        h3 = fmaf(__expf(d##S * An[3]), h3, du * Bv##S.w);                      \
        float yv = h0 * Cv##S.x + h1 * Cv##S.y + h2 * Cv##S.z + h3 * Cv##S.w;   \
        yv += __shfl_xor_sync(0xFFFFFFFFu, yv, 1);                              \
        yv += __shfl_xor_sync(0xFFFFFFFFu, yv, 2);                              \
        if (sg == 0) {                                                          \
            const float sz = z##S / (1.f + __expf(-z##S));                      \
            const float v = (yv + dp * u##S) * sz;                              \
            __nv_bfloat16 vh, vl;                                               \
            split_bf16(v, vh, vl);                                              \
            yh[(size_t)(t) * E_ + e] = vh;                                      \
            yl[(size_t)(t) * E_ + e] = vl;                                      \
        }                                                                       \
    } while (0)

    float d0, u0, z0, d1, u1, z1;
    float4 Bv0, Cv0, Bv1, Cv1;

    SLOAD(0, tbase);
#pragma unroll 1
    for (int l = 0; l < L_; l += 2) {
        SLOAD(1, tbase + l + 1);
        SSTEP(0, tbase + l);
        if (l + 2 < L_) SLOAD(0, tbase + l + 2);
        SSTEP(1, tbase + l + 1);
    }
#undef SLOAD
#undef SSTEP
}

// ---------------------------------------------------------------------------
// LayerNorm over D, in place; also writes h hi/lo bf16.
// ---------------------------------------------------------------------------
__global__ void layernorm_kernel(float* __restrict__ h,
                                 const float* __restrict__ g,
                                 const float* __restrict__ bb,
                                 __nv_bfloat16* __restrict__ hh,
                                 __nv_bfloat16* __restrict__ hl)
{
    const int t = blockIdx.x;
    float* row = h + (size_t)t * D_;
    float s = 0.f, s2 = 0.f;
    for (int i = threadIdx.x; i < D_; i += blockDim.x) {
        const float v = row[i];
        s += v;
        s2 = fmaf(v, v, s2);
    }
    __shared__ float red[64];
#pragma unroll
    for (int o = 16; o > 0; o >>= 1) {
        s  += __shfl_xor_sync(0xFFFFFFFFu, s, o);
        s2 += __shfl_xor_sync(0xFFFFFFFFu, s2, o);
    }
    const int wid = threadIdx.x >> 5, lid = threadIdx.x & 31;
    if (lid == 0) { red[wid] = s; red[32 + wid] = s2; }
    __syncthreads();
    if (threadIdx.x < 32) {
        const int nw = blockDim.x >> 5;
        float a = (threadIdx.x < nw) ? red[threadIdx.x] : 0.f;
        float c = (threadIdx.x < nw) ? red[32 + threadIdx.x] : 0.f;
#pragma unroll
        for (int o = 16; o > 0; o >>= 1) {
            a += __shfl_xor_sync(0xFFFFFFFFu, a, o);
            c += __shfl_xor_sync(0xFFFFFFFFu, c, o);
        }
        if (threadIdx.x == 0) { red[0] = a; red[1] = c; }
    }
    __syncthreads();
    const float mean = red[0] * (1.f / D_);
    const float var  = red[1] * (1.f / D_) - mean * mean;
    const float inv  = rsqrtf(var + 1e-5f);
    for (int i = threadIdx.x; i < D_; i += blockDim.x) {
        const float v = (row[i] - mean) * inv * g[i] + bb[i];
        row[i] = v;
        __nv_bfloat16 hv, lv;
        split_bf16(v, hv, lv);
        hh[(size_t)t * D_ + i] = hv;
        hl[(size_t)t * D_ + i] = lv;
    }
}

__global__ void mean_kernel(const float* __restrict__ h, float* __restrict__ out) {
    const int d = blockIdx.x * blockDim.x + threadIdx.x;
    const int b = blockIdx.y;
    const float* p = h + (size_t)b * L_ * D_ + d;
    float s = 0.f;
    for (int l = 0; l < L_; l++) s += p[(size_t)l * D_];
    out[b * D_ + d] = s * (1.f / L_);
}

// ---------------------------------------------------------------------------
// Launch
// ---------------------------------------------------------------------------
extern "C" void kernel_launch(void* const* d_in, const int* in_sizes, int n_in,
                              void* d_out, int out_size)
{
    const float* x     = (const float*)d_in[0];
    const float* Win   = (const float*)d_in[1];
    const float* convw = (const float*)d_in[2];
    const float* convb = (const float*)d_in[3];
    const float* Wx    = (const float*)d_in[4];
    const float* Wdt   = (const float*)d_in[5];
    const float* bdt   = (const float*)d_in[6];
    const float* Alog  = (const float*)d_in[7];
    const float* Dp    = (const float*)d_in[8];
    const float* Wout  = (const float*)d_in[9];
    const float* ln_g  = (const float*)d_in[10];
    const float* ln_b  = (const float*)d_in[11];

    float *h, *xz, *u, *xdbl, *xp, *delta;
    cudaGetSymbolAddress((void**)&h,     g_h);
    cudaGetSymbolAddress((void**)&xz,    g_xz);
    cudaGetSymbolAddress((void**)&u,     g_u);
    cudaGetSymbolAddress((void**)&xdbl,  g_xdbl);
    cudaGetSymbolAddress((void**)&xp,    g_xp);
    cudaGetSymbolAddress((void**)&delta, g_delta);

    __nv_bfloat16 *winh, *winl, *wouth, *woutl, *wdth, *wdtl, *wxph, *wxpl;
    __nv_bfloat16 *hh, *hl, *uh, *ul, *yh, *yl, *dtrh, *dtrl;
    cudaGetSymbolAddress((void**)&winh,  g_winh);
    cudaGetSymbolAddress((void**)&winl,  g_winl);
    cudaGetSymbolAddress((void**)&wouth, g_wouth);
    cudaGetSymbolAddress((void**)&woutl, g_woutl);
    cudaGetSymbolAddress((void**)&wdth,  g_wdth);
    cudaGetSymbolAddress((void**)&wdtl,  g_wdtl);
    cudaGetSymbolAddress((void**)&wxph,  g_wxph);
    cudaGetSymbolAddress((void**)&wxpl,  g_wxpl);
    cudaGetSymbolAddress((void**)&hh,    g_hh);
    cudaGetSymbolAddress((void**)&hl,    g_hl);
    cudaGetSymbolAddress((void**)&uh,    g_uh);
    cudaGetSymbolAddress((void**)&ul,    g_ul);
    cudaGetSymbolAddress((void**)&yh,    g_yh);
    cudaGetSymbolAddress((void**)&yl,    g_yl);
    cudaGetSymbolAddress((void**)&dtrh,  g_dtrh);
    cudaGetSymbolAddress((void**)&dtrl,  g_dtrl);

    cudaFuncSetAttribute(hmma_gemm<0>, cudaFuncAttributeMaxDynamicSharedMemorySize, GS_SMEM);
    cudaFuncSetAttribute(hmma_gemm<1>, cudaFuncAttributeMaxDynamicSharedMemorySize, GS_SMEM);
    cudaFuncSetAttribute(hmma_gemm<2>, cudaFuncAttributeMaxDynamicSharedMemorySize, GS_SMEM);

    // ---- one-time (per call) weight splits ----
    {
        int n4 = NL_ * 2 * E_ * D_ / 4;
        split_kernel<<<CDIV(n4, 256), 256>>>((const float4*)Win, winh, winl, n4);
        n4 = NL_ * D_ * E_ / 4;
        split_kernel<<<CDIV(n4, 256), 256>>>((const float4*)Wout, wouth, woutl, n4);
        n4 = NL_ * E_ * R_ / 4;
        split_kernel<<<CDIV(n4, 256), 256>>>((const float4*)Wdt, wdth, wdtl, n4);
        const int nt = NL_ * 128 * E_;
        wxpad_kernel<<<CDIV(nt, 256), 256>>>(Wx, wxph, wxpl);
    }

    const int n4 = (T_ * D_) / 4;
    init_h_kernel<<<CDIV(n4, 256), 256>>>((const float4*)x, (float4*)h, hh, hl, n4);

    for (int i = 0; i < NL_; i++) {
        // 1) xz = h @ Win^T   (4096 x 4096, K=1024)
        hmma_gemm<0><<<dim3((2 * E_) / 128, T_ / 128), 256, GS_SMEM>>>(
            T_, 2 * E_, D_,
            hh, hl, D_,
            winh + (size_t)i * 2 * E_ * D_, winl + (size_t)i * 2 * E_ * D_, D_,
            xz, 2 * E_, nullptr, nullptr, 0, 0);

        // 2) u = silu(causal_conv(xz[:, :E]) + convb)   (+ bf16 split)
        conv_silu_kernel<<<dim3(E_ / 256, T_), 256>>>(
            xz, convw + (size_t)i * E_ * KC_, convb + (size_t)i * E_, u, uh, ul);

        // 3) x_dbl = u @ Wx^T  (4096 x 128pad, K=2048), split-K x8 HMMA
        hmma_gemm<0><<<dim3(1, T_ / 128, XSPLIT_), 256, GS_SMEM>>>(
            T_, 128, E_,
            uh, ul, E_,
            wxph + (size_t)i * 128 * E_, wxpl + (size_t)i * 128 * E_, E_,
            xp, 128, nullptr, nullptr,
            E_ / XSPLIT_, (long long)T_ * 128);
        reduce_xdbl_kernel<<<CDIV(T_ * XD_, 256), 256>>>(xp, xdbl, dtrh, dtrl);

        // 4) delta = softplus(dtr @ Wdt^T + bdt)  (4096 x 2048, K=64)
        hmma_gemm<1><<<dim3(E_ / 128, T_ / 128), 256, GS_SMEM>>>(
            T_, E_, R_,
            dtrh, dtrl, R_,
            wdth + (size_t)i * E_ * R_, wdtl + (size_t)i * E_ * R_, R_,
            delta, E_, bdt + (size_t)i * E_, nullptr, 0, 0);

        // 5) selective scan -> y (state-parallel, bf16 hi/lo out)
        scan_kernel<<<dim3(E_ / 32, B_), 128>>>(
            delta, u, xz, xdbl,
            Alog + (size_t)i * E_ * NS_, Dp + (size_t)i * E_, yh, yl);

        // 6) h = y @ Wout^T + h  (4096 x 1024, K=2048)
        hmma_gemm<2><<<dim3(D_ / 128, T_ / 128), 256, GS_SMEM>>>(
            T_, D_, E_,
            yh, yl, E_,
            wouth + (size_t)i * D_ * E_, woutl + (size_t)i * D_ * E_, E_,
            h, D_, nullptr, h, 0, 0);

        // 7) layernorm (+ h bf16 split)
        layernorm_kernel<<<T_, 256>>>(h, ln_g + (size_t)i * D_, ln_b + (size_t)i * D_, hh, hl);
    }

    mean_kernel<<<dim3(D_ / 256, B_), 256>>>(h, (float*)d_out);
}

// round 8
// speedup vs baseline: 2.7166x; 1.0557x over previous
#include <cuda_runtime.h>
#include <cuda_bf16.h>
#include <cstdint>
#include <math.h>

// ---------------------------------------------------------------------------
// Problem constants (MambaModel: B=4, L=1024, D=1024, E=2048, N=16, K=4, R=64)
// ---------------------------------------------------------------------------
constexpr int B_  = 4;
constexpr int L_  = 1024;
constexpr int D_  = 1024;
constexpr int E_  = 2048;
constexpr int NS_ = 16;
constexpr int KC_ = 4;
constexpr int R_  = 64;
constexpr int NL_ = 4;
constexpr int T_  = B_ * L_;       // 4096
constexpr int XD_ = R_ + 2 * NS_;  // 96
constexpr int XSPLIT_ = 8;         // split-K for x_dbl HMMA

#define CDIV(a, b) (((a) + (b) - 1) / (b))

// ---------------------------------------------------------------------------
// Scratch (fp32)
// ---------------------------------------------------------------------------
__device__ float g_h    [(size_t)T_ * D_];
__device__ float g_xz   [(size_t)T_ * 2 * E_];
__device__ float g_u    [(size_t)T_ * E_];
__device__ float g_xdbl [(size_t)T_ * XD_];
__device__ float g_xp   [(size_t)XSPLIT_ * T_ * 128];
__device__ float g_delta[(size_t)T_ * E_];

// bf16 hi/lo operand buffers
__device__ __nv_bfloat16 g_winh[(size_t)NL_ * 2 * E_ * D_];
__device__ __nv_bfloat16 g_winl[(size_t)NL_ * 2 * E_ * D_];
__device__ __nv_bfloat16 g_wouth[(size_t)NL_ * D_ * E_];
__device__ __nv_bfloat16 g_woutl[(size_t)NL_ * D_ * E_];
__device__ __nv_bfloat16 g_wdth[(size_t)NL_ * E_ * R_];
__device__ __nv_bfloat16 g_wdtl[(size_t)NL_ * E_ * R_];
__device__ __nv_bfloat16 g_wxph[(size_t)NL_ * 128 * E_];
__device__ __nv_bfloat16 g_wxpl[(size_t)NL_ * 128 * E_];
__device__ __nv_bfloat16 g_hh[(size_t)T_ * D_];
__device__ __nv_bfloat16 g_hl[(size_t)T_ * D_];
__device__ __nv_bfloat16 g_uh[(size_t)T_ * E_];
__device__ __nv_bfloat16 g_ul[(size_t)T_ * E_];
__device__ __nv_bfloat16 g_yh[(size_t)T_ * E_];
__device__ __nv_bfloat16 g_yl[(size_t)T_ * E_];
__device__ __nv_bfloat16 g_dtrh[(size_t)T_ * R_];
__device__ __nv_bfloat16 g_dtrl[(size_t)T_ * R_];

// ---------------------------------------------------------------------------
// Helpers
// ---------------------------------------------------------------------------
__device__ __forceinline__ uint32_t smem_to_u32(const void* p) {
    uint32_t a;
    asm("{ .reg .u64 t; cvta.to.shared.u64 t, %1; cvt.u32.u64 %0, t; }"
        : "=r"(a) : "l"(p));
    return a;
}

__device__ __forceinline__ void cp_async16(uint32_t dst, const void* src) {
    asm volatile("cp.async.cg.shared.global [%0], [%1], 16;" :: "r"(dst), "l"(src));
}
#define CP_COMMIT() asm volatile("cp.async.commit_group;" ::: "memory")
#define CP_WAIT1()  asm volatile("cp.async.wait_group 1;" ::: "memory")

__device__ __forceinline__ void ldmatrix_x4(uint32_t& r0, uint32_t& r1,
                                            uint32_t& r2, uint32_t& r3,
                                            uint32_t addr) {
    asm volatile("ldmatrix.sync.aligned.m8n8.x4.shared.b16 {%0,%1,%2,%3}, [%4];"
                 : "=r"(r0), "=r"(r1), "=r"(r2), "=r"(r3) : "r"(addr));
}

__device__ __forceinline__ void mma_bf16(float& c0, float& c1, float& c2, float& c3,
                                         uint32_t a0, uint32_t a1, uint32_t a2, uint32_t a3,
                                         uint32_t b0, uint32_t b1) {
    asm volatile(
        "mma.sync.aligned.m16n8k16.row.col.f32.bf16.bf16.f32 "
        "{%0,%1,%2,%3}, {%4,%5,%6,%7}, {%8,%9}, {%0,%1,%2,%3};"
        : "+f"(c0), "+f"(c1), "+f"(c2), "+f"(c3)
        : "r"(a0), "r"(a1), "r"(a2), "r"(a3), "r"(b0), "r"(b1));
}

// SW128 swizzle for 128B-row tiles (128 rows x 64 bf16)
__device__ __forceinline__ uint32_t sw128(uint32_t off) {
    return off ^ ((off >> 3) & 0x70);
}

__device__ __forceinline__ void split_bf16(float v, __nv_bfloat16& h, __nv_bfloat16& l) {
    h = __float2bfloat16(v);
    l = __float2bfloat16(v - __bfloat162float(h));
}

// ===========================================================================
// HMMA GEMM v2 (bf16x3): C[M,N] = A[M,K]*B[N,K]^T + epi.
// Block 128x128, K-chunk 64, 2-stage cp.async pipeline (128 KB smem).
// 256 threads = 8 warps (4m x 2n), warp tile 32x64.
// Per k16 step: 12 unique ldmatrix.x4 (Ah,Al,Bh,Bl), then 48 mma (3 passes).
// EPI: 0 plain, 1 softplus(acc+bias[n]), 2 acc+res.
// ===========================================================================
constexpr int GT_TILE  = 16384;              // 128 rows x 128 bytes
constexpr int GT_AL = GT_TILE, GT_BH = 2 * GT_TILE, GT_BL = 3 * GT_TILE;
constexpr int GT_STAGE = 4 * GT_TILE;        // 64 KB
constexpr int GT_SMEM  = 2 * GT_STAGE;       // 128 KB

__device__ __forceinline__ void load_tile_async64(
    const __nv_bfloat16* src, int ld, uint32_t dst_sb, int tid)
{
#pragma unroll
    for (int i = 0; i < 4; i++) {
        const int idx = tid + (i << 8);         // 0..1023
        const int row = idx >> 3;               // 0..127
        const int c   = idx & 7;                // 16B chunk in 128B row
        const uint32_t off = (uint32_t)(row << 7) + (uint32_t)(c << 4);
        cp_async16(dst_sb + sw128(off), src + (size_t)row * ld + (c << 3));
    }
}

template <int EPI>
__global__ __launch_bounds__(256) void hmma_gemm(
    int M, int N, int K,
    const __nv_bfloat16* __restrict__ Ah, const __nv_bfloat16* __restrict__ Al, int lda,
    const __nv_bfloat16* __restrict__ Bh, const __nv_bfloat16* __restrict__ Bl, int ldb,
    float* __restrict__ C, int ldc,
    const float* __restrict__ bias,
    const float* __restrict__ res,
    int kchunk, long long cslab)
{
    extern __shared__ __align__(1024) char smem[];
    const uint32_t sb = smem_to_u32(smem);
    const int tid    = threadIdx.x;
    const int wid    = tid >> 5;
    const int lane   = tid & 31;
    const int mb     = (wid >> 1) * 32;
    const int nb     = (wid & 1) * 64;
    const int m0 = blockIdx.y * 128;
    const int n0 = blockIdx.x * 128;

    int Kloc = K, koff = 0;
    if (kchunk) {
        Kloc = kchunk;
        koff = blockIdx.z * kchunk;
        C += (size_t)blockIdx.z * cslab;
    }

    const __nv_bfloat16* A0h = Ah + (size_t)m0 * lda + koff;
    const __nv_bfloat16* A0l = Al + (size_t)m0 * lda + koff;
    const __nv_bfloat16* B0h = Bh + (size_t)n0 * ldb + koff;
    const __nv_bfloat16* B0l = Bl + (size_t)n0 * ldb + koff;

    const int a_row_off = (lane & 15);
    const int a_koff    = (lane >> 4) << 4;
    const int b_row_off = (lane & 7) + ((lane >> 4) << 3);
    const int b_koff    = ((lane >> 3) & 1) << 4;

    float acc[2][8][4];
#pragma unroll
    for (int i = 0; i < 2; i++)
#pragma unroll
        for (int j = 0; j < 8; j++)
#pragma unroll
            for (int q = 0; q < 4; q++) acc[i][j][q] = 0.f;

    const int nch = Kloc >> 6;

#define LOAD_CHUNK(kc, stage)                                                  \
    do {                                                                       \
        const int kk = (kc) << 6;                                              \
        const uint32_t s0 = sb + (stage) * GT_STAGE;                           \
        load_tile_async64(A0h + kk, lda, s0,          tid);                    \
        load_tile_async64(A0l + kk, lda, s0 + GT_AL,  tid);                    \
        load_tile_async64(B0h + kk, ldb, s0 + GT_BH,  tid);                    \
        load_tile_async64(B0l + kk, ldb, s0 + GT_BL,  tid);                    \
    } while (0)

    LOAD_CHUNK(0, 0);
    CP_COMMIT();

    int buf = 0;
#pragma unroll 1
    for (int kc = 0; kc < nch; kc++) {
        if (kc + 1 < nch) LOAD_CHUNK(kc + 1, buf ^ 1);
        CP_COMMIT();
        CP_WAIT1();
        __syncthreads();

        const uint32_t stage = sb + buf * GT_STAGE;
#pragma unroll
        for (int s = 0; s < 4; s++) {
            const int ks = s << 5;   // k16 step = 32 bytes

            // ---- load 12 unique fragments once ----
            uint32_t ah[2][4], al[2][4];
#pragma unroll
            for (int tm = 0; tm < 2; tm++) {
                const int row = mb + tm * 16 + a_row_off;
                const uint32_t off = sw128((uint32_t)(row << 7) + ks + a_koff);
                ldmatrix_x4(ah[tm][0], ah[tm][1], ah[tm][2], ah[tm][3], stage + off);
                ldmatrix_x4(al[tm][0], al[tm][1], al[tm][2], al[tm][3], stage + GT_AL + off);
            }
            uint32_t bh[4][4], bl[4][4];
#pragma unroll
            for (int g = 0; g < 4; g++) {
                const int row = nb + g * 16 + b_row_off;
                const uint32_t off = sw128((uint32_t)(row << 7) + ks + b_koff);
                ldmatrix_x4(bh[g][0], bh[g][1], bh[g][2], bh[g][3], stage + GT_BH + off);
                ldmatrix_x4(bl[g][0], bl[g][1], bl[g][2], bl[g][3], stage + GT_BL + off);
            }

            // ---- 3 passes x 16 mma, no reloads ----
#define DO_PASS(AF, BF)                                                        \
            _Pragma("unroll")                                                  \
            for (int tm = 0; tm < 2; tm++)                                     \
                _Pragma("unroll")                                              \
                for (int g = 0; g < 4; g++) {                                  \
                    mma_bf16(acc[tm][2*g][0], acc[tm][2*g][1],                 \
                             acc[tm][2*g][2], acc[tm][2*g][3],                 \
                             AF[tm][0], AF[tm][1], AF[tm][2], AF[tm][3],       \
                             BF[g][0], BF[g][1]);                              \
                    mma_bf16(acc[tm][2*g+1][0], acc[tm][2*g+1][1],             \
                             acc[tm][2*g+1][2], acc[tm][2*g+1][3],             \
                             AF[tm][0], AF[tm][1], AF[tm][2], AF[tm][3],       \
                             BF[g][2], BF[g][3]);                              \
                }
            DO_PASS(ah, bh)
            DO_PASS(al, bh)
            DO_PASS(ah, bl)
#undef DO_PASS
        }
        __syncthreads();
        buf ^= 1;
    }
#undef LOAD_CHUNK

    const int erow = m0 + mb + (lane >> 2);
    const int ecol0 = n0 + nb + (lane & 3) * 2;
#pragma unroll
    for (int tm = 0; tm < 2; tm++) {
#pragma unroll
        for (int j = 0; j < 8; j++) {
            const int col = ecol0 + j * 8;
#pragma unroll
            for (int half = 0; half < 2; half++) {
                const int row = erow + tm * 16 + half * 8;
                float v0 = acc[tm][j][2 * half + 0];
                float v1 = acc[tm][j][2 * half + 1];
                if (EPI == 1) {
                    v0 += bias[col];
                    v1 += bias[col + 1];
                    v0 = (v0 > 20.f) ? v0 : log1pf(__expf(v0));
                    v1 = (v1 > 20.f) ? v1 : log1pf(__expf(v1));
                } else if (EPI == 2) {
                    v0 += res[(size_t)row * ldc + col];
                    v1 += res[(size_t)row * ldc + col + 1];
                }
                C[(size_t)row * ldc + col]     = v0;
                C[(size_t)row * ldc + col + 1] = v1;
            }
        }
    }
}

// ---------------------------------------------------------------------------
// Weight / activation split kernels
// ---------------------------------------------------------------------------
__global__ void split_kernel(const float4* __restrict__ src,
                             __nv_bfloat16* __restrict__ dh,
                             __nv_bfloat16* __restrict__ dl, int n4)
{
    const int i = blockIdx.x * blockDim.x + threadIdx.x;
    if (i >= n4) return;
    float4 v = src[i];
    __nv_bfloat16 h0, h1, h2, h3, l0, l1, l2, l3;
    split_bf16(v.x, h0, l0); split_bf16(v.y, h1, l1);
    split_bf16(v.z, h2, l2); split_bf16(v.w, h3, l3);
    __nv_bfloat162 hp0 = __halves2bfloat162(h0, h1), hp1 = __halves2bfloat162(h2, h3);
    __nv_bfloat162 lp0 = __halves2bfloat162(l0, l1), lp1 = __halves2bfloat162(l2, l3);
    uint2 hv = {*reinterpret_cast<uint32_t*>(&hp0), *reinterpret_cast<uint32_t*>(&hp1)};
    uint2 lv = {*reinterpret_cast<uint32_t*>(&lp0), *reinterpret_cast<uint32_t*>(&lp1)};
    *reinterpret_cast<uint2*>(dh + 4 * (size_t)i) = hv;
    *reinterpret_cast<uint2*>(dl + 4 * (size_t)i) = lv;
}

// Wx (NL, 96, E) -> padded (NL, 128, E) hi/lo, rows 96..127 zero.
__global__ void wxpad_kernel(const float* __restrict__ wx,
                             __nv_bfloat16* __restrict__ dh,
                             __nv_bfloat16* __restrict__ dl)
{
    const int i = blockIdx.x * blockDim.x + threadIdx.x;
    const int nt = NL_ * 128 * E_;
    if (i >= nt) return;
    const int lyr = i / (128 * E_);
    const int rem = i - lyr * 128 * E_;
    const int r = rem / E_;
    const int c = rem - r * E_;
    float v = (r < XD_) ? wx[((size_t)lyr * XD_ + r) * E_ + c] : 0.f;
    __nv_bfloat16 h, l;
    split_bf16(v, h, l);
    dh[i] = h; dl[i] = l;
}

__global__ void init_h_kernel(const float4* __restrict__ x, float4* __restrict__ h,
                              __nv_bfloat16* __restrict__ hh,
                              __nv_bfloat16* __restrict__ hl, int n4)
{
    const int i = blockIdx.x * blockDim.x + threadIdx.x;
    if (i >= n4) return;
    float4 v = x[i];
    h[i] = v;
    __nv_bfloat16 h0, h1, h2, h3, l0, l1, l2, l3;
    split_bf16(v.x, h0, l0); split_bf16(v.y, h1, l1);
    split_bf16(v.z, h2, l2); split_bf16(v.w, h3, l3);
    __nv_bfloat162 hp0 = __halves2bfloat162(h0, h1), hp1 = __halves2bfloat162(h2, h3);
    __nv_bfloat162 lp0 = __halves2bfloat162(l0, l1), lp1 = __halves2bfloat162(l2, l3);
    uint2 hv = {*reinterpret_cast<uint32_t*>(&hp0), *reinterpret_cast<uint32_t*>(&hp1)};
    uint2 lv = {*reinterpret_cast<uint32_t*>(&lp0), *reinterpret_cast<uint32_t*>(&lp1)};
    *reinterpret_cast<uint2*>(hh + 4 * (size_t)i) = hv;
    *reinterpret_cast<uint2*>(hl + 4 * (size_t)i) = lv;
}

// ---------------------------------------------------------------------------
// Depthwise causal conv1d + SiLU; writes u fp32 and bf16 hi/lo.
// ---------------------------------------------------------------------------
__global__ void conv_silu_kernel(
    const float* __restrict__ xz, const float* __restrict__ cw,
    const float* __restrict__ cb, float* __restrict__ u,
    __nv_bfloat16* __restrict__ uh, __nv_bfloat16* __restrict__ ul)
{
    const int e = blockIdx.x * blockDim.x + threadIdx.x;
    const int t = blockIdx.y;
    const int l = t & (L_ - 1);
    const float4 w = reinterpret_cast<const float4*>(cw)[e];
    float acc = cb[e];
    const float* col = xz + e;
    if (l >= 3) acc = fmaf(col[(size_t)(t - 3) * (2 * E_)], w.x, acc);
    if (l >= 2) acc = fmaf(col[(size_t)(t - 2) * (2 * E_)], w.y, acc);
    if (l >= 1) acc = fmaf(col[(size_t)(t - 1) * (2 * E_)], w.z, acc);
    acc = fmaf(col[(size_t)t * (2 * E_)], w.w, acc);
    const float v = acc / (1.f + __expf(-acc));
    const size_t o = (size_t)t * E_ + e;
    u[o] = v;
    __nv_bfloat16 hh, ll;
    split_bf16(v, hh, ll);
    uh[o] = hh; ul[o] = ll;
}

// ---------------------------------------------------------------------------
// Split-K reduce for x_dbl (128-wide partials -> 96-wide) + dtr hi/lo
// ---------------------------------------------------------------------------
__global__ void reduce_xdbl_kernel(const float* __restrict__ xp,
                                   float* __restrict__ xdbl,
                                   __nv_bfloat16* __restrict__ dtrh,
                                   __nv_bfloat16* __restrict__ dtrl)
{
    const int i = blockIdx.x * blockDim.x + threadIdx.x;
    if (i >= T_ * XD_) return;
    const int t = i / XD_;
    const int c = i - t * XD_;
    float s = 0.f;
#pragma unroll
    for (int k = 0; k < XSPLIT_; k++) s += xp[(size_t)k * T_ * 128 + (size_t)t * 128 + c];
    xdbl[i] = s;
    if (c < R_) {
        __nv_bfloat16 hh, ll;
        split_bf16(s, hh, ll);
        dtrh[(size_t)t * R_ + c] = hh;
        dtrl[(size_t)t * R_ + c] = ll;
    }
}

// ---------------------------------------------------------------------------
// Selective scan, state-parallel: 4 lanes per channel, 4 states each.
// ---------------------------------------------------------------------------
__global__ __launch_bounds__(128) void scan_kernel(
    const float* __restrict__ delta, const float* __restrict__ u,
    const float* __restrict__ xz, const float* __restrict__ xdbl,
    const float* __restrict__ Alog, const float* __restrict__ Dp,
    __nv_bfloat16* __restrict__ yh, __nv_bfloat16* __restrict__ yl)
{
    const int tid = threadIdx.x;
    const int sg  = tid & 3;
    const int e   = blockIdx.x * 32 + (tid >> 2);
    const int b   = blockIdx.y;
    const int tbase = b * L_;

    float An[4];
#pragma unroll
    for (int j = 0; j < 4; j++)
        An[j] = -__expf(Alog[(size_t)e * NS_ + sg * 4 + j]);
    const float dp = Dp[e];

    float h0 = 0.f, h1 = 0.f, h2 = 0.f, h3 = 0.f;

#define SLOAD(S, t)                                                             \
    do {                                                                        \
        d##S = delta[(size_t)(t) * E_ + e];                                     \
        u##S = u[(size_t)(t) * E_ + e];                                         \
        z##S = xz[(size_t)(t) * (2 * E_) + E_ + e];                             \
        Bv##S = *reinterpret_cast<const float4*>(xdbl + (size_t)(t) * XD_ + R_ + sg * 4);        \
        Cv##S = *reinterpret_cast<const float4*>(xdbl + (size_t)(t) * XD_ + R_ + NS_ + sg * 4);  \
    } while (0)

#define SSTEP(S, t)                                                             \
    do {                                                                        \
        const float du = d##S * u##S;                                           \
        h0 = fmaf(__expf(d##S * An[0]), h0, du * Bv##S.x);                      \
        h1 = fmaf(__expf(d##S * An[1]), h1, du * Bv##S.y);                      \
        h2 = fmaf(__expf(d##S * An[2]), h2, du * Bv##S.z);                      \
        h3 = fmaf(__expf(d##S * An[3]), h3, du * Bv##S.w);                      \
        float yv = h0 * Cv##S.x + h1 * Cv##S.y + h2 * Cv##S.z + h3 * Cv##S.w;   \
        yv += __shfl_xor_sync(0xFFFFFFFFu, yv, 1);                              \
        yv += __shfl_xor_sync(0xFFFFFFFFu, yv, 2);                              \
        if (sg == 0) {                                                          \
            const float sz = z##S / (1.f + __expf(-z##S));                      \
            const float v = (yv + dp * u##S) * sz;                              \
            __nv_bfloat16 vh, vl;                                               \
            split_bf16(v, vh, vl);                                              \
            yh[(size_t)(t) * E_ + e] = vh;                                      \
            yl[(size_t)(t) * E_ + e] = vl;                                      \
        }                                                                       \
    } while (0)

    float d0, u0, z0, d1, u1, z1;
    float4 Bv0, Cv0, Bv1, Cv1;

    SLOAD(0, tbase);
#pragma unroll 1
    for (int l = 0; l < L_; l += 2) {
        SLOAD(1, tbase + l + 1);
        SSTEP(0, tbase + l);
        if (l + 2 < L_) SLOAD(0, tbase + l + 2);
        SSTEP(1, tbase + l + 1);
    }
#undef SLOAD
#undef SSTEP
}

// ---------------------------------------------------------------------------
// LayerNorm over D, in place; also writes h hi/lo bf16.
// ---------------------------------------------------------------------------
__global__ void layernorm_kernel(float* __restrict__ h,
                                 const float* __restrict__ g,
                                 const float* __restrict__ bb,
                                 __nv_bfloat16* __restrict__ hh,
                                 __nv_bfloat16* __restrict__ hl)
{
    const int t = blockIdx.x;
    float* row = h + (size_t)t * D_;
    float s = 0.f, s2 = 0.f;
    for (int i = threadIdx.x; i < D_; i += blockDim.x) {
        const float v = row[i];
        s += v;
        s2 = fmaf(v, v, s2);
    }
    __shared__ float red[64];
#pragma unroll
    for (int o = 16; o > 0; o >>= 1) {
        s  += __shfl_xor_sync(0xFFFFFFFFu, s, o);
        s2 += __shfl_xor_sync(0xFFFFFFFFu, s2, o);
    }
    const int wid = threadIdx.x >> 5, lid = threadIdx.x & 31;
    if (lid == 0) { red[wid] = s; red[32 + wid] = s2; }
    __syncthreads();
    if (threadIdx.x < 32) {
        const int nw = blockDim.x >> 5;
        float a = (threadIdx.x < nw) ? red[threadIdx.x] : 0.f;
        float c = (threadIdx.x < nw) ? red[32 + threadIdx.x] : 0.f;
#pragma unroll
        for (int o = 16; o > 0; o >>= 1) {
            a += __shfl_xor_sync(0xFFFFFFFFu, a, o);
            c += __shfl_xor_sync(0xFFFFFFFFu, c, o);
        }
        if (threadIdx.x == 0) { red[0] = a; red[1] = c; }
    }
    __syncthreads();
    const float mean = red[0] * (1.f / D_);
    const float var  = red[1] * (1.f / D_) - mean * mean;
    const float inv  = rsqrtf(var + 1e-5f);
    for (int i = threadIdx.x; i < D_; i += blockDim.x) {
        const float v = (row[i] - mean) * inv * g[i] + bb[i];
        row[i] = v;
        __nv_bfloat16 hv, lv;
        split_bf16(v, hv, lv);
        hh[(size_t)t * D_ + i] = hv;
        hl[(size_t)t * D_ + i] = lv;
    }
}

__global__ void mean_kernel(const float* __restrict__ h, float* __restrict__ out) {
    const int d = blockIdx.x * blockDim.x + threadIdx.x;
    const int b = blockIdx.y;
    const float* p = h + (size_t)b * L_ * D_ + d;
    float s = 0.f;
    for (int l = 0; l < L_; l++) s += p[(size_t)l * D_];
    out[b * D_ + d] = s * (1.f / L_);
}

// ---------------------------------------------------------------------------
// Launch
// ---------------------------------------------------------------------------
extern "C" void kernel_launch(void* const* d_in, const int* in_sizes, int n_in,
                              void* d_out, int out_size)
{
    const float* x     = (const float*)d_in[0];
    const float* Win   = (const float*)d_in[1];
    const float* convw = (const float*)d_in[2];
    const float* convb = (const float*)d_in[3];
    const float* Wx    = (const float*)d_in[4];
    const float* Wdt   = (const float*)d_in[5];
    const float* bdt   = (const float*)d_in[6];
    const float* Alog  = (const float*)d_in[7];
    const float* Dp    = (const float*)d_in[8];
    const float* Wout  = (const float*)d_in[9];
    const float* ln_g  = (const float*)d_in[10];
    const float* ln_b  = (const float*)d_in[11];

    float *h, *xz, *u, *xdbl, *xp, *delta;
    cudaGetSymbolAddress((void**)&h,     g_h);
    cudaGetSymbolAddress((void**)&xz,    g_xz);
    cudaGetSymbolAddress((void**)&u,     g_u);
    cudaGetSymbolAddress((void**)&xdbl,  g_xdbl);
    cudaGetSymbolAddress((void**)&xp,    g_xp);
    cudaGetSymbolAddress((void**)&delta, g_delta);

    __nv_bfloat16 *winh, *winl, *wouth, *woutl, *wdth, *wdtl, *wxph, *wxpl;
    __nv_bfloat16 *hh, *hl, *uh, *ul, *yh, *yl, *dtrh, *dtrl;
    cudaGetSymbolAddress((void**)&winh,  g_winh);
    cudaGetSymbolAddress((void**)&winl,  g_winl);
    cudaGetSymbolAddress((void**)&wouth, g_wouth);
    cudaGetSymbolAddress((void**)&woutl, g_woutl);
    cudaGetSymbolAddress((void**)&wdth,  g_wdth);
    cudaGetSymbolAddress((void**)&wdtl,  g_wdtl);
    cudaGetSymbolAddress((void**)&wxph,  g_wxph);
    cudaGetSymbolAddress((void**)&wxpl,  g_wxpl);
    cudaGetSymbolAddress((void**)&hh,    g_hh);
    cudaGetSymbolAddress((void**)&hl,    g_hl);
    cudaGetSymbolAddress((void**)&uh,    g_uh);
    cudaGetSymbolAddress((void**)&ul,    g_ul);
    cudaGetSymbolAddress((void**)&yh,    g_yh);
    cudaGetSymbolAddress((void**)&yl,    g_yl);
    cudaGetSymbolAddress((void**)&dtrh,  g_dtrh);
    cudaGetSymbolAddress((void**)&dtrl,  g_dtrl);

    cudaFuncSetAttribute(hmma_gemm<0>, cudaFuncAttributeMaxDynamicSharedMemorySize, GT_SMEM);
    cudaFuncSetAttribute(hmma_gemm<1>, cudaFuncAttributeMaxDynamicSharedMemorySize, GT_SMEM);
    cudaFuncSetAttribute(hmma_gemm<2>, cudaFuncAttributeMaxDynamicSharedMemorySize, GT_SMEM);

    // ---- one-time (per call) weight splits ----
    {
        int n4 = NL_ * 2 * E_ * D_ / 4;
        split_kernel<<<CDIV(n4, 256), 256>>>((const float4*)Win, winh, winl, n4);
        n4 = NL_ * D_ * E_ / 4;
        split_kernel<<<CDIV(n4, 256), 256>>>((const float4*)Wout, wouth, woutl, n4);
        n4 = NL_ * E_ * R_ / 4;
        split_kernel<<<CDIV(n4, 256), 256>>>((const float4*)Wdt, wdth, wdtl, n4);
        const int nt = NL_ * 128 * E_;
        wxpad_kernel<<<CDIV(nt, 256), 256>>>(Wx, wxph, wxpl);
    }

    const int n4 = (T_ * D_) / 4;
    init_h_kernel<<<CDIV(n4, 256), 256>>>((const float4*)x, (float4*)h, hh, hl, n4);

    for (int i = 0; i < NL_; i++) {
        // 1) xz = h @ Win^T   (4096 x 4096, K=1024)
        hmma_gemm<0><<<dim3((2 * E_) / 128, T_ / 128), 256, GT_SMEM>>>(
            T_, 2 * E_, D_,
            hh, hl, D_,
            winh + (size_t)i * 2 * E_ * D_, winl + (size_t)i * 2 * E_ * D_, D_,
            xz, 2 * E_, nullptr, nullptr, 0, 0);

        // 2) u = silu(causal_conv(xz[:, :E]) + convb)   (+ bf16 split)
        conv_silu_kernel<<<dim3(E_ / 256, T_), 256>>>(
            xz, convw + (size_t)i * E_ * KC_, convb + (size_t)i * E_, u, uh, ul);

        // 3) x_dbl = u @ Wx^T  (4096 x 128pad, K=2048), split-K x8 HMMA
        hmma_gemm<0><<<dim3(1, T_ / 128, XSPLIT_), 256, GT_SMEM>>>(
            T_, 128, E_,
            uh, ul, E_,
            wxph + (size_t)i * 128 * E_, wxpl + (size_t)i * 128 * E_, E_,
            xp, 128, nullptr, nullptr,
            E_ / XSPLIT_, (long long)T_ * 128);
        reduce_xdbl_kernel<<<CDIV(T_ * XD_, 256), 256>>>(xp, xdbl, dtrh, dtrl);

        // 4) delta = softplus(dtr @ Wdt^T + bdt)  (4096 x 2048, K=64)
        hmma_gemm<1><<<dim3(E_ / 128, T_ / 128), 256, GT_SMEM>>>(
            T_, E_, R_,
            dtrh, dtrl, R_,
            wdth + (size_t)i * E_ * R_, wdtl + (size_t)i * E_ * R_, R_,
            delta, E_, bdt + (size_t)i * E_, nullptr, 0, 0);

        // 5) selective scan -> y (state-parallel, bf16 hi/lo out)
        scan_kernel<<<dim3(E_ / 32, B_), 128>>>(
            delta, u, xz, xdbl,
            Alog + (size_t)i * E_ * NS_, Dp + (size_t)i * E_, yh, yl);

        // 6) h = y @ Wout^T + h  (4096 x 1024, K=2048)
        hmma_gemm<2><<<dim3(D_ / 128, T_ / 128), 256, GT_SMEM>>>(
            T_, D_, E_,
            yh, yl, E_,
            wouth + (size_t)i * D_ * E_, woutl + (size_t)i * D_ * E_, E_,
            h, D_, nullptr, h, 0, 0);

        // 7) layernorm (+ h bf16 split)
        layernorm_kernel<<<T_, 256>>>(h, ln_g + (size_t)i * D_, ln_b + (size_t)i * D_, hh, hl);
    }

    mean_kernel<<<dim3(D_ / 256, B_), 256>>>(h, (float*)d_out);
}

// round 9
// speedup vs baseline: 3.1462x; 1.1581x over previous
#include <cuda_runtime.h>
#include <cuda_fp16.h>
#include <cstdint>
#include <math.h>

// ---------------------------------------------------------------------------
// Problem constants (MambaModel: B=4, L=1024, D=1024, E=2048, N=16, K=4, R=64)
// ---------------------------------------------------------------------------
constexpr int B_  = 4;
constexpr int L_  = 1024;
constexpr int D_  = 1024;
constexpr int E_  = 2048;
constexpr int NS_ = 16;
constexpr int KC_ = 4;
constexpr int R_  = 64;
constexpr int NL_ = 4;
constexpr int T_  = B_ * L_;       // 4096
constexpr int XD_ = R_ + 2 * NS_;  // 96
constexpr int XSPLIT_ = 8;         // split-K for x_dbl HMMA

#define CDIV(a, b) (((a) + (b) - 1) / (b))

// ---------------------------------------------------------------------------
// Scratch (fp32)
// ---------------------------------------------------------------------------
__device__ float g_h    [(size_t)T_ * D_];
__device__ float g_xz   [(size_t)T_ * 2 * E_];
__device__ float g_u    [(size_t)T_ * E_];
__device__ float g_xdbl [(size_t)T_ * XD_];
__device__ float g_xp   [(size_t)XSPLIT_ * T_ * 128];
__device__ float g_delta[(size_t)T_ * E_];

// fp16 operand buffers: weights rounded (hi only), activations hi/lo
__device__ __half g_win [(size_t)NL_ * 2 * E_ * D_];
__device__ __half g_wout[(size_t)NL_ * D_ * E_];
__device__ __half g_wdt [(size_t)NL_ * E_ * R_];
__device__ __half g_wxp [(size_t)NL_ * 128 * E_];
__device__ __half g_hh[(size_t)T_ * D_];
__device__ __half g_hl[(size_t)T_ * D_];
__device__ __half g_uh[(size_t)T_ * E_];
__device__ __half g_ul[(size_t)T_ * E_];
__device__ __half g_yh[(size_t)T_ * E_];
__device__ __half g_yl[(size_t)T_ * E_];
__device__ __half g_dtrh[(size_t)T_ * R_];
__device__ __half g_dtrl[(size_t)T_ * R_];

// ---------------------------------------------------------------------------
// Helpers
// ---------------------------------------------------------------------------
__device__ __forceinline__ uint32_t smem_to_u32(const void* p) {
    uint32_t a;
    asm("{ .reg .u64 t; cvta.to.shared.u64 t, %1; cvt.u32.u64 %0, t; }"
        : "=r"(a) : "l"(p));
    return a;
}

__device__ __forceinline__ void cp_async16(uint32_t dst, const void* src) {
    asm volatile("cp.async.cg.shared.global [%0], [%1], 16;" :: "r"(dst), "l"(src));
}
#define CP_COMMIT() asm volatile("cp.async.commit_group;" ::: "memory")
#define CP_WAIT1()  asm volatile("cp.async.wait_group 1;" ::: "memory")

__device__ __forceinline__ void ldmatrix_x4(uint32_t& r0, uint32_t& r1,
                                            uint32_t& r2, uint32_t& r3,
                                            uint32_t addr) {
    asm volatile("ldmatrix.sync.aligned.m8n8.x4.shared.b16 {%0,%1,%2,%3}, [%4];"
                 : "=r"(r0), "=r"(r1), "=r"(r2), "=r"(r3) : "r"(addr));
}

__device__ __forceinline__ void mma_fp16(float& c0, float& c1, float& c2, float& c3,
                                         uint32_t a0, uint32_t a1, uint32_t a2, uint32_t a3,
                                         uint32_t b0, uint32_t b1) {
    asm volatile(
        "mma.sync.aligned.m16n8k16.row.col.f32.f16.f16.f32 "
        "{%0,%1,%2,%3}, {%4,%5,%6,%7}, {%8,%9}, {%0,%1,%2,%3};"
        : "+f"(c0), "+f"(c1), "+f"(c2), "+f"(c3)
        : "r"(a0), "r"(a1), "r"(a2), "r"(a3), "r"(b0), "r"(b1));
}

// SW128 swizzle for 128B-row tiles (128 rows x 64 fp16)
__device__ __forceinline__ uint32_t sw128(uint32_t off) {
    return off ^ ((off >> 3) & 0x70);
}

__device__ __forceinline__ void split_fp16(float v, __half& h, __half& l) {
    h = __float2half_rn(v);
    l = __float2half_rn(v - __half2float(h));
}

// ===========================================================================
// HMMA GEMM (fp16x2): C[M,N] = A[M,K]*B[N,K]^T + epi.
// A as fp16 hi/lo pair; B rounded fp16. Block 128x128, K-chunk 64, 2-stage
// cp.async (96 KB smem -> 2 CTAs/SM). 256 threads = 8 warps (4m x 2n),
// warp tile 32x64. Per k16 step: 8 ldmatrix.x4, then 32 mma (2 passes).
// EPI: 0 plain, 1 softplus(acc+bias[n]), 2 acc+res.
// ===========================================================================
constexpr int HT_TILE  = 16384;              // 128 rows x 128 bytes
constexpr int HT_AL = HT_TILE, HT_B = 2 * HT_TILE;
constexpr int HT_STAGE = 3 * HT_TILE;        // 48 KB
constexpr int HT_SMEM  = 2 * HT_STAGE;       // 96 KB

__device__ __forceinline__ void load_tile_async64(
    const __half* src, int ld, uint32_t dst_sb, int tid)
{
#pragma unroll
    for (int i = 0; i < 4; i++) {
        const int idx = tid + (i << 8);         // 0..1023
        const int row = idx >> 3;               // 0..127
        const int c   = idx & 7;                // 16B chunk in 128B row
        const uint32_t off = (uint32_t)(row << 7) + (uint32_t)(c << 4);
        cp_async16(dst_sb + sw128(off), src + (size_t)row * ld + (c << 3));
    }
}

template <int EPI>
__global__ __launch_bounds__(256, 2) void hmma_gemm(
    int M, int N, int K,
    const __half* __restrict__ Ah, const __half* __restrict__ Al, int lda,
    const __half* __restrict__ Bw, int ldb,
    float* __restrict__ C, int ldc,
    const float* __restrict__ bias,
    const float* __restrict__ res,
    int kchunk, long long cslab)
{
    extern __shared__ __align__(1024) char smem[];
    const uint32_t sb = smem_to_u32(smem);
    const int tid    = threadIdx.x;
    const int wid    = tid >> 5;
    const int lane   = tid & 31;
    const int mb     = (wid >> 1) * 32;
    const int nb     = (wid & 1) * 64;
    const int m0 = blockIdx.y * 128;
    const int n0 = blockIdx.x * 128;

    int Kloc = K, koff = 0;
    if (kchunk) {
        Kloc = kchunk;
        koff = blockIdx.z * kchunk;
        C += (size_t)blockIdx.z * cslab;
    }

    const __half* A0h = Ah + (size_t)m0 * lda + koff;
    const __half* A0l = Al + (size_t)m0 * lda + koff;
    const __half* B0  = Bw + (size_t)n0 * ldb + koff;

    const int a_row_off = (lane & 15);
    const int a_koff    = (lane >> 4) << 4;
    const int b_row_off = (lane & 7) + ((lane >> 4) << 3);
    const int b_koff    = ((lane >> 3) & 1) << 4;

    float acc[2][8][4];
#pragma unroll
    for (int i = 0; i < 2; i++)
#pragma unroll
        for (int j = 0; j < 8; j++)
#pragma unroll
            for (int q = 0; q < 4; q++) acc[i][j][q] = 0.f;

    const int nch = Kloc >> 6;

#define LOAD_CHUNK(kc, stage)                                                  \
    do {                                                                       \
        const int kk = (kc) << 6;                                              \
        const uint32_t s0 = sb + (stage) * HT_STAGE;                           \
        load_tile_async64(A0h + kk, lda, s0,          tid);                    \
        load_tile_async64(A0l + kk, lda, s0 + HT_AL,  tid);                    \
        load_tile_async64(B0  + kk, ldb, s0 + HT_B,   tid);                    \
    } while (0)

    LOAD_CHUNK(0, 0);
    CP_COMMIT();

    int buf = 0;
#pragma unroll 1
    for (int kc = 0; kc < nch; kc++) {
        if (kc + 1 < nch) LOAD_CHUNK(kc + 1, buf ^ 1);
        CP_COMMIT();
        CP_WAIT1();
        __syncthreads();

        const uint32_t stage = sb + buf * HT_STAGE;
#pragma unroll
        for (int s = 0; s < 4; s++) {
            const int ks = s << 5;   // k16 step = 32 bytes

            // ---- 8 unique ldmatrix per k-step ----
            uint32_t ah[2][4], al[2][4];
#pragma unroll
            for (int tm = 0; tm < 2; tm++) {
                const int row = mb + tm * 16 + a_row_off;
                const uint32_t off = sw128((uint32_t)(row << 7) + ks + a_koff);
                ldmatrix_x4(ah[tm][0], ah[tm][1], ah[tm][2], ah[tm][3], stage + off);
                ldmatrix_x4(al[tm][0], al[tm][1], al[tm][2], al[tm][3], stage + HT_AL + off);
            }
            uint32_t bf[4][4];
#pragma unroll
            for (int g = 0; g < 4; g++) {
                const int row = nb + g * 16 + b_row_off;
                const uint32_t off = sw128((uint32_t)(row << 7) + ks + b_koff);
                ldmatrix_x4(bf[g][0], bf[g][1], bf[g][2], bf[g][3], stage + HT_B + off);
            }

            // ---- 2 passes x 16 mma ----
#define DO_PASS(AF)                                                            \
            _Pragma("unroll")                                                  \
            for (int tm = 0; tm < 2; tm++)                                     \
                _Pragma("unroll")                                              \
                for (int g = 0; g < 4; g++) {                                  \
                    mma_fp16(acc[tm][2*g][0], acc[tm][2*g][1],                 \
                             acc[tm][2*g][2], acc[tm][2*g][3],                 \
                             AF[tm][0], AF[tm][1], AF[tm][2], AF[tm][3],       \
                             bf[g][0], bf[g][1]);                              \
                    mma_fp16(acc[tm][2*g+1][0], acc[tm][2*g+1][1],             \
                             acc[tm][2*g+1][2], acc[tm][2*g+1][3],             \
                             AF[tm][0], AF[tm][1], AF[tm][2], AF[tm][3],       \
                             bf[g][2], bf[g][3]);                              \
                }
            DO_PASS(ah)
            DO_PASS(al)
#undef DO_PASS
        }
        __syncthreads();
        buf ^= 1;
    }
#undef LOAD_CHUNK

    const int erow = m0 + mb + (lane >> 2);
    const int ecol0 = n0 + nb + (lane & 3) * 2;
#pragma unroll
    for (int tm = 0; tm < 2; tm++) {
#pragma unroll
        for (int j = 0; j < 8; j++) {
            const int col = ecol0 + j * 8;
#pragma unroll
            for (int half = 0; half < 2; half++) {
                const int row = erow + tm * 16 + half * 8;
                float v0 = acc[tm][j][2 * half + 0];
                float v1 = acc[tm][j][2 * half + 1];
                if (EPI == 1) {
                    v0 += bias[col];
                    v1 += bias[col + 1];
                    v0 = (v0 > 20.f) ? v0 : log1pf(__expf(v0));
                    v1 = (v1 > 20.f) ? v1 : log1pf(__expf(v1));
                } else if (EPI == 2) {
                    v0 += res[(size_t)row * ldc + col];
                    v1 += res[(size_t)row * ldc + col + 1];
                }
                C[(size_t)row * ldc + col]     = v0;
                C[(size_t)row * ldc + col + 1] = v1;
            }
        }
    }
}

// ---------------------------------------------------------------------------
// Weight round / activation split kernels
// ---------------------------------------------------------------------------
__global__ void round_kernel(const float4* __restrict__ src,
                             __half* __restrict__ dst, int n4)
{
    const int i = blockIdx.x * blockDim.x + threadIdx.x;
    if (i >= n4) return;
    float4 v = src[i];
    __half2 p0 = __halves2half2(__float2half_rn(v.x), __float2half_rn(v.y));
    __half2 p1 = __halves2half2(__float2half_rn(v.z), __float2half_rn(v.w));
    uint2 o = {*reinterpret_cast<uint32_t*>(&p0), *reinterpret_cast<uint32_t*>(&p1)};
    *reinterpret_cast<uint2*>(dst + 4 * (size_t)i) = o;
}

// Wx (NL, 96, E) -> padded (NL, 128, E) fp16, rows 96..127 zero.
__global__ void wxpad_kernel(const float* __restrict__ wx,
                             __half* __restrict__ dst)
{
    const int i = blockIdx.x * blockDim.x + threadIdx.x;
    const int nt = NL_ * 128 * E_;
    if (i >= nt) return;
    const int lyr = i / (128 * E_);
    const int rem = i - lyr * 128 * E_;
    const int r = rem / E_;
    const int c = rem - r * E_;
    float v = (r < XD_) ? wx[((size_t)lyr * XD_ + r) * E_ + c] : 0.f;
    dst[i] = __float2half_rn(v);
}

__device__ __forceinline__ void pack_split4(float4 v, __half* dh, __half* dl) {
    __half h0, h1, h2, h3, l0, l1, l2, l3;
    split_fp16(v.x, h0, l0); split_fp16(v.y, h1, l1);
    split_fp16(v.z, h2, l2); split_fp16(v.w, h3, l3);
    __half2 hp0 = __halves2half2(h0, h1), hp1 = __halves2half2(h2, h3);
    __half2 lp0 = __halves2half2(l0, l1), lp1 = __halves2half2(l2, l3);
    uint2 hv = {*reinterpret_cast<uint32_t*>(&hp0), *reinterpret_cast<uint32_t*>(&hp1)};
    uint2 lv = {*reinterpret_cast<uint32_t*>(&lp0), *reinterpret_cast<uint32_t*>(&lp1)};
    *reinterpret_cast<uint2*>(dh) = hv;
    *reinterpret_cast<uint2*>(dl) = lv;
}

__global__ void init_h_kernel(const float4* __restrict__ x, float4* __restrict__ h,
                              __half* __restrict__ hh, __half* __restrict__ hl, int n4)
{
    const int i = blockIdx.x * blockDim.x + threadIdx.x;
    if (i >= n4) return;
    float4 v = x[i];
    h[i] = v;
    pack_split4(v, hh + 4 * (size_t)i, hl + 4 * (size_t)i);
}

// ---------------------------------------------------------------------------
// Depthwise causal conv1d + SiLU; writes u fp32 and fp16 hi/lo.
// ---------------------------------------------------------------------------
__global__ void conv_silu_kernel(
    const float* __restrict__ xz, const float* __restrict__ cw,
    const float* __restrict__ cb, float* __restrict__ u,
    __half* __restrict__ uh, __half* __restrict__ ul)
{
    const int e = blockIdx.x * blockDim.x + threadIdx.x;
    const int t = blockIdx.y;
    const int l = t & (L_ - 1);
    const float4 w = reinterpret_cast<const float4*>(cw)[e];
    float acc = cb[e];
    const float* col = xz + e;
    if (l >= 3) acc = fmaf(col[(size_t)(t - 3) * (2 * E_)], w.x, acc);
    if (l >= 2) acc = fmaf(col[(size_t)(t - 2) * (2 * E_)], w.y, acc);
    if (l >= 1) acc = fmaf(col[(size_t)(t - 1) * (2 * E_)], w.z, acc);
    acc = fmaf(col[(size_t)t * (2 * E_)], w.w, acc);
    const float v = acc / (1.f + __expf(-acc));
    const size_t o = (size_t)t * E_ + e;
    u[o] = v;
    __half hh, ll;
    split_fp16(v, hh, ll);
    uh[o] = hh; ul[o] = ll;
}

// ---------------------------------------------------------------------------
// Split-K reduce for x_dbl (128-wide partials -> 96-wide) + dtr fp16 hi/lo
// ---------------------------------------------------------------------------
__global__ void reduce_xdbl_kernel(const float* __restrict__ xp,
                                   float* __restrict__ xdbl,
                                   __half* __restrict__ dtrh,
                                   __half* __restrict__ dtrl)
{
    const int i = blockIdx.x * blockDim.x + threadIdx.x;
    if (i >= T_ * XD_) return;
    const int t = i / XD_;
    const int c = i - t * XD_;
    float s = 0.f;
#pragma unroll
    for (int k = 0; k < XSPLIT_; k++) s += xp[(size_t)k * T_ * 128 + (size_t)t * 128 + c];
    xdbl[i] = s;
    if (c < R_) {
        __half hh, ll;
        split_fp16(s, hh, ll);
        dtrh[(size_t)t * R_ + c] = hh;
        dtrl[(size_t)t * R_ + c] = ll;
    }
}

// ---------------------------------------------------------------------------
// Selective scan, state-parallel: 4 lanes per channel, 4 states each.
// ---------------------------------------------------------------------------
__global__ __launch_bounds__(128) void scan_kernel(
    const float* __restrict__ delta, const float* __restrict__ u,
    const float* __restrict__ xz, const float* __restrict__ xdbl,
    const float* __restrict__ Alog, const float* __restrict__ Dp,
    __half* __restrict__ yh, __half* __restrict__ yl)
{
    const int tid = threadIdx.x;
    const int sg  = tid & 3;
    const int e   = blockIdx.x * 32 + (tid >> 2);
    const int b   = blockIdx.y;
    const int tbase = b * L_;

    float An[4];
#pragma unroll
    for (int j = 0; j < 4; j++)
        An[j] = -__expf(Alog[(size_t)e * NS_ + sg * 4 + j]);
    const float dp = Dp[e];

    float h0 = 0.f, h1 = 0.f, h2 = 0.f, h3 = 0.f;

#define SLOAD(S, t)                                                             \
    do {                                                                        \
        d##S = delta[(size_t)(t) * E_ + e];                                     \
        u##S = u[(size_t)(t) * E_ + e];                                         \
        z##S = xz[(size_t)(t) * (2 * E_) + E_ + e];                             \
        Bv##S = *reinterpret_cast<const float4*>(xdbl + (size_t)(t) * XD_ + R_ + sg * 4);        \
        Cv##S = *reinterpret_cast<const float4*>(xdbl + (size_t)(t) * XD_ + R_ + NS_ + sg * 4);  \
    } while (0)

#define SSTEP(S, t)                                                             \
    do {                                                                        \
        const float du = d##S * u##S;                                           \
        h0 = fmaf(__expf(d##S * An[0]), h0, du * Bv##S.x);                      \
        h1 = fmaf(__expf(d##S * An[1]), h1, du * Bv##S.y);                      \
        h2 = fmaf(__expf(d##S * An[2]), h2, du * Bv##S.z);                      \
        h3 = fmaf(__expf(d##S * An[3]), h3, du * Bv##S.w);                      \
        float yv = h0 * Cv##S.x + h1 * Cv##S.y + h2 * Cv##S.z + h3 * Cv##S.w;   \
        yv += __shfl_xor_sync(0xFFFFFFFFu, yv, 1);                              \
        yv += __shfl_xor_sync(0xFFFFFFFFu, yv, 2);                              \
        if (sg == 0) {                                                          \
            const float sz = z##S / (1.f + __expf(-z##S));                      \
            const float v = (yv + dp * u##S) * sz;                              \
            __half vh, vl;                                                      \
            split_fp16(v, vh, vl);                                              \
            yh[(size_t)(t) * E_ + e] = vh;                                      \
            yl[(size_t)(t) * E_ + e] = vl;                                      \
        }                                                                       \
    } while (0)

    float d0, u0, z0, d1, u1, z1;
    float4 Bv0, Cv0, Bv1, Cv1;

    SLOAD(0, tbase);
#pragma unroll 1
    for (int l = 0; l < L_; l += 2) {
        SLOAD(1, tbase + l + 1);
        SSTEP(0, tbase + l);
        if (l + 2 < L_) SLOAD(0, tbase + l + 2);
        SSTEP(1, tbase + l + 1);
    }
#undef SLOAD
#undef SSTEP
}

// ---------------------------------------------------------------------------
// LayerNorm over D, in place; also writes h fp16 hi/lo.
// ---------------------------------------------------------------------------
__global__ void layernorm_kernel(float* __restrict__ h,
                                 const float* __restrict__ g,
                                 const float* __restrict__ bb,
                                 __half* __restrict__ hh,
                                 __half* __restrict__ hl)
{
    const int t = blockIdx.x;
    float* row = h + (size_t)t * D_;
    float s = 0.f, s2 = 0.f;
    for (int i = threadIdx.x; i < D_; i += blockDim.x) {
        const float v = row[i];
        s += v;
        s2 = fmaf(v, v, s2);
    }
    __shared__ float red[64];
#pragma unroll
    for (int o = 16; o > 0; o >>= 1) {
        s  += __shfl_xor_sync(0xFFFFFFFFu, s, o);
        s2 += __shfl_xor_sync(0xFFFFFFFFu, s2, o);
    }
    const int wid = threadIdx.x >> 5, lid = threadIdx.x & 31;
    if (lid == 0) { red[wid] = s; red[32 + wid] = s2; }
    __syncthreads();
    if (threadIdx.x < 32) {
        const int nw = blockDim.x >> 5;
        float a = (threadIdx.x < nw) ? red[threadIdx.x] : 0.f;
        float c = (threadIdx.x < nw) ? red[32 + threadIdx.x] : 0.f;
#pragma unroll
        for (int o = 16; o > 0; o >>= 1) {
            a += __shfl_xor_sync(0xFFFFFFFFu, a, o);
            c += __shfl_xor_sync(0xFFFFFFFFu, c, o);
        }
        if (threadIdx.x == 0) { red[0] = a; red[1] = c; }
    }
    __syncthreads();
    const float mean = red[0] * (1.f / D_);
    const float var  = red[1] * (1.f / D_) - mean * mean;
    const float inv  = rsqrtf(var + 1e-5f);
    for (int i = threadIdx.x; i < D_; i += blockDim.x) {
        const float v = (row[i] - mean) * inv * g[i] + bb[i];
        row[i] = v;
        __half hv, lv;
        split_fp16(v, hv, lv);
        hh[(size_t)t * D_ + i] = hv;
        hl[(size_t)t * D_ + i] = lv;
    }
}

__global__ void mean_kernel(const float* __restrict__ h, float* __restrict__ out) {
    const int d = blockIdx.x * blockDim.x + threadIdx.x;
    const int b = blockIdx.y;
    const float* p = h + (size_t)b * L_ * D_ + d;
    float s = 0.f;
    for (int l = 0; l < L_; l++) s += p[(size_t)l * D_];
    out[b * D_ + d] = s * (1.f / L_);
}

// ---------------------------------------------------------------------------
// Launch
// ---------------------------------------------------------------------------
extern "C" void kernel_launch(void* const* d_in, const int* in_sizes, int n_in,
                              void* d_out, int out_size)
{
    const float* x     = (const float*)d_in[0];
    const float* Win   = (const float*)d_in[1];
    const float* convw = (const float*)d_in[2];
    const float* convb = (const float*)d_in[3];
    const float* Wx    = (const float*)d_in[4];
    const float* Wdt   = (const float*)d_in[5];
    const float* bdt   = (const float*)d_in[6];
    const float* Alog  = (const float*)d_in[7];
    const float* Dp    = (const float*)d_in[8];
    const float* Wout  = (const float*)d_in[9];
    const float* ln_g  = (const float*)d_in[10];
    const float* ln_b  = (const float*)d_in[11];

    float *h, *xz, *u, *xdbl, *xp, *delta;
    cudaGetSymbolAddress((void**)&h,     g_h);
    cudaGetSymbolAddress((void**)&xz,    g_xz);
    cudaGetSymbolAddress((void**)&u,     g_u);
    cudaGetSymbolAddress((void**)&xdbl,  g_xdbl);
    cudaGetSymbolAddress((void**)&xp,    g_xp);
    cudaGetSymbolAddress((void**)&delta, g_delta);

    __half *win, *wout, *wdt, *wxp;
    __half *hh, *hl, *uh, *ul, *yh, *yl, *dtrh, *dtrl;
    cudaGetSymbolAddress((void**)&win,  g_win);
    cudaGetSymbolAddress((void**)&wout, g_wout);
    cudaGetSymbolAddress((void**)&wdt,  g_wdt);
    cudaGetSymbolAddress((void**)&wxp,  g_wxp);
    cudaGetSymbolAddress((void**)&hh,   g_hh);
    cudaGetSymbolAddress((void**)&hl,   g_hl);
    cudaGetSymbolAddress((void**)&uh,   g_uh);
    cudaGetSymbolAddress((void**)&ul,   g_ul);
    cudaGetSymbolAddress((void**)&yh,   g_yh);
    cudaGetSymbolAddress((void**)&yl,   g_yl);
    cudaGetSymbolAddress((void**)&dtrh, g_dtrh);
    cudaGetSymbolAddress((void**)&dtrl, g_dtrl);

    cudaFuncSetAttribute(hmma_gemm<0>, cudaFuncAttributeMaxDynamicSharedMemorySize, HT_SMEM);
    cudaFuncSetAttribute(hmma_gemm<1>, cudaFuncAttributeMaxDynamicSharedMemorySize, HT_SMEM);
    cudaFuncSetAttribute(hmma_gemm<2>, cudaFuncAttributeMaxDynamicSharedMemorySize, HT_SMEM);

    // ---- weight rounding to fp16 ----
    {
        int n4 = NL_ * 2 * E_ * D_ / 4;
        round_kernel<<<CDIV(n4, 256), 256>>>((const float4*)Win, win, n4);
        n4 = NL_ * D_ * E_ / 4;
        round_kernel<<<CDIV(n4, 256), 256>>>((const float4*)Wout, wout, n4);
        n4 = NL_ * E_ * R_ / 4;
        round_kernel<<<CDIV(n4, 256), 256>>>((const float4*)Wdt, wdt, n4);
        const int nt = NL_ * 128 * E_;
        wxpad_kernel<<<CDIV(nt, 256), 256>>>(Wx, wxp);
    }

    const int n4 = (T_ * D_) / 4;
    init_h_kernel<<<CDIV(n4, 256), 256>>>((const float4*)x, (float4*)h, hh, hl, n4);

    for (int i = 0; i < NL_; i++) {
        // 1) xz = h @ Win^T   (4096 x 4096, K=1024)
        hmma_gemm<0><<<dim3((2 * E_) / 128, T_ / 128), 256, HT_SMEM>>>(
            T_, 2 * E_, D_,
            hh, hl, D_,
            win + (size_t)i * 2 * E_ * D_, D_,
            xz, 2 * E_, nullptr, nullptr, 0, 0);

        // 2) u = silu(causal_conv(xz[:, :E]) + convb)   (+ fp16 split)
        conv_silu_kernel<<<dim3(E_ / 256, T_), 256>>>(
            xz, convw + (size_t)i * E_ * KC_, convb + (size_t)i * E_, u, uh, ul);

        // 3) x_dbl = u @ Wx^T  (4096 x 128pad, K=2048), split-K x8
        hmma_gemm<0><<<dim3(1, T_ / 128, XSPLIT_), 256, HT_SMEM>>>(
            T_, 128, E_,
            uh, ul, E_,
            wxp + (size_t)i * 128 * E_, E_,
            xp, 128, nullptr, nullptr,
            E_ / XSPLIT_, (long long)T_ * 128);
        reduce_xdbl_kernel<<<CDIV(T_ * XD_, 256), 256>>>(xp, xdbl, dtrh, dtrl);

        // 4) delta = softplus(dtr @ Wdt^T + bdt)  (4096 x 2048, K=64)
        hmma_gemm<1><<<dim3(E_ / 128, T_ / 128), 256, HT_SMEM>>>(
            T_, E_, R_,
            dtrh, dtrl, R_,
            wdt + (size_t)i * E_ * R_, R_,
            delta, E_, bdt + (size_t)i * E_, nullptr, 0, 0);

        // 5) selective scan -> y (state-parallel, fp16 hi/lo out)
        scan_kernel<<<dim3(E_ / 32, B_), 128>>>(
            delta, u, xz, xdbl,
            Alog + (size_t)i * E_ * NS_, Dp + (size_t)i * E_, yh, yl);

        // 6) h = y @ Wout^T + h  (4096 x 1024, K=2048)
        hmma_gemm<2><<<dim3(D_ / 128, T_ / 128), 256, HT_SMEM>>>(
            T_, D_, E_,
            yh, yl, E_,
            wout + (size_t)i * D_ * E_, E_,
            h, D_, nullptr, h, 0, 0);

        // 7) layernorm (+ h fp16 split)
        layernorm_kernel<<<T_, 256>>>(h, ln_g + (size_t)i * D_, ln_b + (size_t)i * D_, hh, hl);
    }

    mean_kernel<<<dim3(D_ / 256, B_), 256>>>(h, (float*)d_out);
}

// round 10
// speedup vs baseline: 3.6905x; 1.1730x over previous
#include <cuda_runtime.h>
#include <cuda_fp16.h>
#include <cstdint>
#include <math.h>

// ---------------------------------------------------------------------------
// Problem constants (MambaModel: B=4, L=1024, D=1024, E=2048, N=16, K=4, R=64)
// ---------------------------------------------------------------------------
constexpr int B_  = 4;
constexpr int L_  = 1024;
constexpr int D_  = 1024;
constexpr int E_  = 2048;
constexpr int NS_ = 16;
constexpr int KC_ = 4;
constexpr int R_  = 64;
constexpr int NL_ = 4;
constexpr int T_  = B_ * L_;       // 4096
constexpr int XD_ = R_ + 2 * NS_;  // 96
constexpr int XSPLIT_ = 8;         // split-K for x_dbl HMMA

#define CDIV(a, b) (((a) + (b) - 1) / (b))

// ---------------------------------------------------------------------------
// Scratch (fp32)
// ---------------------------------------------------------------------------
__device__ float g_h    [(size_t)T_ * D_];
__device__ float g_xz   [(size_t)T_ * 2 * E_];
__device__ float g_u    [(size_t)T_ * E_];
__device__ float g_xdbl [(size_t)T_ * XD_];
__device__ float g_xp   [(size_t)XSPLIT_ * T_ * 128];
__device__ float g_delta[(size_t)T_ * E_];

// fp16 operand buffers (all rounded; no lo terms)
__device__ __half g_win [(size_t)NL_ * 2 * E_ * D_];
__device__ __half g_wout[(size_t)NL_ * D_ * E_];
__device__ __half g_wdt [(size_t)NL_ * E_ * R_];
__device__ __half g_wxp [(size_t)NL_ * 128 * E_];
__device__ __half g_hh  [(size_t)T_ * D_];
__device__ __half g_uh  [(size_t)T_ * E_];
__device__ __half g_yh  [(size_t)T_ * E_];
__device__ __half g_dtrh[(size_t)T_ * R_];

// ---------------------------------------------------------------------------
// Helpers
// ---------------------------------------------------------------------------
__device__ __forceinline__ uint32_t smem_to_u32(const void* p) {
    uint32_t a;
    asm("{ .reg .u64 t; cvta.to.shared.u64 t, %1; cvt.u32.u64 %0, t; }"
        : "=r"(a) : "l"(p));
    return a;
}

__device__ __forceinline__ void cp_async16(uint32_t dst, const void* src) {
    asm volatile("cp.async.cg.shared.global [%0], [%1], 16;" :: "r"(dst), "l"(src));
}
#define CP_COMMIT() asm volatile("cp.async.commit_group;" ::: "memory")
#define CP_WAIT1()  asm volatile("cp.async.wait_group 1;" ::: "memory")

__device__ __forceinline__ void ldmatrix_x4(uint32_t& r0, uint32_t& r1,
                                            uint32_t& r2, uint32_t& r3,
                                            uint32_t addr) {
    asm volatile("ldmatrix.sync.aligned.m8n8.x4.shared.b16 {%0,%1,%2,%3}, [%4];"
                 : "=r"(r0), "=r"(r1), "=r"(r2), "=r"(r3) : "r"(addr));
}

__device__ __forceinline__ void mma_fp16(float& c0, float& c1, float& c2, float& c3,
                                         uint32_t a0, uint32_t a1, uint32_t a2, uint32_t a3,
                                         uint32_t b0, uint32_t b1) {
    asm volatile(
        "mma.sync.aligned.m16n8k16.row.col.f32.f16.f16.f32 "
        "{%0,%1,%2,%3}, {%4,%5,%6,%7}, {%8,%9}, {%0,%1,%2,%3};"
        : "+f"(c0), "+f"(c1), "+f"(c2), "+f"(c3)
        : "r"(a0), "r"(a1), "r"(a2), "r"(a3), "r"(b0), "r"(b1));
}

// SW128 swizzle for 128B-row tiles (128 rows x 64 fp16)
__device__ __forceinline__ uint32_t sw128(uint32_t off) {
    return off ^ ((off >> 3) & 0x70);
}

// ===========================================================================
// HMMA GEMM (pure fp16, fp32 accumulate): C[M,N] = A[M,K]*B[N,K]^T + epi.
// Block 128x128, K-chunk 64, 2-stage cp.async (64 KB smem -> 2 CTAs/SM).
// 256 threads = 8 warps (4m x 2n), warp tile 32x64.
// Per k16 step: 6 ldmatrix.x4 (A x2, B x4), 16 mma.
// EPI: 0 plain, 1 softplus(acc+bias[n]), 2 acc+res.
// ===========================================================================
constexpr int HT_TILE  = 16384;              // 128 rows x 128 bytes
constexpr int HT_B = HT_TILE;
constexpr int HT_STAGE = 2 * HT_TILE;        // 32 KB
constexpr int HT_SMEM  = 2 * HT_STAGE;       // 64 KB

__device__ __forceinline__ void load_tile_async64(
    const __half* src, int ld, uint32_t dst_sb, int tid)
{
#pragma unroll
    for (int i = 0; i < 4; i++) {
        const int idx = tid + (i << 8);         // 0..1023
        const int row = idx >> 3;               // 0..127
        const int c   = idx & 7;                // 16B chunk in 128B row
        const uint32_t off = (uint32_t)(row << 7) + (uint32_t)(c << 4);
        cp_async16(dst_sb + sw128(off), src + (size_t)row * ld + (c << 3));
    }
}

template <int EPI>
__global__ __launch_bounds__(256, 2) void hmma_gemm(
    int M, int N, int K,
    const __half* __restrict__ Aw, int lda,
    const __half* __restrict__ Bw, int ldb,
    float* __restrict__ C, int ldc,
    const float* __restrict__ bias,
    const float* __restrict__ res,
    int kchunk, long long cslab)
{
    extern __shared__ __align__(1024) char smem[];
    const uint32_t sb = smem_to_u32(smem);
    const int tid    = threadIdx.x;
    const int wid    = tid >> 5;
    const int lane   = tid & 31;
    const int mb     = (wid >> 1) * 32;
    const int nb     = (wid & 1) * 64;
    const int m0 = blockIdx.y * 128;
    const int n0 = blockIdx.x * 128;

    int Kloc = K, koff = 0;
    if (kchunk) {
        Kloc = kchunk;
        koff = blockIdx.z * kchunk;
        C += (size_t)blockIdx.z * cslab;
    }

    const __half* A0 = Aw + (size_t)m0 * lda + koff;
    const __half* B0 = Bw + (size_t)n0 * ldb + koff;

    const int a_row_off = (lane & 15);
    const int a_koff    = (lane >> 4) << 4;
    const int b_row_off = (lane & 7) + ((lane >> 4) << 3);
    const int b_koff    = ((lane >> 3) & 1) << 4;

    float acc[2][8][4];
#pragma unroll
    for (int i = 0; i < 2; i++)
#pragma unroll
        for (int j = 0; j < 8; j++)
#pragma unroll
            for (int q = 0; q < 4; q++) acc[i][j][q] = 0.f;

    const int nch = Kloc >> 6;

#define LOAD_CHUNK(kc, stage)                                                  \
    do {                                                                       \
        const int kk = (kc) << 6;                                              \
        const uint32_t s0 = sb + (stage) * HT_STAGE;                           \
        load_tile_async64(A0 + kk, lda, s0,        tid);                       \
        load_tile_async64(B0 + kk, ldb, s0 + HT_B, tid);                       \
    } while (0)

    LOAD_CHUNK(0, 0);
    CP_COMMIT();

    int buf = 0;
#pragma unroll 1
    for (int kc = 0; kc < nch; kc++) {
        if (kc + 1 < nch) LOAD_CHUNK(kc + 1, buf ^ 1);
        CP_COMMIT();
        CP_WAIT1();
        __syncthreads();

        const uint32_t stage = sb + buf * HT_STAGE;
#pragma unroll
        for (int s = 0; s < 4; s++) {
            const int ks = s << 5;   // k16 step = 32 bytes

            uint32_t af[2][4];
#pragma unroll
            for (int tm = 0; tm < 2; tm++) {
                const int row = mb + tm * 16 + a_row_off;
                const uint32_t off = sw128((uint32_t)(row << 7) + ks + a_koff);
                ldmatrix_x4(af[tm][0], af[tm][1], af[tm][2], af[tm][3], stage + off);
            }
            uint32_t bf[4][4];
#pragma unroll
            for (int g = 0; g < 4; g++) {
                const int row = nb + g * 16 + b_row_off;
                const uint32_t off = sw128((uint32_t)(row << 7) + ks + b_koff);
                ldmatrix_x4(bf[g][0], bf[g][1], bf[g][2], bf[g][3], stage + HT_B + off);
            }

#pragma unroll
            for (int tm = 0; tm < 2; tm++)
#pragma unroll
                for (int g = 0; g < 4; g++) {
                    mma_fp16(acc[tm][2*g][0], acc[tm][2*g][1],
                             acc[tm][2*g][2], acc[tm][2*g][3],
                             af[tm][0], af[tm][1], af[tm][2], af[tm][3],
                             bf[g][0], bf[g][1]);
                    mma_fp16(acc[tm][2*g+1][0], acc[tm][2*g+1][1],
                             acc[tm][2*g+1][2], acc[tm][2*g+1][3],
                             af[tm][0], af[tm][1], af[tm][2], af[tm][3],
                             bf[g][2], bf[g][3]);
                }
        }
        __syncthreads();
        buf ^= 1;
    }
#undef LOAD_CHUNK

    const int erow = m0 + mb + (lane >> 2);
    const int ecol0 = n0 + nb + (lane & 3) * 2;
#pragma unroll
    for (int tm = 0; tm < 2; tm++) {
#pragma unroll
        for (int j = 0; j < 8; j++) {
            const int col = ecol0 + j * 8;
#pragma unroll
            for (int half = 0; half < 2; half++) {
                const int row = erow + tm * 16 + half * 8;
                float v0 = acc[tm][j][2 * half + 0];
                float v1 = acc[tm][j][2 * half + 1];
                if (EPI == 1) {
                    v0 += bias[col];
                    v1 += bias[col + 1];
                    v0 = (v0 > 20.f) ? v0 : log1pf(__expf(v0));
                    v1 = (v1 > 20.f) ? v1 : log1pf(__expf(v1));
                } else if (EPI == 2) {
                    v0 += res[(size_t)row * ldc + col];
                    v1 += res[(size_t)row * ldc + col + 1];
                }
                C[(size_t)row * ldc + col]     = v0;
                C[(size_t)row * ldc + col + 1] = v1;
            }
        }
    }
}

// ---------------------------------------------------------------------------
// Weight / activation rounding kernels
// ---------------------------------------------------------------------------
__global__ void round_kernel(const float4* __restrict__ src,
                             __half* __restrict__ dst, int n4)
{
    const int i = blockIdx.x * blockDim.x + threadIdx.x;
    if (i >= n4) return;
    float4 v = src[i];
    __half2 p0 = __halves2half2(__float2half_rn(v.x), __float2half_rn(v.y));
    __half2 p1 = __halves2half2(__float2half_rn(v.z), __float2half_rn(v.w));
    uint2 o = {*reinterpret_cast<uint32_t*>(&p0), *reinterpret_cast<uint32_t*>(&p1)};
    *reinterpret_cast<uint2*>(dst + 4 * (size_t)i) = o;
}

// Wx (NL, 96, E) -> padded (NL, 128, E) fp16, rows 96..127 zero.
__global__ void wxpad_kernel(const float* __restrict__ wx,
                             __half* __restrict__ dst)
{
    const int i = blockIdx.x * blockDim.x + threadIdx.x;
    const int nt = NL_ * 128 * E_;
    if (i >= nt) return;
    const int lyr = i / (128 * E_);
    const int rem = i - lyr * 128 * E_;
    const int r = rem / E_;
    const int c = rem - r * E_;
    float v = (r < XD_) ? wx[((size_t)lyr * XD_ + r) * E_ + c] : 0.f;
    dst[i] = __float2half_rn(v);
}

__device__ __forceinline__ void pack_round4(float4 v, __half* dst) {
    __half2 p0 = __halves2half2(__float2half_rn(v.x), __float2half_rn(v.y));
    __half2 p1 = __halves2half2(__float2half_rn(v.z), __float2half_rn(v.w));
    uint2 o = {*reinterpret_cast<uint32_t*>(&p0), *reinterpret_cast<uint32_t*>(&p1)};
    *reinterpret_cast<uint2*>(dst) = o;
}

__global__ void init_h_kernel(const float4* __restrict__ x, float4* __restrict__ h,
                              __half* __restrict__ hh, int n4)
{
    const int i = blockIdx.x * blockDim.x + threadIdx.x;
    if (i >= n4) return;
    float4 v = x[i];
    h[i] = v;
    pack_round4(v, hh + 4 * (size_t)i);
}

// ---------------------------------------------------------------------------
// Depthwise causal conv1d + SiLU; writes u fp32 and fp16.
// ---------------------------------------------------------------------------
__global__ void conv_silu_kernel(
    const float* __restrict__ xz, const float* __restrict__ cw,
    const float* __restrict__ cb, float* __restrict__ u,
    __half* __restrict__ uh)
{
    const int e = blockIdx.x * blockDim.x + threadIdx.x;
    const int t = blockIdx.y;
    const int l = t & (L_ - 1);
    const float4 w = reinterpret_cast<const float4*>(cw)[e];
    float acc = cb[e];
    const float* col = xz + e;
    if (l >= 3) acc = fmaf(col[(size_t)(t - 3) * (2 * E_)], w.x, acc);
    if (l >= 2) acc = fmaf(col[(size_t)(t - 2) * (2 * E_)], w.y, acc);
    if (l >= 1) acc = fmaf(col[(size_t)(t - 1) * (2 * E_)], w.z, acc);
    acc = fmaf(col[(size_t)t * (2 * E_)], w.w, acc);
    const float v = acc / (1.f + __expf(-acc));
    const size_t o = (size_t)t * E_ + e;
    u[o] = v;
    uh[o] = __float2half_rn(v);
}

// ---------------------------------------------------------------------------
// Split-K reduce for x_dbl (128-wide partials -> 96-wide) + dtr fp16
// ---------------------------------------------------------------------------
__global__ void reduce_xdbl_kernel(const float* __restrict__ xp,
                                   float* __restrict__ xdbl,
                                   __half* __restrict__ dtrh)
{
    const int i = blockIdx.x * blockDim.x + threadIdx.x;
    if (i >= T_ * XD_) return;
    const int t = i / XD_;
    const int c = i - t * XD_;
    float s = 0.f;
#pragma unroll
    for (int k = 0; k < XSPLIT_; k++) s += xp[(size_t)k * T_ * 128 + (size_t)t * 128 + c];
    xdbl[i] = s;
    if (c < R_) dtrh[(size_t)t * R_ + c] = __float2half_rn(s);
}

// ---------------------------------------------------------------------------
// Selective scan, state-parallel: 4 lanes per channel, 4 states each.
// ---------------------------------------------------------------------------
__global__ __launch_bounds__(128) void scan_kernel(
    const float* __restrict__ delta, const float* __restrict__ u,
    const float* __restrict__ xz, const float* __restrict__ xdbl,
    const float* __restrict__ Alog, const float* __restrict__ Dp,
    __half* __restrict__ yh)
{
    const int tid = threadIdx.x;
    const int sg  = tid & 3;
    const int e   = blockIdx.x * 32 + (tid >> 2);
    const int b   = blockIdx.y;
    const int tbase = b * L_;

    float An[4];
#pragma unroll
    for (int j = 0; j < 4; j++)
        An[j] = -__expf(Alog[(size_t)e * NS_ + sg * 4 + j]);
    const float dp = Dp[e];

    float h0 = 0.f, h1 = 0.f, h2 = 0.f, h3 = 0.f;

#define SLOAD(S, t)                                                             \
    do {                                                                        \
        d##S = delta[(size_t)(t) * E_ + e];                                     \
        u##S = u[(size_t)(t) * E_ + e];                                         \
        z##S = xz[(size_t)(t) * (2 * E_) + E_ + e];                             \
        Bv##S = *reinterpret_cast<const float4*>(xdbl + (size_t)(t) * XD_ + R_ + sg * 4);        \
        Cv##S = *reinterpret_cast<const float4*>(xdbl + (size_t)(t) * XD_ + R_ + NS_ + sg * 4);  \
    } while (0)

#define SSTEP(S, t)                                                             \
    do {                                                                        \
        const float du = d##S * u##S;                                           \
        h0 = fmaf(__expf(d##S * An[0]), h0, du * Bv##S.x);                      \
        h1 = fmaf(__expf(d##S * An[1]), h1, du * Bv##S.y);                      \
        h2 = fmaf(__expf(d##S * An[2]), h2, du * Bv##S.z);                      \
        h3 = fmaf(__expf(d##S * An[3]), h3, du * Bv##S.w);                      \
        float yv = h0 * Cv##S.x + h1 * Cv##S.y + h2 * Cv##S.z + h3 * Cv##S.w;   \
        yv += __shfl_xor_sync(0xFFFFFFFFu, yv, 1);                              \
        yv += __shfl_xor_sync(0xFFFFFFFFu, yv, 2);                              \
        if (sg == 0) {                                                          \
            const float sz = z##S / (1.f + __expf(-z##S));                      \
            const float v = (yv + dp * u##S) * sz;                              \
            yh[(size_t)(t) * E_ + e] = __float2half_rn(v);                      \
        }                                                                       \
    } while (0)

    float d0, u0, z0, d1, u1, z1;
    float4 Bv0, Cv0, Bv1, Cv1;

    SLOAD(0, tbase);
#pragma unroll 1
    for (int l = 0; l < L_; l += 2) {
        SLOAD(1, tbase + l + 1);
        SSTEP(0, tbase + l);
        if (l + 2 < L_) SLOAD(0, tbase + l + 2);
        SSTEP(1, tbase + l + 1);
    }
#undef SLOAD
#undef SSTEP
}

// ---------------------------------------------------------------------------
// LayerNorm over D, in place; also writes h fp16.
// ---------------------------------------------------------------------------
__global__ void layernorm_kernel(float* __restrict__ h,
                                 const float* __restrict__ g,
                                 const float* __restrict__ bb,
                                 __half* __restrict__ hh)
{
    const int t = blockIdx.x;
    float* row = h + (size_t)t * D_;
    float s = 0.f, s2 = 0.f;
    for (int i = threadIdx.x; i < D_; i += blockDim.x) {
        const float v = row[i];
        s += v;
        s2 = fmaf(v, v, s2);
    }
    __shared__ float red[64];
#pragma unroll
    for (int o = 16; o > 0; o >>= 1) {
        s  += __shfl_xor_sync(0xFFFFFFFFu, s, o);
        s2 += __shfl_xor_sync(0xFFFFFFFFu, s2, o);
    }
    const int wid = threadIdx.x >> 5, lid = threadIdx.x & 31;
    if (lid == 0) { red[wid] = s; red[32 + wid] = s2; }
    __syncthreads();
    if (threadIdx.x < 32) {
        const int nw = blockDim.x >> 5;
        float a = (threadIdx.x < nw) ? red[threadIdx.x] : 0.f;
        float c = (threadIdx.x < nw) ? red[32 + threadIdx.x] : 0.f;
#pragma unroll
        for (int o = 16; o > 0; o >>= 1) {
            a += __shfl_xor_sync(0xFFFFFFFFu, a, o);
            c += __shfl_xor_sync(0xFFFFFFFFu, c, o);
        }
        if (threadIdx.x == 0) { red[0] = a; red[1] = c; }
    }
    __syncthreads();
    const float mean = red[0] * (1.f / D_);
    const float var  = red[1] * (1.f / D_) - mean * mean;
    const float inv  = rsqrtf(var + 1e-5f);
    for (int i = threadIdx.x; i < D_; i += blockDim.x) {
        const float v = (row[i] - mean) * inv * g[i] + bb[i];
        row[i] = v;
        hh[(size_t)t * D_ + i] = __float2half_rn(v);
    }
}

__global__ void mean_kernel(const float* __restrict__ h, float* __restrict__ out) {
    const int d = blockIdx.x * blockDim.x + threadIdx.x;
    const int b = blockIdx.y;
    const float* p = h + (size_t)b * L_ * D_ + d;
    float s = 0.f;
    for (int l = 0; l < L_; l++) s += p[(size_t)l * D_];
    out[b * D_ + d] = s * (1.f / L_);
}

// ---------------------------------------------------------------------------
// Launch
// ---------------------------------------------------------------------------
extern "C" void kernel_launch(void* const* d_in, const int* in_sizes, int n_in,
                              void* d_out, int out_size)
{
    const float* x     = (const float*)d_in[0];
    const float* Win   = (const float*)d_in[1];
    const float* convw = (const float*)d_in[2];
    const float* convb = (const float*)d_in[3];
    const float* Wx    = (const float*)d_in[4];
    const float* Wdt   = (const float*)d_in[5];
    const float* bdt   = (const float*)d_in[6];
    const float* Alog  = (const float*)d_in[7];
    const float* Dp    = (const float*)d_in[8];
    const float* Wout  = (const float*)d_in[9];
    const float* ln_g  = (const float*)d_in[10];
    const float* ln_b  = (const float*)d_in[11];

    float *h, *xz, *u, *xdbl, *xp, *delta;
    cudaGetSymbolAddress((void**)&h,     g_h);
    cudaGetSymbolAddress((void**)&xz,    g_xz);
    cudaGetSymbolAddress((void**)&u,     g_u);
    cudaGetSymbolAddress((void**)&xdbl,  g_xdbl);
    cudaGetSymbolAddress((void**)&xp,    g_xp);
    cudaGetSymbolAddress((void**)&delta, g_delta);

    __half *win, *wout, *wdt, *wxp, *hh, *uh, *yh, *dtrh;
    cudaGetSymbolAddress((void**)&win,  g_win);
    cudaGetSymbolAddress((void**)&wout, g_wout);
    cudaGetSymbolAddress((void**)&wdt,  g_wdt);
    cudaGetSymbolAddress((void**)&wxp,  g_wxp);
    cudaGetSymbolAddress((void**)&hh,   g_hh);
    cudaGetSymbolAddress((void**)&uh,   g_uh);
    cudaGetSymbolAddress((void**)&yh,   g_yh);
    cudaGetSymbolAddress((void**)&dtrh, g_dtrh);

    cudaFuncSetAttribute(hmma_gemm<0>, cudaFuncAttributeMaxDynamicSharedMemorySize, HT_SMEM);
    cudaFuncSetAttribute(hmma_gemm<1>, cudaFuncAttributeMaxDynamicSharedMemorySize, HT_SMEM);
    cudaFuncSetAttribute(hmma_gemm<2>, cudaFuncAttributeMaxDynamicSharedMemorySize, HT_SMEM);

    // ---- weight rounding to fp16 ----
    {
        int n4 = NL_ * 2 * E_ * D_ / 4;
        round_kernel<<<CDIV(n4, 256), 256>>>((const float4*)Win, win, n4);
        n4 = NL_ * D_ * E_ / 4;
        round_kernel<<<CDIV(n4, 256), 256>>>((const float4*)Wout, wout, n4);
        n4 = NL_ * E_ * R_ / 4;
        round_kernel<<<CDIV(n4, 256), 256>>>((const float4*)Wdt, wdt, n4);
        const int nt = NL_ * 128 * E_;
        wxpad_kernel<<<CDIV(nt, 256), 256>>>(Wx, wxp);
    }

    const int n4 = (T_ * D_) / 4;
    init_h_kernel<<<CDIV(n4, 256), 256>>>((const float4*)x, (float4*)h, hh, n4);

    for (int i = 0; i < NL_; i++) {
        // 1) xz = h @ Win^T   (4096 x 4096, K=1024)
        hmma_gemm<0><<<dim3((2 * E_) / 128, T_ / 128), 256, HT_SMEM>>>(
            T_, 2 * E_, D_,
            hh, D_,
            win + (size_t)i * 2 * E_ * D_, D_,
            xz, 2 * E_, nullptr, nullptr, 0, 0);

        // 2) u = silu(causal_conv(xz[:, :E]) + convb)   (+ fp16 round)
        conv_silu_kernel<<<dim3(E_ / 256, T_), 256>>>(
            xz, convw + (size_t)i * E_ * KC_, convb + (size_t)i * E_, u, uh);

        // 3) x_dbl = u @ Wx^T  (4096 x 128pad, K=2048), split-K x8
        hmma_gemm<0><<<dim3(1, T_ / 128, XSPLIT_), 256, HT_SMEM>>>(
            T_, 128, E_,
            uh, E_,
            wxp + (size_t)i * 128 * E_, E_,
            xp, 128, nullptr, nullptr,
            E_ / XSPLIT_, (long long)T_ * 128);
        reduce_xdbl_kernel<<<CDIV(T_ * XD_, 256), 256>>>(xp, xdbl, dtrh);

        // 4) delta = softplus(dtr @ Wdt^T + bdt)  (4096 x 2048, K=64)
        hmma_gemm<1><<<dim3(E_ / 128, T_ / 128), 256, HT_SMEM>>>(
            T_, E_, R_,
            dtrh, R_,
            wdt + (size_t)i * E_ * R_, R_,
            delta, E_, bdt + (size_t)i * E_, nullptr, 0, 0);

        // 5) selective scan -> y (state-parallel, fp16 out)
        scan_kernel<<<dim3(E_ / 32, B_), 128>>>(
            delta, u, xz, xdbl,
            Alog + (size_t)i * E_ * NS_, Dp + (size_t)i * E_, yh);

        // 6) h = y @ Wout^T + h  (4096 x 1024, K=2048)
        hmma_gemm<2><<<dim3(D_ / 128, T_ / 128), 256, HT_SMEM>>>(
            T_, D_, E_,
            yh, E_,
            wout + (size_t)i * D_ * E_, E_,
            h, D_, nullptr, h, 0, 0);

        // 7) layernorm (+ h fp16 round)
        layernorm_kernel<<<T_, 256>>>(h, ln_g + (size_t)i * D_, ln_b + (size_t)i * D_, hh);
    }

    mean_kernel<<<dim3(D_ / 256, B_), 256>>>(h, (float*)d_out);
}